// round 7
// baseline (speedup 1.0000x reference)
#include <cuda_runtime.h>
#include <math.h>

#define BB 4
#define NN 40960
#define KK 16
#define HH 16
#define DD 32
#define PPC 16          // points per CTA (2 pairs x 8)
#define BN_EPS 1e-5f

typedef unsigned long long u64t;

__device__ float g_feat_t[BB * NN * HH];   // feature transposed to [b, n, 16]
__device__ float g_agg1[BB * NN * HH];     // f_agg1 [b, n, 16]

__device__ __forceinline__ float lrelu(float y) { return fmaxf(y, 0.2f * y); }

// ---- packed f32x2 helpers (sm_100+) ----
__device__ __forceinline__ void FMA2(u64t& d, u64t a, u64t b) {
    asm("fma.rn.f32x2 %0, %1, %2, %0;" : "+l"(d) : "l"(a), "l"(b));
}
__device__ __forceinline__ void ADD2(u64t& d, u64t a) {
    asm("add.rn.f32x2 %0, %0, %1;" : "+l"(d) : "l"(a));
}
__device__ __forceinline__ u64t PACK2(float lo, float hi) {
    u64t r; asm("mov.b64 %0, {%1, %2};" : "=l"(r) : "f"(lo), "f"(hi)); return r;
}
__device__ __forceinline__ float HSUM2(u64t v) {
    float lo, hi; asm("mov.b64 {%0, %1}, %2;" : "=f"(lo), "=f"(hi) : "l"(v));
    return lo + hi;
}
__device__ __forceinline__ void LDS2x64(u64t& a, u64t& b, unsigned addr) {
    asm volatile("ld.shared.v2.b64 {%0, %1}, [%2];" : "=l"(a), "=l"(b) : "r"(addr));
}
__device__ __forceinline__ u64t LDS64(unsigned addr) {
    u64t a; asm volatile("ld.shared.b64 %0, [%1];" : "=l"(a) : "r"(addr)); return a;
}

// ---- cp.async helpers ----
__device__ __forceinline__ void cp16(unsigned dst, const float* src) {
    asm volatile("cp.async.cg.shared.global [%0], [%1], 16;" :: "r"(dst), "l"(src));
}
__device__ __forceinline__ void cp4(unsigned dst, const float* src) {
    asm volatile("cp.async.ca.shared.global [%0], [%1], 4;" :: "r"(dst), "l"(src));
}
__device__ __forceinline__ void cp_commit() {
    asm volatile("cp.async.commit_group;");
}
template <int N> __device__ __forceinline__ void cp_wait() {
    asm volatile("cp.async.wait_group %0;" :: "n"(N));
}
__device__ __forceinline__ void bar_pair(int pair) {
    asm volatile("bar.sync %0, 64;" :: "r"(pair + 1) : "memory");
}

// ---------------------------------------------------------------------------
// Transpose feature [B,16,N,1] -> [B*N,16]
// ---------------------------------------------------------------------------
__global__ void transpose_feat_kernel(const float* __restrict__ feature) {
    __shared__ float tile[HH][64 + 1];
    int b = blockIdx.y;
    int n0 = blockIdx.x * 64;
    int t = threadIdx.x;  // 256 threads
    int i = t & 63, cq = t >> 6;
    #pragma unroll
    for (int cc = cq; cc < HH; cc += 4)
        tile[cc][i] = feature[(b * HH + cc) * NN + n0 + i];
    __syncthreads();
    int c = t & 15, iq = t >> 4;
    #pragma unroll
    for (int ii = iq; ii < 64; ii += 16)
        g_feat_t[(b * NN + n0 + ii) * HH + c] = tile[c][ii];
}

// ---------------------------------------------------------------------------
// Stage 1: warp-pair per point. Each warp owns 8 of 16 neighbors.
// ---------------------------------------------------------------------------
__global__ void __launch_bounds__(128) stage1_kernel(
    const float* __restrict__ xyz, const int* __restrict__ nidx,
    const float* __restrict__ w1, const float* __restrict__ b1,
    const float* __restrict__ g1, const float* __restrict__ be1,
    const float* __restrict__ fc1w, const float* __restrict__ fc1b,
    const float* __restrict__ ap1w, const float* __restrict__ ap1b,
    const float* __restrict__ ap1g, const float* __restrict__ ap1be)
{
    __shared__ __align__(16) float sh_feat[2][8][KK][HH];   // all 8 iters resident
    __shared__ __align__(16) float sh_nxyz[2][8][KK][4];
    __shared__ __align__(16) float sh_fxyz[2][KK][12];
    __shared__ __align__(16) float sh_conv[2][2][KK][HH];   // double-buffered
    __shared__ __align__(16) float sh_sc[2][2][KK][DD];     // double-buffered
    __shared__ __align__(16) int   sh_idx[2][8][KK];
    __shared__ float sh_cxyz[2][8][3];

    const int warp = threadIdx.x >> 5;
    const int lane = threadIdx.x & 31;
    const int pair = warp >> 1;
    const int half = warp & 1;
    const int cm16 = lane & 15;
    const float inv_bn = rsqrtf(1.0f + BN_EPS);

    u64t w1p[5]; float b1f;
    {
        float s = g1[cm16] * inv_bn;
        #pragma unroll
        for (int i = 0; i < 5; i++)
            w1p[i] = PACK2(w1[cm16 * 10 + 2 * i] * s, w1[cm16 * 10 + 2 * i + 1] * s);
        b1f = b1[cm16] * s + be1[cm16];
    }
    u64t fcp[16]; float fcb = fc1b[lane];
    #pragma unroll
    for (int i = 0; i < 16; i++)
        fcp[i] = PACK2(fc1w[lane * DD + 2 * i], fc1w[lane * DD + 2 * i + 1]);
    u64t app[16]; float apb;
    {
        float s = ap1g[cm16] * inv_bn;
        #pragma unroll
        for (int i = 0; i < 16; i++)
            app[i] = PACK2(ap1w[cm16 * DD + 2 * i] * s, ap1w[cm16 * DD + 2 * i + 1] * s);
        apb = ap1b[cm16] * s + ap1be[cm16];
    }

    const int b  = blockIdx.x / (NN / PPC);
    const int n0 = (blockIdx.x % (NN / PPC)) * PPC;
    const int pbase = b * NN + n0 + pair * 8;   // pair's first point

    const unsigned feat_a = (unsigned)__cvta_generic_to_shared(&sh_feat[pair][0][0][0]);
    const unsigned conv_a = (unsigned)__cvta_generic_to_shared(&sh_conv[pair][0][0][0]);
    const unsigned nxyz_a = (unsigned)__cvta_generic_to_shared(&sh_nxyz[pair][0][0][0]);
    const unsigned fxyz_a = (unsigned)__cvta_generic_to_shared(&sh_fxyz[pair][0][0]);

    // w0 loads pair's 128 indices; w1 loads pair's 24 center coords
    if (half == 0) {
        int4 iv = *(const int4*)(nidx + (size_t)pbase * KK + lane * 4);
        *(int4*)&sh_idx[pair][lane >> 2][(lane & 3) * 4] = iv;
    } else if (lane < 24) {
        sh_cxyz[pair][lane / 3][lane % 3] = xyz[pbase * 3 + lane];
    }
    bar_pair(pair);

    // ---- prologue: issue ALL 8 gather groups (own j-range only) ----
    const int jq = half * 8 + (lane >> 2), quar = lane & 3;  // feat mapping
    #pragma unroll
    for (int s = 0; s < 8; s++) {
        {
            int idx = sh_idx[pair][s][jq];
            cp16(feat_a + s * 1024 + jq * 64 + quar * 16,
                 g_feat_t + (size_t)(b * NN + idx) * HH + quar * 4);
        }
        if (lane < 8) {
            int j = half * 8 + lane;
            int ix = sh_idx[pair][s][j];
            const float* xs = xyz + (size_t)(b * NN + ix) * 3;
            unsigned dn = nxyz_a + s * 256 + j * 16;
            cp4(dn, xs); cp4(dn + 4, xs + 1); cp4(dn + 8, xs + 2);
        }
        cp_commit();
    }

    #pragma unroll
    for (int t = 0; t < 8; t++) {
        const int pn = pbase + t;
        const int db = t & 1;
        switch (t) {
            case 0: cp_wait<7>(); break; case 1: cp_wait<6>(); break;
            case 2: cp_wait<5>(); break; case 3: cp_wait<4>(); break;
            case 4: cp_wait<3>(); break; case 5: cp_wait<2>(); break;
            case 6: cp_wait<1>(); break; default: cp_wait<0>(); break;
        }
        __syncwarp();

        // geometry for my 8 j's (lanes 0..7)
        if (lane < 8) {
            int j = half * 8 + lane;
            const float* np_ = &sh_nxyz[pair][t][j][0];
            float nx = np_[0], ny = np_[1], nz = np_[2];
            float cx = sh_cxyz[pair][t][0], cy = sh_cxyz[pair][t][1], cz = sh_cxyz[pair][t][2];
            float rx = cx - nx, ry = cy - ny, rz = cz - nz;
            float dis = sqrtf(rx * rx + ry * ry + rz * rz);
            float4* row = (float4*)&sh_fxyz[pair][j][0];
            row[0] = make_float4(dis, rx, ry, rz);
            row[1] = make_float4(cx, cy, cz, nx);
            ((float2*)&sh_fxyz[pair][j][8])[0] = make_float2(ny, nz);
        }
        __syncwarp();

        // conv1 (10->16): my 8 j's, lane-halves take 4 each
        {
            int jb = half * 8 + ((lane >> 4) << 2);
            #pragma unroll
            for (int jj = 0; jj < 4; jj++) {
                int j = jb + jj;
                unsigned a = fxyz_a + j * 48;
                u64t x0, x1, x2, x3, x4;
                LDS2x64(x0, x1, a);
                LDS2x64(x2, x3, a + 16);
                x4 = LDS64(a + 32);
                u64t acc0 = PACK2(b1f, 0.f), acc1 = PACK2(0.f, 0.f);
                FMA2(acc0, x0, w1p[0]); FMA2(acc1, x1, w1p[1]);
                FMA2(acc0, x2, w1p[2]); FMA2(acc1, x3, w1p[3]);
                FMA2(acc0, x4, w1p[4]);
                ADD2(acc0, acc1);
                sh_conv[pair][db][j][cm16] = lrelu(HSUM2(acc0));
            }
        }
        __syncwarp();

        // fc scores for my 8 j's -> sh_sc
        {
            const unsigned fb = feat_a + t * 1024;
            const unsigned cb = conv_a + db * 1024;
            #pragma unroll
            for (int jj = 0; jj < 8; jj++) {
                int j = half * 8 + jj;
                unsigned fa = fb + j * 64;
                unsigned ca = cb + j * 64;
                u64t p0, p1, p2, p3;
                u64t acc0 = PACK2(fcb, 0.f), acc1 = PACK2(0.f, 0.f);
                LDS2x64(p0, p1, fa);      FMA2(acc0, p0, fcp[0]);  FMA2(acc1, p1, fcp[1]);
                LDS2x64(p2, p3, fa + 16); FMA2(acc0, p2, fcp[2]);  FMA2(acc1, p3, fcp[3]);
                LDS2x64(p0, p1, ca);      FMA2(acc0, p0, fcp[8]);  FMA2(acc1, p1, fcp[9]);
                LDS2x64(p2, p3, ca + 16); FMA2(acc0, p2, fcp[10]); FMA2(acc1, p3, fcp[11]);
                LDS2x64(p0, p1, fa + 32); FMA2(acc0, p0, fcp[4]);  FMA2(acc1, p1, fcp[5]);
                LDS2x64(p2, p3, fa + 48); FMA2(acc0, p2, fcp[6]);  FMA2(acc1, p3, fcp[7]);
                LDS2x64(p0, p1, ca + 32); FMA2(acc0, p0, fcp[12]); FMA2(acc1, p1, fcp[13]);
                LDS2x64(p2, p3, ca + 48); FMA2(acc0, p2, fcp[14]); FMA2(acc1, p3, fcp[15]);
                ADD2(acc0, acc1);
                sh_sc[pair][db][j][lane] = HSUM2(acc0);
            }
        }
        bar_pair(pair);   // all 16 sc rows + conv rows + gathers visible

        // softmax over 16 j (duplicated in both warps), channel = lane
        float ex[KK]; float ssum = 0.0f;
        {
            const float* sp = &sh_sc[pair][db][0][lane];
            #pragma unroll
            for (int j = 0; j < KK; j++) {
                ex[j] = __expf(sp[j * DD]);
                ssum += ex[j];
            }
        }
        float inv = 1.0f / ssum;
        const float* wsp = (lane < HH) ? &sh_feat[pair][t][0][lane]
                                       : &sh_conv[pair][db][0][lane - HH];
        float a0 = 0.f, a1 = 0.f;
        #pragma unroll
        for (int j = 0; j < KK; j += 2) {
            a0 += wsp[j * HH] * ex[j];
            a1 += wsp[(j + 1) * HH] * ex[j + 1];
        }
        float agg = (a0 + a1) * inv;

        // mlp (32->16) via shuffle broadcasts (no shared, no barrier)
        {
            u64t acc0 = PACK2(apb, 0.f), acc1 = PACK2(0.f, 0.f);
            #pragma unroll
            for (int q = 0; q < 16; q += 2) {
                float v0 = __shfl_sync(0xffffffffu, agg, 2 * q);
                float v1 = __shfl_sync(0xffffffffu, agg, 2 * q + 1);
                FMA2(acc0, PACK2(v0, v1), app[q]);
                float v2 = __shfl_sync(0xffffffffu, agg, 2 * q + 2);
                float v3 = __shfl_sync(0xffffffffu, agg, 2 * q + 3);
                FMA2(acc1, PACK2(v2, v3), app[q + 1]);
            }
            ADD2(acc0, acc1);
            if (half == 0 && lane < HH)
                g_agg1[(size_t)pn * HH + lane] = lrelu(HSUM2(acc0));
        }
    }
}

// ---------------------------------------------------------------------------
// Stage 2: warp-pair per point; + conv1 recompute + conv2; output staged.
// ---------------------------------------------------------------------------
__global__ void __launch_bounds__(128) stage2_kernel(
    const float* __restrict__ xyz, const int* __restrict__ nidx,
    const float* __restrict__ w1, const float* __restrict__ b1,
    const float* __restrict__ g1, const float* __restrict__ be1,
    const float* __restrict__ w2, const float* __restrict__ b2,
    const float* __restrict__ g2, const float* __restrict__ be2,
    const float* __restrict__ fc2w, const float* __restrict__ fc2b,
    const float* __restrict__ ap2w, const float* __restrict__ ap2b,
    const float* __restrict__ ap2g, const float* __restrict__ ap2be,
    float* __restrict__ out)
{
    __shared__ __align__(16) float sh_feat[2][8][KK][HH];   // gathered g_agg1
    __shared__ __align__(16) float sh_nxyz[2][8][KK][4];
    __shared__ __align__(16) float sh_fxyz[2][KK][12];
    __shared__ __align__(16) float sh_fx1[2][KK][HH];       // warp-private j rows
    __shared__ __align__(16) float sh_conv[2][2][KK][HH];   // conv2, double-buffered
    __shared__ __align__(16) float sh_sc[2][2][KK][DD];
    __shared__ __align__(16) int   sh_idx[2][8][KK];
    __shared__ float sh_cxyz[2][8][3];
    __shared__ float sh_out[DD][PPC + 1];

    const int warp = threadIdx.x >> 5;
    const int lane = threadIdx.x & 31;
    const int pair = warp >> 1;
    const int half = warp & 1;
    const int cm16 = lane & 15;
    const float inv_bn = rsqrtf(1.0f + BN_EPS);

    u64t w1p[5]; float b1f;
    {
        float s = g1[cm16] * inv_bn;
        #pragma unroll
        for (int i = 0; i < 5; i++)
            w1p[i] = PACK2(w1[cm16 * 10 + 2 * i] * s, w1[cm16 * 10 + 2 * i + 1] * s);
        b1f = b1[cm16] * s + be1[cm16];
    }
    u64t w2p[8]; float b2f;
    {
        float s = g2[cm16] * inv_bn;
        #pragma unroll
        for (int i = 0; i < 8; i++)
            w2p[i] = PACK2(w2[cm16 * HH + 2 * i] * s, w2[cm16 * HH + 2 * i + 1] * s);
        b2f = b2[cm16] * s + be2[cm16];
    }
    u64t fcp[16]; float fcb = fc2b[lane];
    #pragma unroll
    for (int i = 0; i < 16; i++)
        fcp[i] = PACK2(fc2w[lane * DD + 2 * i], fc2w[lane * DD + 2 * i + 1]);
    u64t app[16]; float apb;
    {
        float s = ap2g[lane] * inv_bn;
        #pragma unroll
        for (int i = 0; i < 16; i++)
            app[i] = PACK2(ap2w[lane * DD + 2 * i] * s, ap2w[lane * DD + 2 * i + 1] * s);
        apb = ap2b[lane] * s + ap2be[lane];
    }

    const int b  = blockIdx.x / (NN / PPC);
    const int n0 = (blockIdx.x % (NN / PPC)) * PPC;
    const int pbase = b * NN + n0 + pair * 8;

    const unsigned feat_a = (unsigned)__cvta_generic_to_shared(&sh_feat[pair][0][0][0]);
    const unsigned conv_a = (unsigned)__cvta_generic_to_shared(&sh_conv[pair][0][0][0]);
    const unsigned nxyz_a = (unsigned)__cvta_generic_to_shared(&sh_nxyz[pair][0][0][0]);
    const unsigned fxyz_a = (unsigned)__cvta_generic_to_shared(&sh_fxyz[pair][0][0]);
    const unsigned fx1_a  = (unsigned)__cvta_generic_to_shared(&sh_fx1[pair][0][0]);

    if (half == 0) {
        int4 iv = *(const int4*)(nidx + (size_t)pbase * KK + lane * 4);
        *(int4*)&sh_idx[pair][lane >> 2][(lane & 3) * 4] = iv;
    } else if (lane < 24) {
        sh_cxyz[pair][lane / 3][lane % 3] = xyz[pbase * 3 + lane];
    }
    bar_pair(pair);

    const int jq = half * 8 + (lane >> 2), quar = lane & 3;
    #pragma unroll
    for (int s = 0; s < 8; s++) {
        {
            int idx = sh_idx[pair][s][jq];
            cp16(feat_a + s * 1024 + jq * 64 + quar * 16,
                 g_agg1 + (size_t)(b * NN + idx) * HH + quar * 4);
        }
        if (lane < 8) {
            int j = half * 8 + lane;
            int ix = sh_idx[pair][s][j];
            const float* xs = xyz + (size_t)(b * NN + ix) * 3;
            unsigned dn = nxyz_a + s * 256 + j * 16;
            cp4(dn, xs); cp4(dn + 4, xs + 1); cp4(dn + 8, xs + 2);
        }
        cp_commit();
    }

    #pragma unroll
    for (int t = 0; t < 8; t++) {
        const int ln = pair * 8 + t;
        const int db = t & 1;
        switch (t) {
            case 0: cp_wait<7>(); break; case 1: cp_wait<6>(); break;
            case 2: cp_wait<5>(); break; case 3: cp_wait<4>(); break;
            case 4: cp_wait<3>(); break; case 5: cp_wait<2>(); break;
            case 6: cp_wait<1>(); break; default: cp_wait<0>(); break;
        }
        __syncwarp();

        if (lane < 8) {
            int j = half * 8 + lane;
            const float* np_ = &sh_nxyz[pair][t][j][0];
            float nx = np_[0], ny = np_[1], nz = np_[2];
            float cx = sh_cxyz[pair][t][0], cy = sh_cxyz[pair][t][1], cz = sh_cxyz[pair][t][2];
            float rx = cx - nx, ry = cy - ny, rz = cz - nz;
            float dis = sqrtf(rx * rx + ry * ry + rz * rz);
            float4* row = (float4*)&sh_fxyz[pair][j][0];
            row[0] = make_float4(dis, rx, ry, rz);
            row[1] = make_float4(cx, cy, cz, nx);
            ((float2*)&sh_fxyz[pair][j][8])[0] = make_float2(ny, nz);
        }
        __syncwarp();

        // conv1 recompute (10->16) for my 4 j's per lane-half
        {
            int jb = half * 8 + ((lane >> 4) << 2);
            #pragma unroll
            for (int jj = 0; jj < 4; jj++) {
                int j = jb + jj;
                unsigned a = fxyz_a + j * 48;
                u64t x0, x1, x2, x3, x4;
                LDS2x64(x0, x1, a);
                LDS2x64(x2, x3, a + 16);
                x4 = LDS64(a + 32);
                u64t acc0 = PACK2(b1f, 0.f), acc1 = PACK2(0.f, 0.f);
                FMA2(acc0, x0, w1p[0]); FMA2(acc1, x1, w1p[1]);
                FMA2(acc0, x2, w1p[2]); FMA2(acc1, x3, w1p[3]);
                FMA2(acc0, x4, w1p[4]);
                ADD2(acc0, acc1);
                sh_fx1[pair][j][cm16] = lrelu(HSUM2(acc0));
            }
        }
        __syncwarp();

        // conv2 (16->16) for my j's
        {
            int jb = half * 8 + ((lane >> 4) << 2);
            #pragma unroll
            for (int jj = 0; jj < 4; jj++) {
                int j = jb + jj;
                unsigned a = fx1_a + j * 64;
                u64t p0, p1, p2, p3;
                u64t acc0 = PACK2(b2f, 0.f), acc1 = PACK2(0.f, 0.f);
                LDS2x64(p0, p1, a);      FMA2(acc0, p0, w2p[0]); FMA2(acc1, p1, w2p[1]);
                LDS2x64(p2, p3, a + 16); FMA2(acc0, p2, w2p[2]); FMA2(acc1, p3, w2p[3]);
                LDS2x64(p0, p1, a + 32); FMA2(acc0, p0, w2p[4]); FMA2(acc1, p1, w2p[5]);
                LDS2x64(p2, p3, a + 48); FMA2(acc0, p2, w2p[6]); FMA2(acc1, p3, w2p[7]);
                ADD2(acc0, acc1);
                sh_conv[pair][db][j][cm16] = lrelu(HSUM2(acc0));
            }
        }
        __syncwarp();

        // fc2 scores for my 8 j's
        {
            const unsigned fb = feat_a + t * 1024;
            const unsigned cb = conv_a + db * 1024;
            #pragma unroll
            for (int jj = 0; jj < 8; jj++) {
                int j = half * 8 + jj;
                unsigned fa = fb + j * 64;
                unsigned ca = cb + j * 64;
                u64t p0, p1, p2, p3;
                u64t acc0 = PACK2(fcb, 0.f), acc1 = PACK2(0.f, 0.f);
                LDS2x64(p0, p1, fa);      FMA2(acc0, p0, fcp[0]);  FMA2(acc1, p1, fcp[1]);
                LDS2x64(p2, p3, fa + 16); FMA2(acc0, p2, fcp[2]);  FMA2(acc1, p3, fcp[3]);
                LDS2x64(p0, p1, ca);      FMA2(acc0, p0, fcp[8]);  FMA2(acc1, p1, fcp[9]);
                LDS2x64(p2, p3, ca + 16); FMA2(acc0, p2, fcp[10]); FMA2(acc1, p3, fcp[11]);
                LDS2x64(p0, p1, fa + 32); FMA2(acc0, p0, fcp[4]);  FMA2(acc1, p1, fcp[5]);
                LDS2x64(p2, p3, fa + 48); FMA2(acc0, p2, fcp[6]);  FMA2(acc1, p3, fcp[7]);
                LDS2x64(p0, p1, ca + 32); FMA2(acc0, p0, fcp[12]); FMA2(acc1, p1, fcp[13]);
                LDS2x64(p2, p3, ca + 48); FMA2(acc0, p2, fcp[14]); FMA2(acc1, p3, fcp[15]);
                ADD2(acc0, acc1);
                sh_sc[pair][db][j][lane] = HSUM2(acc0);
            }
        }
        bar_pair(pair);

        // softmax + pool (duplicated)
        float ex[KK]; float ssum = 0.0f;
        {
            const float* sp = &sh_sc[pair][db][0][lane];
            #pragma unroll
            for (int j = 0; j < KK; j++) {
                ex[j] = __expf(sp[j * DD]);
                ssum += ex[j];
            }
        }
        float inv = 1.0f / ssum;
        const float* wsp = (lane < HH) ? &sh_feat[pair][t][0][lane]
                                       : &sh_conv[pair][db][0][lane - HH];
        float a0 = 0.f, a1 = 0.f;
        #pragma unroll
        for (int j = 0; j < KK; j += 2) {
            a0 += wsp[j * HH] * ex[j];
            a1 += wsp[(j + 1) * HH] * ex[j + 1];
        }
        float agg = (a0 + a1) * inv;

        // mlp2 (32->32) via shuffle
        {
            u64t acc0 = PACK2(apb, 0.f), acc1 = PACK2(0.f, 0.f);
            #pragma unroll
            for (int q = 0; q < 16; q += 2) {
                float v0 = __shfl_sync(0xffffffffu, agg, 2 * q);
                float v1 = __shfl_sync(0xffffffffu, agg, 2 * q + 1);
                FMA2(acc0, PACK2(v0, v1), app[q]);
                float v2 = __shfl_sync(0xffffffffu, agg, 2 * q + 2);
                float v3 = __shfl_sync(0xffffffffu, agg, 2 * q + 3);
                FMA2(acc1, PACK2(v2, v3), app[q + 1]);
            }
            ADD2(acc0, acc1);
            if (half == 0)
                sh_out[lane][ln] = lrelu(HSUM2(acc0));
        }
    }

    __syncthreads();
    for (int e = threadIdx.x; e < DD * PPC; e += 128) {
        int c = e >> 4, ln = e & (PPC - 1);
        out[((size_t)b * DD + c) * NN + n0 + ln] = sh_out[c][ln];
    }
}

// ---------------------------------------------------------------------------
extern "C" void kernel_launch(void* const* d_in, const int* in_sizes, int n_in,
                              void* d_out, int out_size) {
    const float* xyz     = (const float*)d_in[0];
    const float* feature = (const float*)d_in[1];
    const int*   nidx    = (const int*)  d_in[2];
    const float* w1   = (const float*)d_in[3];
    const float* b1   = (const float*)d_in[4];
    const float* g1   = (const float*)d_in[5];
    const float* be1  = (const float*)d_in[6];
    const float* fc1w = (const float*)d_in[7];
    const float* fc1b = (const float*)d_in[8];
    const float* ap1w = (const float*)d_in[9];
    const float* ap1b = (const float*)d_in[10];
    const float* ap1g = (const float*)d_in[11];
    const float* ap1be= (const float*)d_in[12];
    const float* w2   = (const float*)d_in[13];
    const float* b2   = (const float*)d_in[14];
    const float* g2   = (const float*)d_in[15];
    const float* be2  = (const float*)d_in[16];
    const float* fc2w = (const float*)d_in[17];
    const float* fc2b = (const float*)d_in[18];
    const float* ap2w = (const float*)d_in[19];
    const float* ap2b = (const float*)d_in[20];
    const float* ap2g = (const float*)d_in[21];
    const float* ap2be= (const float*)d_in[22];
    float* out = (float*)d_out;

    transpose_feat_kernel<<<dim3(NN / 64, BB), 256>>>(feature);
    stage1_kernel<<<BB * NN / PPC, 128>>>(xyz, nidx, w1, b1, g1, be1,
                                          fc1w, fc1b, ap1w, ap1b, ap1g, ap1be);
    stage2_kernel<<<BB * NN / PPC, 128>>>(xyz, nidx, w1, b1, g1, be1,
                                          w2, b2, g2, be2, fc2w, fc2b,
                                          ap2w, ap2b, ap2g, ap2be, out);
}

// round 8
// speedup vs baseline: 1.5694x; 1.5694x over previous
#include <cuda_runtime.h>
#include <math.h>

#define BB 4
#define NN 40960
#define KK 16
#define HH 16
#define DD 32
#define BN_EPS 1e-5f

typedef unsigned long long u64t;

// scratch (device globals: no allocation allowed)
__device__ float g_feat_t[BB * NN * HH];   // feature transposed to [b, n, 16]
__device__ float g_agg1[BB * NN * HH];     // f_agg1 [b, n, 16]

__device__ __forceinline__ float lrelu(float y) { return fmaxf(y, 0.2f * y); }

// ---- packed f32x2 helpers (sm_100+) ----
__device__ __forceinline__ void FMA2(u64t& d, u64t a, u64t b) {
    asm("fma.rn.f32x2 %0, %1, %2, %0;" : "+l"(d) : "l"(a), "l"(b));
}
__device__ __forceinline__ void ADD2(u64t& d, u64t a) {
    asm("add.rn.f32x2 %0, %0, %1;" : "+l"(d) : "l"(a));
}
__device__ __forceinline__ u64t PACK2(float lo, float hi) {
    u64t r; asm("mov.b64 %0, {%1, %2};" : "=l"(r) : "f"(lo), "f"(hi)); return r;
}
__device__ __forceinline__ float HSUM2(u64t v) {
    float lo, hi; asm("mov.b64 {%0, %1}, %2;" : "=f"(lo), "=f"(hi) : "l"(v));
    return lo + hi;
}
__device__ __forceinline__ void LDS2x64(u64t& a, u64t& b, unsigned addr) {
    asm volatile("ld.shared.v2.b64 {%0, %1}, [%2];" : "=l"(a), "=l"(b) : "r"(addr));
}
__device__ __forceinline__ u64t LDS64(unsigned addr) {
    u64t a; asm volatile("ld.shared.b64 %0, [%1];" : "=l"(a) : "r"(addr)); return a;
}

// ---- cp.async helpers ----
__device__ __forceinline__ void cp16(unsigned dst, const float* src) {
    asm volatile("cp.async.cg.shared.global [%0], [%1], 16;" :: "r"(dst), "l"(src));
}
__device__ __forceinline__ void cp4(unsigned dst, const float* src) {
    asm volatile("cp.async.ca.shared.global [%0], [%1], 4;" :: "r"(dst), "l"(src));
}
__device__ __forceinline__ void cp_commit() {
    asm volatile("cp.async.commit_group;");
}
template <int N> __device__ __forceinline__ void cp_wait() {
    asm volatile("cp.async.wait_group %0;" :: "n"(N));
}

// ---------------------------------------------------------------------------
// Transpose feature [B,16,N,1] -> [B*N,16]
// ---------------------------------------------------------------------------
__global__ void transpose_feat_kernel(const float* __restrict__ feature) {
    __shared__ float tile[HH][64 + 1];
    int b = blockIdx.y;
    int n0 = blockIdx.x * 64;
    int t = threadIdx.x;  // 256 threads
    int i = t & 63, cq = t >> 6;
    #pragma unroll
    for (int cc = cq; cc < HH; cc += 4)
        tile[cc][i] = feature[(b * HH + cc) * NN + n0 + i];
    __syncthreads();
    int c = t & 15, iq = t >> 4;
    #pragma unroll
    for (int ii = iq; ii < 64; ii += 16)
        g_feat_t[(b * NN + n0 + ii) * HH + c] = tile[c][ii];
}

// ---------------------------------------------------------------------------
// Stage 1: geometry + conv1(+BN,LReLU) + gather(feat) + att_pool_1 -> g_agg1
// R5 pipeline + register diet: att-mlp weights live in shared (transposed).
// ---------------------------------------------------------------------------
__global__ void __launch_bounds__(128, 4) stage1_kernel(
    const float* __restrict__ xyz, const int* __restrict__ nidx,
    const float* __restrict__ w1, const float* __restrict__ b1,
    const float* __restrict__ g1, const float* __restrict__ be1,
    const float* __restrict__ fc1w, const float* __restrict__ fc1b,
    const float* __restrict__ ap1w, const float* __restrict__ ap1b,
    const float* __restrict__ ap1g, const float* __restrict__ ap1be)
{
    __shared__ __align__(16) float sh_feat[4][4][KK][HH];  // [warp][buf][j][c]
    __shared__ __align__(16) float sh_nxyz[4][4][KK][4];   // [warp][buf][j][xyz-]
    __shared__ __align__(16) float sh_fxyz[4][KK][12];
    __shared__ __align__(16) float sh_conv[4][KK][HH];
    __shared__ __align__(16) float sh_agg[4][DD];
    __shared__ __align__(16) int   sh_idx[4][8][KK];
    __shared__ float sh_cxyz[4][8][3];
    __shared__ __align__(16) u64t sh_appw[16][HH];         // mlp weights [pair q][outc]

    const int warp = threadIdx.x >> 5;
    const int lane = threadIdx.x & 31;
    const int cm16 = lane & 15;
    const float inv_bn = rsqrtf(1.0f + BN_EPS);

    // mlp weights -> shared (transposed, BN folded)
    for (int e = threadIdx.x; e < 16 * HH; e += 128) {
        int q = e >> 4, c = e & 15;
        float s = ap1g[c] * inv_bn;
        sh_appw[q][c] = PACK2(ap1w[c * DD + 2 * q] * s, ap1w[c * DD + 2 * q + 1] * s);
    }

    // packed weights (BN folded) kept in registers
    u64t w1p[5]; float b1f;
    {
        float s = g1[cm16] * inv_bn;
        #pragma unroll
        for (int i = 0; i < 5; i++)
            w1p[i] = PACK2(w1[cm16 * 10 + 2 * i] * s, w1[cm16 * 10 + 2 * i + 1] * s);
        b1f = b1[cm16] * s + be1[cm16];
    }
    u64t fcp[16]; float fcb = fc1b[lane];
    #pragma unroll
    for (int i = 0; i < 16; i++)
        fcp[i] = PACK2(fc1w[lane * DD + 2 * i], fc1w[lane * DD + 2 * i + 1]);
    float apb = ap1b[cm16] * (ap1g[cm16] * inv_bn) + ap1be[cm16];

    const int b  = blockIdx.x / (NN / 32);
    const int n0 = (blockIdx.x % (NN / 32)) * 32;
    const int pbase = b * NN + n0 + warp * 8;

    const unsigned feat_a = (unsigned)__cvta_generic_to_shared(&sh_feat[warp][0][0][0]);
    const unsigned nxyz_a = (unsigned)__cvta_generic_to_shared(&sh_nxyz[warp][0][0][0]);
    const unsigned fxyz_a = (unsigned)__cvta_generic_to_shared(&sh_fxyz[warp][0][0]);
    const unsigned conv_a = (unsigned)__cvta_generic_to_shared(&sh_conv[warp][0][0]);
    const unsigned agg_a  = (unsigned)__cvta_generic_to_shared(&sh_agg[warp][0]);
    const unsigned appw_a = (unsigned)__cvta_generic_to_shared(&sh_appw[0][0]);

    // hoisted coalesced loads: all 128 indices + 24 center coords
    {
        int4 iv = *(const int4*)(nidx + (size_t)pbase * KK + lane * 4);
        *(int4*)&sh_idx[warp][lane >> 2][(lane & 3) * 4] = iv;
    }
    if (lane < 24) sh_cxyz[warp][lane / 3][lane % 3] = xyz[pbase * 3 + lane];
    __syncthreads();   // also covers sh_appw fill

    const int j2 = lane >> 1, h2 = lane & 1;

    // ---- prologue: issue prefetch groups 0..3 ----
    #pragma unroll
    for (int s = 0; s < 4; s++) {
        int idx = sh_idx[warp][s][j2];
        const float* src = g_feat_t + (size_t)(b * NN + idx) * HH + h2 * 8;
        unsigned d = feat_a + s * 1024 + j2 * 64 + h2 * 32;
        cp16(d, src); cp16(d + 16, src + 4);
        if (lane < KK) {
            int ix = sh_idx[warp][s][lane];
            const float* xs = xyz + (size_t)(b * NN + ix) * 3;
            unsigned dn = nxyz_a + s * 256 + lane * 16;
            cp4(dn, xs); cp4(dn + 4, xs + 1); cp4(dn + 8, xs + 2);
        }
        cp_commit();
    }

    #pragma unroll
    for (int t = 0; t < 8; t++) {
        const int pn = pbase + t;
        const int buf = t & 3;
        if (t < 5) cp_wait<3>(); else if (t == 5) cp_wait<2>();
        else if (t == 6) cp_wait<1>(); else cp_wait<0>();
        __syncwarp();

        // -------- geometry (lane<16) --------
        if (lane < KK) {
            const float* np_ = &sh_nxyz[warp][buf][lane][0];
            float nx = np_[0], ny = np_[1], nz = np_[2];
            float cx = sh_cxyz[warp][t][0], cy = sh_cxyz[warp][t][1], cz = sh_cxyz[warp][t][2];
            float rx = cx - nx, ry = cy - ny, rz = cz - nz;
            float dis = sqrtf(rx * rx + ry * ry + rz * rz);
            float4* row = (float4*)&sh_fxyz[warp][lane][0];
            row[0] = make_float4(dis, rx, ry, rz);
            row[1] = make_float4(cx, cy, cz, nx);
            ((float2*)&sh_fxyz[warp][lane][8])[0] = make_float2(ny, nz);
        }
        __syncwarp();

        // -------- conv1 (10->16) + BN + LReLU -> sh_conv --------
        {
            int jb = (lane >> 4) * 8;
            #pragma unroll
            for (int jj = 0; jj < 8; jj++) {
                int j = jb + jj;
                unsigned a = fxyz_a + j * 48;
                u64t x0, x1, x2, x3, x4;
                LDS2x64(x0, x1, a);
                LDS2x64(x2, x3, a + 16);
                x4 = LDS64(a + 32);
                u64t acc0 = PACK2(b1f, 0.f), acc1 = PACK2(0.f, 0.f);
                FMA2(acc0, x0, w1p[0]); FMA2(acc1, x1, w1p[1]);
                FMA2(acc0, x2, w1p[2]); FMA2(acc1, x3, w1p[3]);
                FMA2(acc0, x4, w1p[4]);
                ADD2(acc0, acc1);
                sh_conv[warp][j][cm16] = lrelu(HSUM2(acc0));
            }
        }
        __syncwarp();

        // -------- fc1 scores + softmax over k + weighted sum --------
        const unsigned fbuf_a = feat_a + buf * 1024;
        float sc[KK];
        #pragma unroll
        for (int j = 0; j < KK; j++) {
            unsigned fa = fbuf_a + j * 64;
            unsigned ca = conv_a + j * 64;
            u64t p0, p1, p2, p3;
            u64t acc0 = PACK2(fcb, 0.f), acc1 = PACK2(0.f, 0.f);
            LDS2x64(p0, p1, fa);      FMA2(acc0, p0, fcp[0]);  FMA2(acc1, p1, fcp[1]);
            LDS2x64(p2, p3, fa + 16); FMA2(acc0, p2, fcp[2]);  FMA2(acc1, p3, fcp[3]);
            LDS2x64(p0, p1, ca);      FMA2(acc0, p0, fcp[8]);  FMA2(acc1, p1, fcp[9]);
            LDS2x64(p2, p3, ca + 16); FMA2(acc0, p2, fcp[10]); FMA2(acc1, p3, fcp[11]);
            LDS2x64(p0, p1, fa + 32); FMA2(acc0, p0, fcp[4]);  FMA2(acc1, p1, fcp[5]);
            LDS2x64(p2, p3, fa + 48); FMA2(acc0, p2, fcp[6]);  FMA2(acc1, p3, fcp[7]);
            LDS2x64(p0, p1, ca + 32); FMA2(acc0, p0, fcp[12]); FMA2(acc1, p1, fcp[13]);
            LDS2x64(p2, p3, ca + 48); FMA2(acc0, p2, fcp[14]); FMA2(acc1, p3, fcp[15]);
            ADD2(acc0, acc1);
            sc[j] = HSUM2(acc0);
        }
        float ssum = 0.0f;
        #pragma unroll
        for (int j = 0; j < KK; j++) { sc[j] = __expf(sc[j]); ssum += sc[j]; }
        float inv = 1.0f / ssum;
        const float* wsp = (lane < HH) ? &sh_feat[warp][buf][0][lane]
                                       : &sh_conv[warp][0][lane - HH];
        float agg = 0.0f;
        #pragma unroll
        for (int j = 0; j < KK; j++)
            agg += wsp[j * HH] * (sc[j] * inv);
        sh_agg[warp][lane] = agg;
        __syncwarp();

        // -------- issue prefetch for t+4 (buffer buf now free) --------
        if (t + 4 < 8) {
            int s = t + 4;
            int idx = sh_idx[warp][s][j2];
            const float* src = g_feat_t + (size_t)(b * NN + idx) * HH + h2 * 8;
            unsigned d = feat_a + (s & 3) * 1024 + j2 * 64 + h2 * 32;
            cp16(d, src); cp16(d + 16, src + 4);
            if (lane < KK) {
                int ix = sh_idx[warp][s][lane];
                const float* xs = xyz + (size_t)(b * NN + ix) * 3;
                unsigned dn = nxyz_a + (s & 3) * 256 + lane * 16;
                cp4(dn, xs); cp4(dn + 4, xs + 1); cp4(dn + 8, xs + 2);
            }
            cp_commit();
        }

        // -------- mlp (32->16) + BN + LReLU, weights from shared --------
        if (lane < HH) {
            u64t acc0 = PACK2(apb, 0.f), acc1 = PACK2(0.f, 0.f);
            #pragma unroll
            for (int q = 0; q < 16; q += 2) {
                FMA2(acc0, LDS64(agg_a + q * 8),
                           LDS64(appw_a + q * 128 + lane * 8));
                FMA2(acc1, LDS64(agg_a + q * 8 + 8),
                           LDS64(appw_a + (q + 1) * 128 + lane * 8));
            }
            ADD2(acc0, acc1);
            g_agg1[(size_t)pn * HH + lane] = lrelu(HSUM2(acc0));
        }
        __syncwarp();
    }
}

// ---------------------------------------------------------------------------
// Stage 2: recompute f_xyz1, conv2, gather(f_agg1), att_pool_2 -> output
// R5 pipeline + register diet (w2 + att-mlp weights in shared).
// ---------------------------------------------------------------------------
__global__ void __launch_bounds__(128, 4) stage2_kernel(
    const float* __restrict__ xyz, const int* __restrict__ nidx,
    const float* __restrict__ w1, const float* __restrict__ b1,
    const float* __restrict__ g1, const float* __restrict__ be1,
    const float* __restrict__ w2, const float* __restrict__ b2,
    const float* __restrict__ g2, const float* __restrict__ be2,
    const float* __restrict__ fc2w, const float* __restrict__ fc2b,
    const float* __restrict__ ap2w, const float* __restrict__ ap2b,
    const float* __restrict__ ap2g, const float* __restrict__ ap2be,
    float* __restrict__ out)
{
    __shared__ __align__(16) float sh_feat[4][4][KK][HH];  // gathered g_agg1
    __shared__ __align__(16) float sh_nxyz[4][4][KK][4];
    __shared__ __align__(16) float sh_fxyz[4][KK][12];
    __shared__ __align__(16) float sh_fx1[4][KK][HH];
    __shared__ __align__(16) float sh_conv[4][KK][HH];
    __shared__ __align__(16) float sh_agg[4][DD];
    __shared__ __align__(16) int   sh_idx[4][8][KK];
    __shared__ float sh_cxyz[4][8][3];
    __shared__ float sh_out[DD][33];
    __shared__ __align__(16) u64t sh_appw[16][DD];   // mlp2 weights [pair q][outc]
    __shared__ __align__(16) u64t sh_w2w[8][HH];     // conv2 weights [pair q][outc]

    const int warp = threadIdx.x >> 5;
    const int lane = threadIdx.x & 31;
    const int cm16 = lane & 15;
    const float inv_bn = rsqrtf(1.0f + BN_EPS);

    for (int e = threadIdx.x; e < 16 * DD; e += 128) {
        int q = e >> 5, c = e & 31;
        float s = ap2g[c] * inv_bn;
        sh_appw[q][c] = PACK2(ap2w[c * DD + 2 * q] * s, ap2w[c * DD + 2 * q + 1] * s);
    }
    if (threadIdx.x < 8 * HH) {
        int e = threadIdx.x;
        int q = e >> 4, c = e & 15;
        float s = g2[c] * inv_bn;
        sh_w2w[q][c] = PACK2(w2[c * HH + 2 * q] * s, w2[c * HH + 2 * q + 1] * s);
    }

    u64t w1p[5]; float b1f;
    {
        float s = g1[cm16] * inv_bn;
        #pragma unroll
        for (int i = 0; i < 5; i++)
            w1p[i] = PACK2(w1[cm16 * 10 + 2 * i] * s, w1[cm16 * 10 + 2 * i + 1] * s);
        b1f = b1[cm16] * s + be1[cm16];
    }
    float b2f = b2[cm16] * (g2[cm16] * inv_bn) + be2[cm16];
    u64t fcp[16]; float fcb = fc2b[lane];
    #pragma unroll
    for (int i = 0; i < 16; i++)
        fcp[i] = PACK2(fc2w[lane * DD + 2 * i], fc2w[lane * DD + 2 * i + 1]);
    float apb = ap2b[lane] * (ap2g[lane] * inv_bn) + ap2be[lane];

    const int b  = blockIdx.x / (NN / 32);
    const int n0 = (blockIdx.x % (NN / 32)) * 32;
    const int pbase = b * NN + n0 + warp * 8;

    const unsigned feat_a = (unsigned)__cvta_generic_to_shared(&sh_feat[warp][0][0][0]);
    const unsigned nxyz_a = (unsigned)__cvta_generic_to_shared(&sh_nxyz[warp][0][0][0]);
    const unsigned fxyz_a = (unsigned)__cvta_generic_to_shared(&sh_fxyz[warp][0][0]);
    const unsigned fx1_a  = (unsigned)__cvta_generic_to_shared(&sh_fx1[warp][0][0]);
    const unsigned conv_a = (unsigned)__cvta_generic_to_shared(&sh_conv[warp][0][0]);
    const unsigned agg_a  = (unsigned)__cvta_generic_to_shared(&sh_agg[warp][0]);
    const unsigned appw_a = (unsigned)__cvta_generic_to_shared(&sh_appw[0][0]);
    const unsigned w2w_a  = (unsigned)__cvta_generic_to_shared(&sh_w2w[0][0]);

    {
        int4 iv = *(const int4*)(nidx + (size_t)pbase * KK + lane * 4);
        *(int4*)&sh_idx[warp][lane >> 2][(lane & 3) * 4] = iv;
    }
    if (lane < 24) sh_cxyz[warp][lane / 3][lane % 3] = xyz[pbase * 3 + lane];
    __syncthreads();   // covers weight fills too

    const int j2 = lane >> 1, h2 = lane & 1;

    #pragma unroll
    for (int s = 0; s < 4; s++) {
        int idx = sh_idx[warp][s][j2];
        const float* src = g_agg1 + (size_t)(b * NN + idx) * HH + h2 * 8;
        unsigned d = feat_a + s * 1024 + j2 * 64 + h2 * 32;
        cp16(d, src); cp16(d + 16, src + 4);
        if (lane < KK) {
            int ix = sh_idx[warp][s][lane];
            const float* xs = xyz + (size_t)(b * NN + ix) * 3;
            unsigned dn = nxyz_a + s * 256 + lane * 16;
            cp4(dn, xs); cp4(dn + 4, xs + 1); cp4(dn + 8, xs + 2);
        }
        cp_commit();
    }

    #pragma unroll
    for (int t = 0; t < 8; t++) {
        const int ln = warp * 8 + t;   // local point in [0,32)
        const int buf = t & 3;
        if (t < 5) cp_wait<3>(); else if (t == 5) cp_wait<2>();
        else if (t == 6) cp_wait<1>(); else cp_wait<0>();
        __syncwarp();

        // geometry
        if (lane < KK) {
            const float* np_ = &sh_nxyz[warp][buf][lane][0];
            float nx = np_[0], ny = np_[1], nz = np_[2];
            float cx = sh_cxyz[warp][t][0], cy = sh_cxyz[warp][t][1], cz = sh_cxyz[warp][t][2];
            float rx = cx - nx, ry = cy - ny, rz = cz - nz;
            float dis = sqrtf(rx * rx + ry * ry + rz * rz);
            float4* row = (float4*)&sh_fxyz[warp][lane][0];
            row[0] = make_float4(dis, rx, ry, rz);
            row[1] = make_float4(cx, cy, cz, nx);
            ((float2*)&sh_fxyz[warp][lane][8])[0] = make_float2(ny, nz);
        }
        __syncwarp();

        // conv1 recompute (10->16) -> sh_fx1
        {
            int jb = (lane >> 4) * 8;
            #pragma unroll
            for (int jj = 0; jj < 8; jj++) {
                int j = jb + jj;
                unsigned a = fxyz_a + j * 48;
                u64t x0, x1, x2, x3, x4;
                LDS2x64(x0, x1, a);
                LDS2x64(x2, x3, a + 16);
                x4 = LDS64(a + 32);
                u64t acc0 = PACK2(b1f, 0.f), acc1 = PACK2(0.f, 0.f);
                FMA2(acc0, x0, w1p[0]); FMA2(acc1, x1, w1p[1]);
                FMA2(acc0, x2, w1p[2]); FMA2(acc1, x3, w1p[3]);
                FMA2(acc0, x4, w1p[4]);
                ADD2(acc0, acc1);
                sh_fx1[warp][j][cm16] = lrelu(HSUM2(acc0));
            }
        }
        __syncwarp();

        // conv2 (16->16) + BN + LReLU -> sh_conv (weights from shared)
        {
            int jb = (lane >> 4) * 8;
            #pragma unroll
            for (int jj = 0; jj < 8; jj++) {
                int j = jb + jj;
                unsigned a = fx1_a + j * 64;
                u64t p0, p1, p2, p3;
                u64t acc0 = PACK2(b2f, 0.f), acc1 = PACK2(0.f, 0.f);
                LDS2x64(p0, p1, a);
                FMA2(acc0, p0, LDS64(w2w_a + 0 * 128 + cm16 * 8));
                FMA2(acc1, p1, LDS64(w2w_a + 1 * 128 + cm16 * 8));
                LDS2x64(p2, p3, a + 16);
                FMA2(acc0, p2, LDS64(w2w_a + 2 * 128 + cm16 * 8));
                FMA2(acc1, p3, LDS64(w2w_a + 3 * 128 + cm16 * 8));
                LDS2x64(p0, p1, a + 32);
                FMA2(acc0, p0, LDS64(w2w_a + 4 * 128 + cm16 * 8));
                FMA2(acc1, p1, LDS64(w2w_a + 5 * 128 + cm16 * 8));
                LDS2x64(p2, p3, a + 48);
                FMA2(acc0, p2, LDS64(w2w_a + 6 * 128 + cm16 * 8));
                FMA2(acc1, p3, LDS64(w2w_a + 7 * 128 + cm16 * 8));
                ADD2(acc0, acc1);
                sh_conv[warp][j][cm16] = lrelu(HSUM2(acc0));
            }
        }
        __syncwarp();

        // fc2 + softmax + weighted sum
        const unsigned fbuf_a = feat_a + buf * 1024;
        float sc[KK];
        #pragma unroll
        for (int j = 0; j < KK; j++) {
            unsigned fa = fbuf_a + j * 64;
            unsigned ca = conv_a + j * 64;
            u64t p0, p1, p2, p3;
            u64t acc0 = PACK2(fcb, 0.f), acc1 = PACK2(0.f, 0.f);
            LDS2x64(p0, p1, fa);      FMA2(acc0, p0, fcp[0]);  FMA2(acc1, p1, fcp[1]);
            LDS2x64(p2, p3, fa + 16); FMA2(acc0, p2, fcp[2]);  FMA2(acc1, p3, fcp[3]);
            LDS2x64(p0, p1, ca);      FMA2(acc0, p0, fcp[8]);  FMA2(acc1, p1, fcp[9]);
            LDS2x64(p2, p3, ca + 16); FMA2(acc0, p2, fcp[10]); FMA2(acc1, p3, fcp[11]);
            LDS2x64(p0, p1, fa + 32); FMA2(acc0, p0, fcp[4]);  FMA2(acc1, p1, fcp[5]);
            LDS2x64(p2, p3, fa + 48); FMA2(acc0, p2, fcp[6]);  FMA2(acc1, p3, fcp[7]);
            LDS2x64(p0, p1, ca + 32); FMA2(acc0, p0, fcp[12]); FMA2(acc1, p1, fcp[13]);
            LDS2x64(p2, p3, ca + 48); FMA2(acc0, p2, fcp[14]); FMA2(acc1, p3, fcp[15]);
            ADD2(acc0, acc1);
            sc[j] = HSUM2(acc0);
        }
        float ssum = 0.0f;
        #pragma unroll
        for (int j = 0; j < KK; j++) { sc[j] = __expf(sc[j]); ssum += sc[j]; }
        float inv = 1.0f / ssum;
        const float* wsp = (lane < HH) ? &sh_feat[warp][buf][0][lane]
                                       : &sh_conv[warp][0][lane - HH];
        float agg = 0.0f;
        #pragma unroll
        for (int j = 0; j < KK; j++)
            agg += wsp[j * HH] * (sc[j] * inv);
        sh_agg[warp][lane] = agg;
        __syncwarp();

        // issue prefetch for t+4 (buffer free now)
        if (t + 4 < 8) {
            int s = t + 4;
            int idx = sh_idx[warp][s][j2];
            const float* src = g_agg1 + (size_t)(b * NN + idx) * HH + h2 * 8;
            unsigned d = feat_a + (s & 3) * 1024 + j2 * 64 + h2 * 32;
            cp16(d, src); cp16(d + 16, src + 4);
            if (lane < KK) {
                int ix = sh_idx[warp][s][lane];
                const float* xs = xyz + (size_t)(b * NN + ix) * 3;
                unsigned dn = nxyz_a + (s & 3) * 256 + lane * 16;
                cp4(dn, xs); cp4(dn + 4, xs + 1); cp4(dn + 8, xs + 2);
            }
            cp_commit();
        }

        // mlp2 (32->32) + BN + LReLU, weights from shared
        {
            u64t acc0 = PACK2(apb, 0.f), acc1 = PACK2(0.f, 0.f);
            #pragma unroll
            for (int q = 0; q < 16; q += 2) {
                FMA2(acc0, LDS64(agg_a + q * 8),
                           LDS64(appw_a + q * 256 + lane * 8));
                FMA2(acc1, LDS64(agg_a + q * 8 + 8),
                           LDS64(appw_a + (q + 1) * 256 + lane * 8));
            }
            ADD2(acc0, acc1);
            sh_out[lane][ln] = lrelu(HSUM2(acc0));
        }
        __syncwarp();
    }

    __syncthreads();
    for (int e = threadIdx.x; e < DD * 32; e += 128) {
        int c = e >> 5, ln = e & 31;
        out[((size_t)b * DD + c) * NN + n0 + ln] = sh_out[c][ln];
    }
}

// ---------------------------------------------------------------------------
extern "C" void kernel_launch(void* const* d_in, const int* in_sizes, int n_in,
                              void* d_out, int out_size) {
    const float* xyz     = (const float*)d_in[0];
    const float* feature = (const float*)d_in[1];
    const int*   nidx    = (const int*)  d_in[2];
    const float* w1   = (const float*)d_in[3];
    const float* b1   = (const float*)d_in[4];
    const float* g1   = (const float*)d_in[5];
    const float* be1  = (const float*)d_in[6];
    const float* fc1w = (const float*)d_in[7];
    const float* fc1b = (const float*)d_in[8];
    const float* ap1w = (const float*)d_in[9];
    const float* ap1b = (const float*)d_in[10];
    const float* ap1g = (const float*)d_in[11];
    const float* ap1be= (const float*)d_in[12];
    const float* w2   = (const float*)d_in[13];
    const float* b2   = (const float*)d_in[14];
    const float* g2   = (const float*)d_in[15];
    const float* be2  = (const float*)d_in[16];
    const float* fc2w = (const float*)d_in[17];
    const float* fc2b = (const float*)d_in[18];
    const float* ap2w = (const float*)d_in[19];
    const float* ap2b = (const float*)d_in[20];
    const float* ap2g = (const float*)d_in[21];
    const float* ap2be= (const float*)d_in[22];
    float* out = (float*)d_out;

    transpose_feat_kernel<<<dim3(NN / 64, BB), 256>>>(feature);
    stage1_kernel<<<BB * NN / 32, 128>>>(xyz, nidx, w1, b1, g1, be1,
                                         fc1w, fc1b, ap1w, ap1b, ap1g, ap1be);
    stage2_kernel<<<BB * NN / 32, 128>>>(xyz, nidx, w1, b1, g1, be1,
                                         w2, b2, g2, be2, fc2w, fc2b,
                                         ap2w, ap2b, ap2g, ap2be, out);
}

// round 9
// speedup vs baseline: 1.7402x; 1.1088x over previous
#include <cuda_runtime.h>
#include <math.h>

#define BB 4
#define NN 40960
#define KK 16
#define HH 16
#define DD 32
#define BN_EPS 1e-5f

typedef unsigned long long u64t;

// scratch (device globals: no allocation allowed)
__device__ float g_feat_t[BB * NN * HH];        // feature transposed to [b, n, 16]
__device__ float g_agg1[BB * NN * HH];          // f_agg1 [b, n, 16]
__device__ float g_fx1[(size_t)BB * NN * KK * HH];  // f_xyz1 [b, n, k, 16] (168MB)

__device__ __forceinline__ float lrelu(float y) { return fmaxf(y, 0.2f * y); }

// ---- packed f32x2 helpers (sm_100+) ----
__device__ __forceinline__ void FMA2(u64t& d, u64t a, u64t b) {
    asm("fma.rn.f32x2 %0, %1, %2, %0;" : "+l"(d) : "l"(a), "l"(b));
}
__device__ __forceinline__ void ADD2(u64t& d, u64t a) {
    asm("add.rn.f32x2 %0, %0, %1;" : "+l"(d) : "l"(a));
}
__device__ __forceinline__ u64t PACK2(float lo, float hi) {
    u64t r; asm("mov.b64 %0, {%1, %2};" : "=l"(r) : "f"(lo), "f"(hi)); return r;
}
__device__ __forceinline__ float HSUM2(u64t v) {
    float lo, hi; asm("mov.b64 {%0, %1}, %2;" : "=f"(lo), "=f"(hi) : "l"(v));
    return lo + hi;
}
__device__ __forceinline__ void LDS2x64(u64t& a, u64t& b, unsigned addr) {
    asm volatile("ld.shared.v2.b64 {%0, %1}, [%2];" : "=l"(a), "=l"(b) : "r"(addr));
}
__device__ __forceinline__ u64t LDS64(unsigned addr) {
    u64t a; asm volatile("ld.shared.b64 %0, [%1];" : "=l"(a) : "r"(addr)); return a;
}

// ---- cp.async helpers ----
__device__ __forceinline__ void cp16(unsigned dst, const float* src) {
    asm volatile("cp.async.cg.shared.global [%0], [%1], 16;" :: "r"(dst), "l"(src));
}
__device__ __forceinline__ void cp4(unsigned dst, const float* src) {
    asm volatile("cp.async.ca.shared.global [%0], [%1], 4;" :: "r"(dst), "l"(src));
}
__device__ __forceinline__ void cp_commit() {
    asm volatile("cp.async.commit_group;");
}
template <int N> __device__ __forceinline__ void cp_wait() {
    asm volatile("cp.async.wait_group %0;" :: "n"(N));
}

// ---------------------------------------------------------------------------
// Transpose feature [B,16,N,1] -> [B*N,16]
// ---------------------------------------------------------------------------
__global__ void transpose_feat_kernel(const float* __restrict__ feature) {
    __shared__ float tile[HH][64 + 1];
    int b = blockIdx.y;
    int n0 = blockIdx.x * 64;
    int t = threadIdx.x;  // 256 threads
    int i = t & 63, cq = t >> 6;
    #pragma unroll
    for (int cc = cq; cc < HH; cc += 4)
        tile[cc][i] = feature[(b * HH + cc) * NN + n0 + i];
    __syncthreads();
    int c = t & 15, iq = t >> 4;
    #pragma unroll
    for (int ii = iq; ii < 64; ii += 16)
        g_feat_t[(b * NN + n0 + ii) * HH + c] = tile[c][ii];
}

// ---------------------------------------------------------------------------
// Stage 1: geometry + conv1(+BN,LReLU) + gather(feat) + att_pool_1 -> g_agg1
// Also writes f_xyz1 to g_fx1 so stage2 skips geometry+conv1 entirely.
// ---------------------------------------------------------------------------
__global__ void __launch_bounds__(128, 5) stage1_kernel(
    const float* __restrict__ xyz, const int* __restrict__ nidx,
    const float* __restrict__ w1, const float* __restrict__ b1,
    const float* __restrict__ g1, const float* __restrict__ be1,
    const float* __restrict__ fc1w, const float* __restrict__ fc1b,
    const float* __restrict__ ap1w, const float* __restrict__ ap1b,
    const float* __restrict__ ap1g, const float* __restrict__ ap1be)
{
    __shared__ __align__(16) float sh_feat[4][4][KK][HH];  // [warp][buf][j][c]
    __shared__ __align__(16) float sh_nxyz[4][4][KK][4];
    __shared__ __align__(16) float sh_fxyz[4][KK][12];
    __shared__ __align__(16) float sh_conv[4][KK][HH];
    __shared__ __align__(16) float sh_agg[4][DD];
    __shared__ __align__(16) int   sh_idx[4][8][KK];
    __shared__ float sh_cxyz[4][8][3];
    __shared__ __align__(16) u64t sh_appw[16][HH];         // mlp weights [pair q][outc]

    const int warp = threadIdx.x >> 5;
    const int lane = threadIdx.x & 31;
    const int cm16 = lane & 15;
    const float inv_bn = rsqrtf(1.0f + BN_EPS);

    for (int e = threadIdx.x; e < 16 * HH; e += 128) {
        int q = e >> 4, c = e & 15;
        float s = ap1g[c] * inv_bn;
        sh_appw[q][c] = PACK2(ap1w[c * DD + 2 * q] * s, ap1w[c * DD + 2 * q + 1] * s);
    }

    u64t w1p[5]; float b1f;
    {
        float s = g1[cm16] * inv_bn;
        #pragma unroll
        for (int i = 0; i < 5; i++)
            w1p[i] = PACK2(w1[cm16 * 10 + 2 * i] * s, w1[cm16 * 10 + 2 * i + 1] * s);
        b1f = b1[cm16] * s + be1[cm16];
    }
    u64t fcp[16]; float fcb = fc1b[lane];
    #pragma unroll
    for (int i = 0; i < 16; i++)
        fcp[i] = PACK2(fc1w[lane * DD + 2 * i], fc1w[lane * DD + 2 * i + 1]);
    float apb = ap1b[cm16] * (ap1g[cm16] * inv_bn) + ap1be[cm16];

    const int b  = blockIdx.x / (NN / 32);
    const int n0 = (blockIdx.x % (NN / 32)) * 32;
    const int pbase = b * NN + n0 + warp * 8;

    const unsigned feat_a = (unsigned)__cvta_generic_to_shared(&sh_feat[warp][0][0][0]);
    const unsigned nxyz_a = (unsigned)__cvta_generic_to_shared(&sh_nxyz[warp][0][0][0]);
    const unsigned fxyz_a = (unsigned)__cvta_generic_to_shared(&sh_fxyz[warp][0][0]);
    const unsigned conv_a = (unsigned)__cvta_generic_to_shared(&sh_conv[warp][0][0]);
    const unsigned agg_a  = (unsigned)__cvta_generic_to_shared(&sh_agg[warp][0]);
    const unsigned appw_a = (unsigned)__cvta_generic_to_shared(&sh_appw[0][0]);

    {
        int4 iv = *(const int4*)(nidx + (size_t)pbase * KK + lane * 4);
        *(int4*)&sh_idx[warp][lane >> 2][(lane & 3) * 4] = iv;
    }
    if (lane < 24) sh_cxyz[warp][lane / 3][lane % 3] = xyz[pbase * 3 + lane];
    __syncthreads();

    const int j2 = lane >> 1, h2 = lane & 1;

    #pragma unroll
    for (int s = 0; s < 4; s++) {
        int idx = sh_idx[warp][s][j2];
        const float* src = g_feat_t + (size_t)(b * NN + idx) * HH + h2 * 8;
        unsigned d = feat_a + s * 1024 + j2 * 64 + h2 * 32;
        cp16(d, src); cp16(d + 16, src + 4);
        if (lane < KK) {
            int ix = sh_idx[warp][s][lane];
            const float* xs = xyz + (size_t)(b * NN + ix) * 3;
            unsigned dn = nxyz_a + s * 256 + lane * 16;
            cp4(dn, xs); cp4(dn + 4, xs + 1); cp4(dn + 8, xs + 2);
        }
        cp_commit();
    }

    #pragma unroll
    for (int t = 0; t < 8; t++) {
        const int pn = pbase + t;
        const int buf = t & 3;
        if (t < 5) cp_wait<3>(); else if (t == 5) cp_wait<2>();
        else if (t == 6) cp_wait<1>(); else cp_wait<0>();
        __syncwarp();

        // geometry (lane<16)
        if (lane < KK) {
            const float* np_ = &sh_nxyz[warp][buf][lane][0];
            float nx = np_[0], ny = np_[1], nz = np_[2];
            float cx = sh_cxyz[warp][t][0], cy = sh_cxyz[warp][t][1], cz = sh_cxyz[warp][t][2];
            float rx = cx - nx, ry = cy - ny, rz = cz - nz;
            float dis = sqrtf(rx * rx + ry * ry + rz * rz);
            float4* row = (float4*)&sh_fxyz[warp][lane][0];
            row[0] = make_float4(dis, rx, ry, rz);
            row[1] = make_float4(cx, cy, cz, nx);
            ((float2*)&sh_fxyz[warp][lane][8])[0] = make_float2(ny, nz);
        }
        __syncwarp();

        // conv1 (10->16) + BN + LReLU -> sh_conv AND g_fx1
        {
            int jb = (lane >> 4) * 8;
            #pragma unroll
            for (int jj = 0; jj < 8; jj++) {
                int j = jb + jj;
                unsigned a = fxyz_a + j * 48;
                u64t x0, x1, x2, x3, x4;
                LDS2x64(x0, x1, a);
                LDS2x64(x2, x3, a + 16);
                x4 = LDS64(a + 32);
                u64t acc0 = PACK2(b1f, 0.f), acc1 = PACK2(0.f, 0.f);
                FMA2(acc0, x0, w1p[0]); FMA2(acc1, x1, w1p[1]);
                FMA2(acc0, x2, w1p[2]); FMA2(acc1, x3, w1p[3]);
                FMA2(acc0, x4, w1p[4]);
                ADD2(acc0, acc1);
                float v = lrelu(HSUM2(acc0));
                sh_conv[warp][j][cm16] = v;
                g_fx1[(size_t)pn * (KK * HH) + j * HH + cm16] = v;
            }
        }
        __syncwarp();

        // fc1 scores + softmax over k + weighted sum
        const unsigned fbuf_a = feat_a + buf * 1024;
        float sc[KK];
        #pragma unroll
        for (int j = 0; j < KK; j++) {
            unsigned fa = fbuf_a + j * 64;
            unsigned ca = conv_a + j * 64;
            u64t p0, p1, p2, p3;
            u64t acc0 = PACK2(fcb, 0.f), acc1 = PACK2(0.f, 0.f);
            LDS2x64(p0, p1, fa);      FMA2(acc0, p0, fcp[0]);  FMA2(acc1, p1, fcp[1]);
            LDS2x64(p2, p3, fa + 16); FMA2(acc0, p2, fcp[2]);  FMA2(acc1, p3, fcp[3]);
            LDS2x64(p0, p1, ca);      FMA2(acc0, p0, fcp[8]);  FMA2(acc1, p1, fcp[9]);
            LDS2x64(p2, p3, ca + 16); FMA2(acc0, p2, fcp[10]); FMA2(acc1, p3, fcp[11]);
            LDS2x64(p0, p1, fa + 32); FMA2(acc0, p0, fcp[4]);  FMA2(acc1, p1, fcp[5]);
            LDS2x64(p2, p3, fa + 48); FMA2(acc0, p2, fcp[6]);  FMA2(acc1, p3, fcp[7]);
            LDS2x64(p0, p1, ca + 32); FMA2(acc0, p0, fcp[12]); FMA2(acc1, p1, fcp[13]);
            LDS2x64(p2, p3, ca + 48); FMA2(acc0, p2, fcp[14]); FMA2(acc1, p3, fcp[15]);
            ADD2(acc0, acc1);
            sc[j] = HSUM2(acc0);
        }
        float ssum = 0.0f;
        #pragma unroll
        for (int j = 0; j < KK; j++) { sc[j] = __expf(sc[j]); ssum += sc[j]; }
        float inv = 1.0f / ssum;
        const float* wsp = (lane < HH) ? &sh_feat[warp][buf][0][lane]
                                       : &sh_conv[warp][0][lane - HH];
        float agg = 0.0f;
        #pragma unroll
        for (int j = 0; j < KK; j++)
            agg += wsp[j * HH] * (sc[j] * inv);
        sh_agg[warp][lane] = agg;
        __syncwarp();

        // prefetch for t+4
        if (t + 4 < 8) {
            int s = t + 4;
            int idx = sh_idx[warp][s][j2];
            const float* src = g_feat_t + (size_t)(b * NN + idx) * HH + h2 * 8;
            unsigned d = feat_a + (s & 3) * 1024 + j2 * 64 + h2 * 32;
            cp16(d, src); cp16(d + 16, src + 4);
            if (lane < KK) {
                int ix = sh_idx[warp][s][lane];
                const float* xs = xyz + (size_t)(b * NN + ix) * 3;
                unsigned dn = nxyz_a + (s & 3) * 256 + lane * 16;
                cp4(dn, xs); cp4(dn + 4, xs + 1); cp4(dn + 8, xs + 2);
            }
            cp_commit();
        }

        // mlp (32->16) + BN + LReLU, weights from shared
        if (lane < HH) {
            u64t acc0 = PACK2(apb, 0.f), acc1 = PACK2(0.f, 0.f);
            #pragma unroll
            for (int q = 0; q < 16; q += 2) {
                FMA2(acc0, LDS64(agg_a + q * 8),
                           LDS64(appw_a + q * 128 + lane * 8));
                FMA2(acc1, LDS64(agg_a + q * 8 + 8),
                           LDS64(appw_a + (q + 1) * 128 + lane * 8));
            }
            ADD2(acc0, acc1);
            g_agg1[(size_t)pn * HH + lane] = lrelu(HSUM2(acc0));
        }
        __syncwarp();
    }
}

// ---------------------------------------------------------------------------
// Stage 2: load f_xyz1 (coalesced) + gather(f_agg1) + conv2 + att_pool_2.
// No geometry, no conv1 recompute.
// ---------------------------------------------------------------------------
__global__ void __launch_bounds__(128, 4) stage2_kernel(
    const int* __restrict__ nidx,
    const float* __restrict__ w2, const float* __restrict__ b2,
    const float* __restrict__ g2, const float* __restrict__ be2,
    const float* __restrict__ fc2w, const float* __restrict__ fc2b,
    const float* __restrict__ ap2w, const float* __restrict__ ap2b,
    const float* __restrict__ ap2g, const float* __restrict__ ap2be,
    float* __restrict__ out)
{
    __shared__ __align__(16) float sh_feat[4][4][KK][HH];  // gathered g_agg1
    __shared__ __align__(16) float sh_fx1[4][4][KK][HH];   // loaded f_xyz1
    __shared__ __align__(16) float sh_conv[4][KK][HH];     // conv2 out (f_xyz2)
    __shared__ __align__(16) float sh_agg[4][DD];
    __shared__ __align__(16) int   sh_idx[4][8][KK];
    __shared__ float sh_out[DD][33];
    __shared__ __align__(16) u64t sh_appw[16][DD];         // mlp2 weights

    const int warp = threadIdx.x >> 5;
    const int lane = threadIdx.x & 31;
    const int cm16 = lane & 15;
    const float inv_bn = rsqrtf(1.0f + BN_EPS);

    for (int e = threadIdx.x; e < 16 * DD; e += 128) {
        int q = e >> 5, c = e & 31;
        float s = ap2g[c] * inv_bn;
        sh_appw[q][c] = PACK2(ap2w[c * DD + 2 * q] * s, ap2w[c * DD + 2 * q + 1] * s);
    }

    u64t w2p[8]; float b2f;
    {
        float s = g2[cm16] * inv_bn;
        #pragma unroll
        for (int i = 0; i < 8; i++)
            w2p[i] = PACK2(w2[cm16 * HH + 2 * i] * s, w2[cm16 * HH + 2 * i + 1] * s);
        b2f = b2[cm16] * s + be2[cm16];
    }
    u64t fcp[16]; float fcb = fc2b[lane];
    #pragma unroll
    for (int i = 0; i < 16; i++)
        fcp[i] = PACK2(fc2w[lane * DD + 2 * i], fc2w[lane * DD + 2 * i + 1]);
    float apb = ap2b[lane] * (ap2g[lane] * inv_bn) + ap2be[lane];

    const int b  = blockIdx.x / (NN / 32);
    const int n0 = (blockIdx.x % (NN / 32)) * 32;
    const int pbase = b * NN + n0 + warp * 8;

    const unsigned feat_a = (unsigned)__cvta_generic_to_shared(&sh_feat[warp][0][0][0]);
    const unsigned fx1_a  = (unsigned)__cvta_generic_to_shared(&sh_fx1[warp][0][0][0]);
    const unsigned conv_a = (unsigned)__cvta_generic_to_shared(&sh_conv[warp][0][0]);
    const unsigned agg_a  = (unsigned)__cvta_generic_to_shared(&sh_agg[warp][0]);
    const unsigned appw_a = (unsigned)__cvta_generic_to_shared(&sh_appw[0][0]);

    {
        int4 iv = *(const int4*)(nidx + (size_t)pbase * KK + lane * 4);
        *(int4*)&sh_idx[warp][lane >> 2][(lane & 3) * 4] = iv;
    }
    __syncthreads();

    const int j2 = lane >> 1, h2 = lane & 1;

    #pragma unroll
    for (int s = 0; s < 4; s++) {
        int idx = sh_idx[warp][s][j2];
        const float* src = g_agg1 + (size_t)(b * NN + idx) * HH + h2 * 8;
        unsigned d = feat_a + s * 1024 + j2 * 64 + h2 * 32;
        cp16(d, src); cp16(d + 16, src + 4);
        {   // coalesced f_xyz1 tile: 1KB per point, 32B per lane
            const float* fs = g_fx1 + (size_t)(pbase + s) * (KK * HH) + lane * 8;
            unsigned fd = fx1_a + s * 1024 + lane * 32;
            cp16(fd, fs); cp16(fd + 16, fs + 4);
        }
        cp_commit();
    }

    #pragma unroll
    for (int t = 0; t < 8; t++) {
        const int ln = warp * 8 + t;   // local point in [0,32)
        const int buf = t & 3;
        if (t < 5) cp_wait<3>(); else if (t == 5) cp_wait<2>();
        else if (t == 6) cp_wait<1>(); else cp_wait<0>();
        __syncwarp();

        // conv2 (16->16) + BN + LReLU -> sh_conv
        {
            int jb = (lane >> 4) * 8;
            const unsigned fb = fx1_a + buf * 1024;
            #pragma unroll
            for (int jj = 0; jj < 8; jj++) {
                int j = jb + jj;
                unsigned a = fb + j * 64;
                u64t p0, p1, p2, p3;
                u64t acc0 = PACK2(b2f, 0.f), acc1 = PACK2(0.f, 0.f);
                LDS2x64(p0, p1, a);      FMA2(acc0, p0, w2p[0]); FMA2(acc1, p1, w2p[1]);
                LDS2x64(p2, p3, a + 16); FMA2(acc0, p2, w2p[2]); FMA2(acc1, p3, w2p[3]);
                LDS2x64(p0, p1, a + 32); FMA2(acc0, p0, w2p[4]); FMA2(acc1, p1, w2p[5]);
                LDS2x64(p2, p3, a + 48); FMA2(acc0, p2, w2p[6]); FMA2(acc1, p3, w2p[7]);
                ADD2(acc0, acc1);
                sh_conv[warp][j][cm16] = lrelu(HSUM2(acc0));
            }
        }
        __syncwarp();

        // fc2 + softmax + weighted sum
        const unsigned fbuf_a = feat_a + buf * 1024;
        float sc[KK];
        #pragma unroll
        for (int j = 0; j < KK; j++) {
            unsigned fa = fbuf_a + j * 64;
            unsigned ca = conv_a + j * 64;
            u64t p0, p1, p2, p3;
            u64t acc0 = PACK2(fcb, 0.f), acc1 = PACK2(0.f, 0.f);
            LDS2x64(p0, p1, fa);      FMA2(acc0, p0, fcp[0]);  FMA2(acc1, p1, fcp[1]);
            LDS2x64(p2, p3, fa + 16); FMA2(acc0, p2, fcp[2]);  FMA2(acc1, p3, fcp[3]);
            LDS2x64(p0, p1, ca);      FMA2(acc0, p0, fcp[8]);  FMA2(acc1, p1, fcp[9]);
            LDS2x64(p2, p3, ca + 16); FMA2(acc0, p2, fcp[10]); FMA2(acc1, p3, fcp[11]);
            LDS2x64(p0, p1, fa + 32); FMA2(acc0, p0, fcp[4]);  FMA2(acc1, p1, fcp[5]);
            LDS2x64(p2, p3, fa + 48); FMA2(acc0, p2, fcp[6]);  FMA2(acc1, p3, fcp[7]);
            LDS2x64(p0, p1, ca + 32); FMA2(acc0, p0, fcp[12]); FMA2(acc1, p1, fcp[13]);
            LDS2x64(p2, p3, ca + 48); FMA2(acc0, p2, fcp[14]); FMA2(acc1, p3, fcp[15]);
            ADD2(acc0, acc1);
            sc[j] = HSUM2(acc0);
        }
        float ssum = 0.0f;
        #pragma unroll
        for (int j = 0; j < KK; j++) { sc[j] = __expf(sc[j]); ssum += sc[j]; }
        float inv = 1.0f / ssum;
        const float* wsp = (lane < HH) ? &sh_feat[warp][buf][0][lane]
                                       : &sh_conv[warp][0][lane - HH];
        float agg = 0.0f;
        #pragma unroll
        for (int j = 0; j < KK; j++)
            agg += wsp[j * HH] * (sc[j] * inv);
        sh_agg[warp][lane] = agg;
        __syncwarp();

        // prefetch for t+4
        if (t + 4 < 8) {
            int s = t + 4;
            int idx = sh_idx[warp][s][j2];
            const float* src = g_agg1 + (size_t)(b * NN + idx) * HH + h2 * 8;
            unsigned d = feat_a + (s & 3) * 1024 + j2 * 64 + h2 * 32;
            cp16(d, src); cp16(d + 16, src + 4);
            {
                const float* fs = g_fx1 + (size_t)(pbase + s) * (KK * HH) + lane * 8;
                unsigned fd = fx1_a + (s & 3) * 1024 + lane * 32;
                cp16(fd, fs); cp16(fd + 16, fs + 4);
            }
            cp_commit();
        }

        // mlp2 (32->32) + BN + LReLU, weights from shared
        {
            u64t acc0 = PACK2(apb, 0.f), acc1 = PACK2(0.f, 0.f);
            #pragma unroll
            for (int q = 0; q < 16; q += 2) {
                FMA2(acc0, LDS64(agg_a + q * 8),
                           LDS64(appw_a + q * 256 + lane * 8));
                FMA2(acc1, LDS64(agg_a + q * 8 + 8),
                           LDS64(appw_a + (q + 1) * 256 + lane * 8));
            }
            ADD2(acc0, acc1);
            sh_out[lane][ln] = lrelu(HSUM2(acc0));
        }
        __syncwarp();
    }

    __syncthreads();
    for (int e = threadIdx.x; e < DD * 32; e += 128) {
        int c = e >> 5, ln = e & 31;
        out[((size_t)b * DD + c) * NN + n0 + ln] = sh_out[c][ln];
    }
}

// ---------------------------------------------------------------------------
extern "C" void kernel_launch(void* const* d_in, const int* in_sizes, int n_in,
                              void* d_out, int out_size) {
    const float* xyz     = (const float*)d_in[0];
    const float* feature = (const float*)d_in[1];
    const int*   nidx    = (const int*)  d_in[2];
    const float* w1   = (const float*)d_in[3];
    const float* b1   = (const float*)d_in[4];
    const float* g1   = (const float*)d_in[5];
    const float* be1  = (const float*)d_in[6];
    const float* fc1w = (const float*)d_in[7];
    const float* fc1b = (const float*)d_in[8];
    const float* ap1w = (const float*)d_in[9];
    const float* ap1b = (const float*)d_in[10];
    const float* ap1g = (const float*)d_in[11];
    const float* ap1be= (const float*)d_in[12];
    const float* w2   = (const float*)d_in[13];
    const float* b2   = (const float*)d_in[14];
    const float* g2   = (const float*)d_in[15];
    const float* be2  = (const float*)d_in[16];
    const float* fc2w = (const float*)d_in[17];
    const float* fc2b = (const float*)d_in[18];
    const float* ap2w = (const float*)d_in[19];
    const float* ap2b = (const float*)d_in[20];
    const float* ap2g = (const float*)d_in[21];
    const float* ap2be= (const float*)d_in[22];
    float* out = (float*)d_out;

    transpose_feat_kernel<<<dim3(NN / 64, BB), 256>>>(feature);
    stage1_kernel<<<BB * NN / 32, 128>>>(xyz, nidx, w1, b1, g1, be1,
                                         fc1w, fc1b, ap1w, ap1b, ap1g, ap1be);
    stage2_kernel<<<BB * NN / 32, 128>>>(nidx, w2, b2, g2, be2, fc2w, fc2b,
                                         ap2w, ap2b, ap2g, ap2be, out);
}

// round 11
// speedup vs baseline: 3.5112x; 2.0176x over previous
#include <cuda_runtime.h>
#include <math.h>
#include <stdint.h>

#define BB 4
#define NN 40960
#define KK 16
#define HH 16
#define DD 32
#define BN_EPS 1e-5f
#define RS 20            // padded row stride (floats) for mma-fed tiles
#define RSB 80           // row stride bytes

typedef unsigned long long u64t;

__device__ float g_feat_t[BB * NN * HH];
__device__ float g_agg1[BB * NN * HH];
__device__ float g_fx1[(size_t)BB * NN * KK * HH];  // f_xyz1 [b,n,k,16]

__device__ __forceinline__ float lrelu(float y) { return fmaxf(y, 0.2f * y); }

// ---- packed f32x2 helpers ----
__device__ __forceinline__ void FMA2(u64t& d, u64t a, u64t b) {
    asm("fma.rn.f32x2 %0, %1, %2, %0;" : "+l"(d) : "l"(a), "l"(b));
}
__device__ __forceinline__ void ADD2(u64t& d, u64t a) {
    asm("add.rn.f32x2 %0, %0, %1;" : "+l"(d) : "l"(a));
}
__device__ __forceinline__ u64t PACK2(float lo, float hi) {
    u64t r; asm("mov.b64 %0, {%1, %2};" : "=l"(r) : "f"(lo), "f"(hi)); return r;
}
__device__ __forceinline__ float HSUM2(u64t v) {
    float lo, hi; asm("mov.b64 {%0, %1}, %2;" : "=f"(lo), "=f"(hi) : "l"(v));
    return lo + hi;
}
__device__ __forceinline__ void LDS2x64(u64t& a, u64t& b, unsigned addr) {
    asm volatile("ld.shared.v2.b64 {%0, %1}, [%2];" : "=l"(a), "=l"(b) : "r"(addr));
}
__device__ __forceinline__ u64t LDS64(unsigned addr) {
    u64t a; asm volatile("ld.shared.b64 %0, [%1];" : "=l"(a) : "r"(addr)); return a;
}
__device__ __forceinline__ uint32_t LDSU(unsigned addr) {
    uint32_t v; asm volatile("ld.shared.b32 %0, [%1];" : "=r"(v) : "r"(addr)); return v;
}
__device__ __forceinline__ float LDSF(unsigned addr) {
    float v; asm volatile("ld.shared.f32 %0, [%1];" : "=f"(v) : "r"(addr)); return v;
}

// tf32 mma m16n8k8: D += A*B (A row-major 16x8, B col-major 8x8)
#define MMA_TF32(d, a, b0, b1) \
    asm volatile("mma.sync.aligned.m16n8k8.row.col.f32.tf32.tf32.f32 " \
        "{%0,%1,%2,%3}, {%4,%5,%6,%7}, {%8,%9}, {%0,%1,%2,%3};" \
        : "+f"((d)[0]), "+f"((d)[1]), "+f"((d)[2]), "+f"((d)[3]) \
        : "r"((a)[0]), "r"((a)[1]), "r"((a)[2]), "r"((a)[3]), "r"(b0), "r"(b1))

// ---- cp.async helpers ----
__device__ __forceinline__ void cp16(unsigned dst, const float* src) {
    asm volatile("cp.async.cg.shared.global [%0], [%1], 16;" :: "r"(dst), "l"(src));
}
__device__ __forceinline__ void cp4(unsigned dst, const float* src) {
    asm volatile("cp.async.ca.shared.global [%0], [%1], 4;" :: "r"(dst), "l"(src));
}
__device__ __forceinline__ void cp_commit() {
    asm volatile("cp.async.commit_group;");
}
template <int N> __device__ __forceinline__ void cp_wait() {
    asm volatile("cp.async.wait_group %0;" :: "n"(N));
}

// ---------------------------------------------------------------------------
__global__ void transpose_feat_kernel(const float* __restrict__ feature) {
    __shared__ float tile[HH][64 + 1];
    int b = blockIdx.y;
    int n0 = blockIdx.x * 64;
    int t = threadIdx.x;
    int i = t & 63, cq = t >> 6;
    #pragma unroll
    for (int cc = cq; cc < HH; cc += 4)
        tile[cc][i] = feature[(b * HH + cc) * NN + n0 + i];
    __syncthreads();
    int c = t & 15, iq = t >> 4;
    #pragma unroll
    for (int ii = iq; ii < 64; ii += 16)
        g_feat_t[(b * NN + n0 + ii) * HH + c] = tile[c][ii];
}

// ---------------------------------------------------------------------------
// Stage 1: geometry + conv1 + gather(feat) + mma-fc + softmax-pool + mlp
// ---------------------------------------------------------------------------
__global__ void __launch_bounds__(128, 5) stage1_kernel(
    const float* __restrict__ xyz, const int* __restrict__ nidx,
    const float* __restrict__ w1, const float* __restrict__ b1,
    const float* __restrict__ g1, const float* __restrict__ be1,
    const float* __restrict__ fc1w, const float* __restrict__ fc1b,
    const float* __restrict__ ap1w, const float* __restrict__ ap1b,
    const float* __restrict__ ap1g, const float* __restrict__ ap1be)
{
    __shared__ __align__(16) float sh_feat[4][4][KK][RS];
    __shared__ __align__(16) float sh_nxyz[4][4][KK][4];
    __shared__ __align__(16) float sh_fxyz[4][KK][12];
    __shared__ __align__(16) float sh_conv[4][KK][RS];
    __shared__ __align__(16) float sh_agg[4][DD];
    __shared__ __align__(16) int   sh_idx[4][8][KK];
    __shared__ float sh_cxyz[4][8][3];
    __shared__ __align__(16) u64t sh_appw[16][HH];

    const int warp = threadIdx.x >> 5;
    const int lane = threadIdx.x & 31;
    const int cm16 = lane & 15;
    const int g = lane >> 2, tq = lane & 3;
    const float inv_bn = rsqrtf(1.0f + BN_EPS);

    for (int e = threadIdx.x; e < 16 * HH; e += 128) {
        int q = e >> 4, c = e & 15;
        float s = ap1g[c] * inv_bn;
        sh_appw[q][c] = PACK2(ap1w[c * DD + 2 * q] * s, ap1w[c * DD + 2 * q + 1] * s);
    }

    u64t w1p[5]; float b1f;
    {
        float s = g1[cm16] * inv_bn;
        #pragma unroll
        for (int i = 0; i < 5; i++)
            w1p[i] = PACK2(w1[cm16 * 10 + 2 * i] * s, w1[cm16 * 10 + 2 * i + 1] * s);
        b1f = b1[cm16] * s + be1[cm16];
    }
    // fc weight fragments (tf32 A): aw[(mT*4+kT)*4 + q]
    uint32_t aw[32];
    #pragma unroll
    for (int mT = 0; mT < 2; mT++)
        #pragma unroll
        for (int kT = 0; kT < 4; kT++) {
            int r0 = 16 * mT + g, r1 = r0 + 8, d0 = 8 * kT + tq, d1 = d0 + 4;
            int o = (mT * 4 + kT) * 4;
            aw[o + 0] = __float_as_uint(fc1w[r0 * DD + d0]);
            aw[o + 1] = __float_as_uint(fc1w[r1 * DD + d0]);
            aw[o + 2] = __float_as_uint(fc1w[r0 * DD + d1]);
            aw[o + 3] = __float_as_uint(fc1w[r1 * DD + d1]);
        }
    float apb = ap1b[cm16] * (ap1g[cm16] * inv_bn) + ap1be[cm16];

    const int b  = blockIdx.x / (NN / 32);
    const int n0 = (blockIdx.x % (NN / 32)) * 32;
    const int pbase = b * NN + n0 + warp * 8;

    const unsigned feat_a = (unsigned)__cvta_generic_to_shared(&sh_feat[warp][0][0][0]);
    const unsigned nxyz_a = (unsigned)__cvta_generic_to_shared(&sh_nxyz[warp][0][0][0]);
    const unsigned fxyz_a = (unsigned)__cvta_generic_to_shared(&sh_fxyz[warp][0][0]);
    const unsigned conv_a = (unsigned)__cvta_generic_to_shared(&sh_conv[warp][0][0]);
    const unsigned agg_a  = (unsigned)__cvta_generic_to_shared(&sh_agg[warp][0]);
    const unsigned appw_a = (unsigned)__cvta_generic_to_shared(&sh_appw[0][0]);

    {
        int4 iv = *(const int4*)(nidx + (size_t)pbase * KK + lane * 4);
        *(int4*)&sh_idx[warp][lane >> 2][(lane & 3) * 4] = iv;
    }
    if (lane < 24) sh_cxyz[warp][lane / 3][lane % 3] = xyz[pbase * 3 + lane];
    __syncthreads();

    const int j2 = lane >> 1, h2 = lane & 1;

    #pragma unroll
    for (int s = 0; s < 4; s++) {
        int idx = sh_idx[warp][s][j2];
        const float* src = g_feat_t + (size_t)(b * NN + idx) * HH + h2 * 8;
        unsigned d = feat_a + s * (KK * RSB) + j2 * RSB + h2 * 32;
        cp16(d, src); cp16(d + 16, src + 4);
        if (lane < KK) {
            int ix = sh_idx[warp][s][lane];
            const float* xs = xyz + (size_t)(b * NN + ix) * 3;
            unsigned dn = nxyz_a + s * 256 + lane * 16;
            cp4(dn, xs); cp4(dn + 4, xs + 1); cp4(dn + 8, xs + 2);
        }
        cp_commit();
    }

    #pragma unroll
    for (int t = 0; t < 8; t++) {
        const int pn = pbase + t;
        const int buf = t & 3;
        if (t < 5) cp_wait<3>(); else if (t == 5) cp_wait<2>();
        else if (t == 6) cp_wait<1>(); else cp_wait<0>();
        __syncwarp();

        // geometry
        if (lane < KK) {
            const float* np_ = &sh_nxyz[warp][buf][lane][0];
            float nx = np_[0], ny = np_[1], nz = np_[2];
            float cx = sh_cxyz[warp][t][0], cy = sh_cxyz[warp][t][1], cz = sh_cxyz[warp][t][2];
            float rx = cx - nx, ry = cy - ny, rz = cz - nz;
            float dis = sqrtf(rx * rx + ry * ry + rz * rz);
            float4* row = (float4*)&sh_fxyz[warp][lane][0];
            row[0] = make_float4(dis, rx, ry, rz);
            row[1] = make_float4(cx, cy, cz, nx);
            ((float2*)&sh_fxyz[warp][lane][8])[0] = make_float2(ny, nz);
        }
        __syncwarp();

        // conv1 (10->16) -> sh_conv + g_fx1
        {
            int jb = (lane >> 4) * 8;
            #pragma unroll
            for (int jj = 0; jj < 8; jj++) {
                int j = jb + jj;
                unsigned a = fxyz_a + j * 48;
                u64t x0, x1, x2, x3, x4;
                LDS2x64(x0, x1, a);
                LDS2x64(x2, x3, a + 16);
                x4 = LDS64(a + 32);
                u64t acc0 = PACK2(b1f, 0.f), acc1 = PACK2(0.f, 0.f);
                FMA2(acc0, x0, w1p[0]); FMA2(acc1, x1, w1p[1]);
                FMA2(acc0, x2, w1p[2]); FMA2(acc1, x3, w1p[3]);
                FMA2(acc0, x4, w1p[4]);
                ADD2(acc0, acc1);
                float v = lrelu(HSUM2(acc0));
                sh_conv[warp][j][cm16] = v;
                g_fx1[(size_t)pn * (KK * HH) + j * HH + cm16] = v;
            }
        }
        __syncwarp();

        // ---- fc via tf32 mma: scores^T(32c x 16j) = W @ X^T ----
        const unsigned fbuf_a = feat_a + buf * (KK * RSB);
        float s[16];
        #pragma unroll
        for (int nT = 0; nT < 2; nT++) {
            float c0[4] = {0.f, 0.f, 0.f, 0.f}, c1[4] = {0.f, 0.f, 0.f, 0.f};
            int j = g + 8 * nT;
            unsigned xf = fbuf_a + j * RSB;
            unsigned xc = conv_a + j * RSB;
            #pragma unroll
            for (int kT = 0; kT < 4; kT++) {
                unsigned base = (kT < 2) ? (xf + (8 * kT + tq) * 4)
                                         : (xc + (8 * (kT - 2) + tq) * 4);
                uint32_t b0v = LDSU(base), b1v = LDSU(base + 16);
                MMA_TF32(c0, &aw[(0 * 4 + kT) * 4], b0v, b1v);
                MMA_TF32(c1, &aw[(1 * 4 + kT) * 4], b0v, b1v);
            }
            #pragma unroll
            for (int q = 0; q < 4; q++) {
                s[(nT * 2 + 0) * 4 + q] = c0[q];
                s[(nT * 2 + 1) * 4 + q] = c1[q];
            }
        }
        // exp (bias cancels in softmax)
        #pragma unroll
        for (int i = 0; i < 16; i++) s[i] = __expf(s[i]);
        // per-channel sums over j (in-lane 4 + quad reduce)
        float p0 = s[0] + s[1] + s[8]  + s[9];
        float p1 = s[2] + s[3] + s[10] + s[11];
        float p2 = s[4] + s[5] + s[12] + s[13];
        float p3 = s[6] + s[7] + s[14] + s[15];
        p0 += __shfl_xor_sync(0xffffffffu, p0, 1); p0 += __shfl_xor_sync(0xffffffffu, p0, 2);
        p1 += __shfl_xor_sync(0xffffffffu, p1, 1); p1 += __shfl_xor_sync(0xffffffffu, p1, 2);
        p2 += __shfl_xor_sync(0xffffffffu, p2, 1); p2 += __shfl_xor_sync(0xffffffffu, p2, 2);
        p3 += __shfl_xor_sync(0xffffffffu, p3, 1); p3 += __shfl_xor_sync(0xffffffffu, p3, 2);
        // weighted pool
        {
            int j0 = 2 * tq, j1 = j0 + 1, j8 = j0 + 8, j9 = j0 + 9;
            unsigned cF0 = g * 4, cF1 = (g + 8) * 4;
            float a0 = LDSF(fbuf_a + j0 * RSB + cF0) * s[0] + LDSF(fbuf_a + j1 * RSB + cF0) * s[1]
                     + LDSF(fbuf_a + j8 * RSB + cF0) * s[8] + LDSF(fbuf_a + j9 * RSB + cF0) * s[9];
            float a1 = LDSF(fbuf_a + j0 * RSB + cF1) * s[2] + LDSF(fbuf_a + j1 * RSB + cF1) * s[3]
                     + LDSF(fbuf_a + j8 * RSB + cF1) * s[10] + LDSF(fbuf_a + j9 * RSB + cF1) * s[11];
            float a2 = LDSF(conv_a + j0 * RSB + cF0) * s[4] + LDSF(conv_a + j1 * RSB + cF0) * s[5]
                     + LDSF(conv_a + j8 * RSB + cF0) * s[12] + LDSF(conv_a + j9 * RSB + cF0) * s[13];
            float a3 = LDSF(conv_a + j0 * RSB + cF1) * s[6] + LDSF(conv_a + j1 * RSB + cF1) * s[7]
                     + LDSF(conv_a + j8 * RSB + cF1) * s[14] + LDSF(conv_a + j9 * RSB + cF1) * s[15];
            a0 += __shfl_xor_sync(0xffffffffu, a0, 1); a0 += __shfl_xor_sync(0xffffffffu, a0, 2);
            a1 += __shfl_xor_sync(0xffffffffu, a1, 1); a1 += __shfl_xor_sync(0xffffffffu, a1, 2);
            a2 += __shfl_xor_sync(0xffffffffu, a2, 1); a2 += __shfl_xor_sync(0xffffffffu, a2, 2);
            a3 += __shfl_xor_sync(0xffffffffu, a3, 1); a3 += __shfl_xor_sync(0xffffffffu, a3, 2);
            if (tq == 0) {
                sh_agg[warp][g]      = __fdividef(a0, p0);
                sh_agg[warp][g + 8]  = __fdividef(a1, p1);
                sh_agg[warp][g + 16] = __fdividef(a2, p2);
                sh_agg[warp][g + 24] = __fdividef(a3, p3);
            }
        }
        __syncwarp();

        // prefetch for t+4
        if (t + 4 < 8) {
            int sN = t + 4;
            int idx = sh_idx[warp][sN][j2];
            const float* src = g_feat_t + (size_t)(b * NN + idx) * HH + h2 * 8;
            unsigned d = feat_a + (sN & 3) * (KK * RSB) + j2 * RSB + h2 * 32;
            cp16(d, src); cp16(d + 16, src + 4);
            if (lane < KK) {
                int ix = sh_idx[warp][sN][lane];
                const float* xs = xyz + (size_t)(b * NN + ix) * 3;
                unsigned dn = nxyz_a + (sN & 3) * 256 + lane * 16;
                cp4(dn, xs); cp4(dn + 4, xs + 1); cp4(dn + 8, xs + 2);
            }
            cp_commit();
        }

        // mlp (32->16)
        if (lane < HH) {
            u64t acc0 = PACK2(apb, 0.f), acc1 = PACK2(0.f, 0.f);
            #pragma unroll
            for (int q = 0; q < 16; q += 2) {
                FMA2(acc0, LDS64(agg_a + q * 8),
                           LDS64(appw_a + q * 128 + lane * 8));
                FMA2(acc1, LDS64(agg_a + q * 8 + 8),
                           LDS64(appw_a + (q + 1) * 128 + lane * 8));
            }
            ADD2(acc0, acc1);
            g_agg1[(size_t)pn * HH + lane] = lrelu(HSUM2(acc0));
        }
        __syncwarp();
    }
}

// ---------------------------------------------------------------------------
// Stage 2: load f_xyz1 + gather(f_agg1) + conv2 + mma-fc2 + pool + mlp2
// Ring depth 3 (smem limit with padded rows).
// ---------------------------------------------------------------------------
__global__ void __launch_bounds__(128, 4) stage2_kernel(
    const int* __restrict__ nidx,
    const float* __restrict__ w2, const float* __restrict__ b2,
    const float* __restrict__ g2, const float* __restrict__ be2,
    const float* __restrict__ fc2w, const float* __restrict__ fc2b,
    const float* __restrict__ ap2w, const float* __restrict__ ap2b,
    const float* __restrict__ ap2g, const float* __restrict__ ap2be,
    float* __restrict__ out)
{
    __shared__ __align__(16) float sh_feat[4][3][KK][RS];
    __shared__ __align__(16) float sh_fx1[4][3][KK][HH];
    __shared__ __align__(16) float sh_conv[4][KK][RS];
    __shared__ __align__(16) float sh_agg[4][DD];
    __shared__ __align__(16) int   sh_idx[4][8][KK];
    __shared__ float sh_out[DD][33];
    __shared__ __align__(16) u64t sh_appw[16][DD];

    const int warp = threadIdx.x >> 5;
    const int lane = threadIdx.x & 31;
    const int cm16 = lane & 15;
    const int g = lane >> 2, tq = lane & 3;
    const float inv_bn = rsqrtf(1.0f + BN_EPS);

    for (int e = threadIdx.x; e < 16 * DD; e += 128) {
        int q = e >> 5, c = e & 31;
        float s = ap2g[c] * inv_bn;
        sh_appw[q][c] = PACK2(ap2w[c * DD + 2 * q] * s, ap2w[c * DD + 2 * q + 1] * s);
    }

    u64t w2p[8]; float b2f;
    {
        float s = g2[cm16] * inv_bn;
        #pragma unroll
        for (int i = 0; i < 8; i++)
            w2p[i] = PACK2(w2[cm16 * HH + 2 * i] * s, w2[cm16 * HH + 2 * i + 1] * s);
        b2f = b2[cm16] * s + be2[cm16];
    }
    uint32_t aw[32];
    #pragma unroll
    for (int mT = 0; mT < 2; mT++)
        #pragma unroll
        for (int kT = 0; kT < 4; kT++) {
            int r0 = 16 * mT + g, r1 = r0 + 8, d0 = 8 * kT + tq, d1 = d0 + 4;
            int o = (mT * 4 + kT) * 4;
            aw[o + 0] = __float_as_uint(fc2w[r0 * DD + d0]);
            aw[o + 1] = __float_as_uint(fc2w[r1 * DD + d0]);
            aw[o + 2] = __float_as_uint(fc2w[r0 * DD + d1]);
            aw[o + 3] = __float_as_uint(fc2w[r1 * DD + d1]);
        }
    float apb = ap2b[lane] * (ap2g[lane] * inv_bn) + ap2be[lane];

    const int b  = blockIdx.x / (NN / 32);
    const int n0 = (blockIdx.x % (NN / 32)) * 32;
    const int pbase = b * NN + n0 + warp * 8;

    const unsigned feat_a = (unsigned)__cvta_generic_to_shared(&sh_feat[warp][0][0][0]);
    const unsigned fx1_a  = (unsigned)__cvta_generic_to_shared(&sh_fx1[warp][0][0][0]);
    const unsigned conv_a = (unsigned)__cvta_generic_to_shared(&sh_conv[warp][0][0]);
    const unsigned agg_a  = (unsigned)__cvta_generic_to_shared(&sh_agg[warp][0]);
    const unsigned appw_a = (unsigned)__cvta_generic_to_shared(&sh_appw[0][0]);

    {
        int4 iv = *(const int4*)(nidx + (size_t)pbase * KK + lane * 4);
        *(int4*)&sh_idx[warp][lane >> 2][(lane & 3) * 4] = iv;
    }
    __syncthreads();

    const int j2 = lane >> 1, h2 = lane & 1;

    #pragma unroll
    for (int s = 0; s < 3; s++) {
        int idx = sh_idx[warp][s][j2];
        const float* src = g_agg1 + (size_t)(b * NN + idx) * HH + h2 * 8;
        unsigned d = feat_a + s * (KK * RSB) + j2 * RSB + h2 * 32;
        cp16(d, src); cp16(d + 16, src + 4);
        {
            const float* fs = g_fx1 + (size_t)(pbase + s) * (KK * HH) + lane * 8;
            unsigned fd = fx1_a + s * 1024 + lane * 32;
            cp16(fd, fs); cp16(fd + 16, fs + 4);
        }
        cp_commit();
    }

    #pragma unroll
    for (int t = 0; t < 8; t++) {
        const int ln = warp * 8 + t;
        const int buf = t % 3;
        if (t < 6) cp_wait<2>(); else if (t == 6) cp_wait<1>(); else cp_wait<0>();
        __syncwarp();

        // conv2 (16->16)
        {
            int jb = (lane >> 4) * 8;
            const unsigned fb = fx1_a + buf * 1024;
            #pragma unroll
            for (int jj = 0; jj < 8; jj++) {
                int j = jb + jj;
                unsigned a = fb + j * 64;
                u64t p0, p1, p2, p3;
                u64t acc0 = PACK2(b2f, 0.f), acc1 = PACK2(0.f, 0.f);
                LDS2x64(p0, p1, a);      FMA2(acc0, p0, w2p[0]); FMA2(acc1, p1, w2p[1]);
                LDS2x64(p2, p3, a + 16); FMA2(acc0, p2, w2p[2]); FMA2(acc1, p3, w2p[3]);
                LDS2x64(p0, p1, a + 32); FMA2(acc0, p0, w2p[4]); FMA2(acc1, p1, w2p[5]);
                LDS2x64(p2, p3, a + 48); FMA2(acc0, p2, w2p[6]); FMA2(acc1, p3, w2p[7]);
                ADD2(acc0, acc1);
                sh_conv[warp][j][cm16] = lrelu(HSUM2(acc0));
            }
        }
        __syncwarp();

        // fc2 via tf32 mma
        const unsigned fbuf_a = feat_a + buf * (KK * RSB);
        float s[16];
        #pragma unroll
        for (int nT = 0; nT < 2; nT++) {
            float c0[4] = {0.f, 0.f, 0.f, 0.f}, c1[4] = {0.f, 0.f, 0.f, 0.f};
            int j = g + 8 * nT;
            unsigned xf = fbuf_a + j * RSB;
            unsigned xc = conv_a + j * RSB;
            #pragma unroll
            for (int kT = 0; kT < 4; kT++) {
                unsigned base = (kT < 2) ? (xf + (8 * kT + tq) * 4)
                                         : (xc + (8 * (kT - 2) + tq) * 4);
                uint32_t b0v = LDSU(base), b1v = LDSU(base + 16);
                MMA_TF32(c0, &aw[(0 * 4 + kT) * 4], b0v, b1v);
                MMA_TF32(c1, &aw[(1 * 4 + kT) * 4], b0v, b1v);
            }
            #pragma unroll
            for (int q = 0; q < 4; q++) {
                s[(nT * 2 + 0) * 4 + q] = c0[q];
                s[(nT * 2 + 1) * 4 + q] = c1[q];
            }
        }
        #pragma unroll
        for (int i = 0; i < 16; i++) s[i] = __expf(s[i]);
        float p0 = s[0] + s[1] + s[8]  + s[9];
        float p1 = s[2] + s[3] + s[10] + s[11];
        float p2 = s[4] + s[5] + s[12] + s[13];
        float p3 = s[6] + s[7] + s[14] + s[15];
        p0 += __shfl_xor_sync(0xffffffffu, p0, 1); p0 += __shfl_xor_sync(0xffffffffu, p0, 2);
        p1 += __shfl_xor_sync(0xffffffffu, p1, 1); p1 += __shfl_xor_sync(0xffffffffu, p1, 2);
        p2 += __shfl_xor_sync(0xffffffffu, p2, 1); p2 += __shfl_xor_sync(0xffffffffu, p2, 2);
        p3 += __shfl_xor_sync(0xffffffffu, p3, 1); p3 += __shfl_xor_sync(0xffffffffu, p3, 2);
        {
            int j0 = 2 * tq, j1 = j0 + 1, j8 = j0 + 8, j9 = j0 + 9;
            unsigned cF0 = g * 4, cF1 = (g + 8) * 4;
            float a0 = LDSF(fbuf_a + j0 * RSB + cF0) * s[0] + LDSF(fbuf_a + j1 * RSB + cF0) * s[1]
                     + LDSF(fbuf_a + j8 * RSB + cF0) * s[8] + LDSF(fbuf_a + j9 * RSB + cF0) * s[9];
            float a1 = LDSF(fbuf_a + j0 * RSB + cF1) * s[2] + LDSF(fbuf_a + j1 * RSB + cF1) * s[3]
                     + LDSF(fbuf_a + j8 * RSB + cF1) * s[10] + LDSF(fbuf_a + j9 * RSB + cF1) * s[11];
            float a2 = LDSF(conv_a + j0 * RSB + cF0) * s[4] + LDSF(conv_a + j1 * RSB + cF0) * s[5]
                     + LDSF(conv_a + j8 * RSB + cF0) * s[12] + LDSF(conv_a + j9 * RSB + cF0) * s[13];
            float a3 = LDSF(conv_a + j0 * RSB + cF1) * s[6] + LDSF(conv_a + j1 * RSB + cF1) * s[7]
                     + LDSF(conv_a + j8 * RSB + cF1) * s[14] + LDSF(conv_a + j9 * RSB + cF1) * s[15];
            a0 += __shfl_xor_sync(0xffffffffu, a0, 1); a0 += __shfl_xor_sync(0xffffffffu, a0, 2);
            a1 += __shfl_xor_sync(0xffffffffu, a1, 1); a1 += __shfl_xor_sync(0xffffffffu, a1, 2);
            a2 += __shfl_xor_sync(0xffffffffu, a2, 1); a2 += __shfl_xor_sync(0xffffffffu, a2, 2);
            a3 += __shfl_xor_sync(0xffffffffu, a3, 1); a3 += __shfl_xor_sync(0xffffffffu, a3, 2);
            if (tq == 0) {
                sh_agg[warp][g]      = __fdividef(a0, p0);
                sh_agg[warp][g + 8]  = __fdividef(a1, p1);
                sh_agg[warp][g + 16] = __fdividef(a2, p2);
                sh_agg[warp][g + 24] = __fdividef(a3, p3);
            }
        }
        __syncwarp();

        // prefetch for t+3
        if (t + 3 < 8) {
            int sN = t + 3;
            int idx = sh_idx[warp][sN][j2];
            const float* src = g_agg1 + (size_t)(b * NN + idx) * HH + h2 * 8;
            unsigned d = feat_a + (sN % 3) * (KK * RSB) + j2 * RSB + h2 * 32;
            cp16(d, src); cp16(d + 16, src + 4);
            {
                const float* fs = g_fx1 + (size_t)(pbase + sN) * (KK * HH) + lane * 8;
                unsigned fd = fx1_a + (sN % 3) * 1024 + lane * 32;
                cp16(fd, fs); cp16(fd + 16, fs + 4);
            }
            cp_commit();
        }

        // mlp2 (32->32)
        {
            u64t acc0 = PACK2(apb, 0.f), acc1 = PACK2(0.f, 0.f);
            #pragma unroll
            for (int q = 0; q < 16; q += 2) {
                FMA2(acc0, LDS64(agg_a + q * 8),
                           LDS64(appw_a + q * 256 + lane * 8));
                FMA2(acc1, LDS64(agg_a + q * 8 + 8),
                           LDS64(appw_a + (q + 1) * 256 + lane * 8));
            }
            ADD2(acc0, acc1);
            sh_out[lane][ln] = lrelu(HSUM2(acc0));
        }
        __syncwarp();
    }

    __syncthreads();
    for (int e = threadIdx.x; e < DD * 32; e += 128) {
        int c = e >> 5, ln = e & 31;
        out[((size_t)b * DD + c) * NN + n0 + ln] = sh_out[c][ln];
    }
}

// ---------------------------------------------------------------------------
extern "C" void kernel_launch(void* const* d_in, const int* in_sizes, int n_in,
                              void* d_out, int out_size) {
    const float* xyz     = (const float*)d_in[0];
    const float* feature = (const float*)d_in[1];
    const int*   nidx    = (const int*)  d_in[2];
    const float* w1   = (const float*)d_in[3];
    const float* b1   = (const float*)d_in[4];
    const float* g1   = (const float*)d_in[5];
    const float* be1  = (const float*)d_in[6];
    const float* fc1w = (const float*)d_in[7];
    const float* fc1b = (const float*)d_in[8];
    const float* ap1w = (const float*)d_in[9];
    const float* ap1b = (const float*)d_in[10];
    const float* ap1g = (const float*)d_in[11];
    const float* ap1be= (const float*)d_in[12];
    const float* w2   = (const float*)d_in[13];
    const float* b2   = (const float*)d_in[14];
    const float* g2   = (const float*)d_in[15];
    const float* be2  = (const float*)d_in[16];
    const float* fc2w = (const float*)d_in[17];
    const float* fc2b = (const float*)d_in[18];
    const float* ap2w = (const float*)d_in[19];
    const float* ap2b = (const float*)d_in[20];
    const float* ap2g = (const float*)d_in[21];
    const float* ap2be= (const float*)d_in[22];
    float* out = (float*)d_out;

    transpose_feat_kernel<<<dim3(NN / 64, BB), 256>>>(feature);
    stage1_kernel<<<BB * NN / 32, 128>>>(xyz, nidx, w1, b1, g1, be1,
                                         fc1w, fc1b, ap1w, ap1b, ap1g, ap1be);
    stage2_kernel<<<BB * NN / 32, 128>>>(nidx, w2, b2, g2, be2, fc2w, fc2b,
                                         ap2w, ap2b, ap2g, ap2be, out);
}

// round 12
// speedup vs baseline: 4.4384x; 1.2641x over previous
#include <cuda_runtime.h>
#include <math.h>
#include <stdint.h>

#define BB 4
#define NN 40960
#define KK 16
#define HH 16
#define DD 32
#define BN_EPS 1e-5f
#define RS 20            // padded row stride (floats) for mma-fed tiles
#define RSB 80           // row stride bytes

__device__ float g_feat_t[BB * NN * HH];
__device__ float g_agg1[BB * NN * HH];
__device__ float g_fx1[(size_t)BB * NN * KK * HH];  // f_xyz1 [b,n,k,16]

__device__ __forceinline__ float lrelu(float y) { return fmaxf(y, 0.2f * y); }

__device__ __forceinline__ uint32_t LDSU(unsigned addr) {
    uint32_t v; asm volatile("ld.shared.b32 %0, [%1];" : "=r"(v) : "r"(addr)); return v;
}
__device__ __forceinline__ float LDSF(unsigned addr) {
    float v; asm volatile("ld.shared.f32 %0, [%1];" : "=f"(v) : "r"(addr)); return v;
}
__device__ __forceinline__ uint32_t CVT_TF32(float x) {
    uint32_t r; asm("cvt.rna.tf32.f32 %0, %1;" : "=r"(r) : "f"(x)); return r;
}

// tf32 mma m16n8k8: D += A*B
#define MMA_TF32(d, a, b0, b1) \
    asm volatile("mma.sync.aligned.m16n8k8.row.col.f32.tf32.tf32.f32 " \
        "{%0,%1,%2,%3}, {%4,%5,%6,%7}, {%8,%9}, {%0,%1,%2,%3};" \
        : "+f"((d)[0]), "+f"((d)[1]), "+f"((d)[2]), "+f"((d)[3]) \
        : "r"((a)[0]), "r"((a)[1]), "r"((a)[2]), "r"((a)[3]), "r"(b0), "r"(b1))

// ---- cp.async helpers ----
__device__ __forceinline__ void cp16(unsigned dst, const float* src) {
    asm volatile("cp.async.cg.shared.global [%0], [%1], 16;" :: "r"(dst), "l"(src));
}
__device__ __forceinline__ void cp4(unsigned dst, const float* src) {
    asm volatile("cp.async.ca.shared.global [%0], [%1], 4;" :: "r"(dst), "l"(src));
}
__device__ __forceinline__ void cp_commit() {
    asm volatile("cp.async.commit_group;");
}
template <int N> __device__ __forceinline__ void cp_wait() {
    asm volatile("cp.async.wait_group %0;" :: "n"(N));
}

// ---------------------------------------------------------------------------
__global__ void transpose_feat_kernel(const float* __restrict__ feature) {
    __shared__ float tile[HH][64 + 1];
    int b = blockIdx.y;
    int n0 = blockIdx.x * 64;
    int t = threadIdx.x;
    int i = t & 63, cq = t >> 6;
    #pragma unroll
    for (int cc = cq; cc < HH; cc += 4)
        tile[cc][i] = feature[(b * HH + cc) * NN + n0 + i];
    __syncthreads();
    int c = t & 15, iq = t >> 4;
    #pragma unroll
    for (int ii = iq; ii < 64; ii += 16)
        g_feat_t[(b * NN + n0 + ii) * HH + c] = tile[c][ii];
}

// ---------------------------------------------------------------------------
// Stage 1: geometry + mma-conv1 + gather(feat) + mma-fc + softmax-pool,
// then batched mma-mlp for all 8 points.
// ---------------------------------------------------------------------------
__global__ void __launch_bounds__(128, 5) stage1_kernel(
    const float* __restrict__ xyz, const int* __restrict__ nidx,
    const float* __restrict__ w1, const float* __restrict__ b1,
    const float* __restrict__ g1, const float* __restrict__ be1,
    const float* __restrict__ fc1w, const float* __restrict__ fc1b,
    const float* __restrict__ ap1w, const float* __restrict__ ap1b,
    const float* __restrict__ ap1g, const float* __restrict__ ap1be)
{
    __shared__ __align__(16) float sh_feat[4][4][KK][RS];
    __shared__ __align__(16) float sh_nxyz[4][4][KK][4];
    __shared__ __align__(16) float sh_fxyz[4][KK][RS];   // padded geometry rows
    __shared__ __align__(16) float sh_conv[4][KK][RS];
    __shared__ __align__(16) float sh_agg[4][8][36];     // [pt][c], padded
    __shared__ __align__(16) int   sh_idx[4][8][KK];
    __shared__ float sh_cxyz[4][8][3];

    const int warp = threadIdx.x >> 5;
    const int lane = threadIdx.x & 31;
    const int g = lane >> 2, tq = lane & 3;
    const float inv_bn = rsqrtf(1.0f + BN_EPS);

    // conv1 weight fragments (BN folded, K padded 10->16, rna-converted)
    uint32_t aw1[8]; float bb1c0, bb1c1;
    {
        float s0 = g1[g] * inv_bn, s1 = g1[g + 8] * inv_bn;
        #pragma unroll
        for (int kT = 0; kT < 2; kT++) {
            int d0 = 8 * kT + tq, d1 = d0 + 4;
            float w00 = (d0 < 10) ? w1[g * 10 + d0] * s0 : 0.f;
            float w10 = (d0 < 10) ? w1[(g + 8) * 10 + d0] * s1 : 0.f;
            float w01 = (d1 < 10) ? w1[g * 10 + d1] * s0 : 0.f;
            float w11 = (d1 < 10) ? w1[(g + 8) * 10 + d1] * s1 : 0.f;
            aw1[kT * 4 + 0] = CVT_TF32(w00); aw1[kT * 4 + 1] = CVT_TF32(w10);
            aw1[kT * 4 + 2] = CVT_TF32(w01); aw1[kT * 4 + 3] = CVT_TF32(w11);
        }
        bb1c0 = b1[g] * s0 + be1[g];
        bb1c1 = b1[g + 8] * s1 + be1[g + 8];
    }
    // fc weight fragments
    uint32_t aw[32];
    #pragma unroll
    for (int mT = 0; mT < 2; mT++)
        #pragma unroll
        for (int kT = 0; kT < 4; kT++) {
            int r0 = 16 * mT + g, r1 = r0 + 8, d0 = 8 * kT + tq, d1 = d0 + 4;
            int o = (mT * 4 + kT) * 4;
            aw[o + 0] = CVT_TF32(fc1w[r0 * DD + d0]);
            aw[o + 1] = CVT_TF32(fc1w[r1 * DD + d0]);
            aw[o + 2] = CVT_TF32(fc1w[r0 * DD + d1]);
            aw[o + 3] = CVT_TF32(fc1w[r1 * DD + d1]);
        }

    const int b  = blockIdx.x / (NN / 32);
    const int n0 = (blockIdx.x % (NN / 32)) * 32;
    const int pbase = b * NN + n0 + warp * 8;

    const unsigned feat_a = (unsigned)__cvta_generic_to_shared(&sh_feat[warp][0][0][0]);
    const unsigned nxyz_a = (unsigned)__cvta_generic_to_shared(&sh_nxyz[warp][0][0][0]);
    const unsigned fxyz_a = (unsigned)__cvta_generic_to_shared(&sh_fxyz[warp][0][0]);
    const unsigned conv_a = (unsigned)__cvta_generic_to_shared(&sh_conv[warp][0][0]);
    const unsigned agg_a  = (unsigned)__cvta_generic_to_shared(&sh_agg[warp][0][0]);

    {
        int4 iv = *(const int4*)(nidx + (size_t)pbase * KK + lane * 4);
        *(int4*)&sh_idx[warp][lane >> 2][(lane & 3) * 4] = iv;
    }
    if (lane < 24) sh_cxyz[warp][lane / 3][lane % 3] = xyz[pbase * 3 + lane];
    // zero-pad geometry rows d=10..15 (once)
    if (lane < KK) {
        ((float2*)&sh_fxyz[warp][lane][10])[0] = make_float2(0.f, 0.f);
        ((float4*)&sh_fxyz[warp][lane][12])[0] = make_float4(0.f, 0.f, 0.f, 0.f);
    }
    __syncthreads();

    const int j2 = lane >> 1, h2 = lane & 1;

    #pragma unroll
    for (int s = 0; s < 4; s++) {
        int idx = sh_idx[warp][s][j2];
        const float* src = g_feat_t + (size_t)(b * NN + idx) * HH + h2 * 8;
        unsigned d = feat_a + s * (KK * RSB) + j2 * RSB + h2 * 32;
        cp16(d, src); cp16(d + 16, src + 4);
        if (lane < KK) {
            int ix = sh_idx[warp][s][lane];
            const float* xs = xyz + (size_t)(b * NN + ix) * 3;
            unsigned dn = nxyz_a + s * 256 + lane * 16;
            cp4(dn, xs); cp4(dn + 4, xs + 1); cp4(dn + 8, xs + 2);
        }
        cp_commit();
    }

    #pragma unroll
    for (int t = 0; t < 8; t++) {
        const int pn = pbase + t;
        const int buf = t & 3;
        if (t < 5) cp_wait<3>(); else if (t == 5) cp_wait<2>();
        else if (t == 6) cp_wait<1>(); else cp_wait<0>();
        __syncwarp();

        // geometry (lane<16)
        if (lane < KK) {
            const float* np_ = &sh_nxyz[warp][buf][lane][0];
            float nx = np_[0], ny = np_[1], nz = np_[2];
            float cx = sh_cxyz[warp][t][0], cy = sh_cxyz[warp][t][1], cz = sh_cxyz[warp][t][2];
            float rx = cx - nx, ry = cy - ny, rz = cz - nz;
            float dis = sqrtf(rx * rx + ry * ry + rz * rz);
            float4* row = (float4*)&sh_fxyz[warp][lane][0];
            row[0] = make_float4(dis, rx, ry, rz);
            row[1] = make_float4(cx, cy, cz, nx);
            ((float2*)&sh_fxyz[warp][lane][8])[0] = make_float2(ny, nz);
        }
        __syncwarp();

        // conv1 via tf32 mma -> sh_conv + g_fx1
        {
            size_t gb = (size_t)pn * (KK * HH);
            #pragma unroll
            for (int nT = 0; nT < 2; nT++) {
                float c[4] = {bb1c0, bb1c0, bb1c1, bb1c1};
                unsigned xb = fxyz_a + (8 * nT + g) * RSB;
                #pragma unroll
                for (int kT = 0; kT < 2; kT++) {
                    unsigned base = xb + (8 * kT + tq) * 4;
                    uint32_t b0v = CVT_TF32(LDSF(base));
                    uint32_t b1v = CVT_TF32(LDSF(base + 16));
                    MMA_TF32(c, &aw1[kT * 4], b0v, b1v);
                }
                int j0 = 8 * nT + 2 * tq, j1 = j0 + 1;
                float v0 = lrelu(c[0]), v1 = lrelu(c[1]);
                float v2 = lrelu(c[2]), v3 = lrelu(c[3]);
                sh_conv[warp][j0][g] = v0;     sh_conv[warp][j1][g] = v1;
                sh_conv[warp][j0][g + 8] = v2; sh_conv[warp][j1][g + 8] = v3;
                g_fx1[gb + j0 * HH + g] = v0;     g_fx1[gb + j1 * HH + g] = v1;
                g_fx1[gb + j0 * HH + g + 8] = v2; g_fx1[gb + j1 * HH + g + 8] = v3;
            }
        }
        __syncwarp();

        // fc via tf32 mma: scores^T(32c x 16j)
        const unsigned fbuf_a = feat_a + buf * (KK * RSB);
        float s[16];
        #pragma unroll
        for (int nT = 0; nT < 2; nT++) {
            float c0[4] = {0.f, 0.f, 0.f, 0.f}, c1[4] = {0.f, 0.f, 0.f, 0.f};
            int j = g + 8 * nT;
            unsigned xf = fbuf_a + j * RSB;
            unsigned xc = conv_a + j * RSB;
            #pragma unroll
            for (int kT = 0; kT < 4; kT++) {
                unsigned base = (kT < 2) ? (xf + (8 * kT + tq) * 4)
                                         : (xc + (8 * (kT - 2) + tq) * 4);
                uint32_t b0v = LDSU(base), b1v = LDSU(base + 16);
                MMA_TF32(c0, &aw[(0 * 4 + kT) * 4], b0v, b1v);
                MMA_TF32(c1, &aw[(1 * 4 + kT) * 4], b0v, b1v);
            }
            #pragma unroll
            for (int q = 0; q < 4; q++) {
                s[(nT * 2 + 0) * 4 + q] = c0[q];
                s[(nT * 2 + 1) * 4 + q] = c1[q];
            }
        }
        #pragma unroll
        for (int i = 0; i < 16; i++) s[i] = __expf(s[i]);
        float p0 = s[0] + s[1] + s[8]  + s[9];
        float p1 = s[2] + s[3] + s[10] + s[11];
        float p2 = s[4] + s[5] + s[12] + s[13];
        float p3 = s[6] + s[7] + s[14] + s[15];
        p0 += __shfl_xor_sync(0xffffffffu, p0, 1); p0 += __shfl_xor_sync(0xffffffffu, p0, 2);
        p1 += __shfl_xor_sync(0xffffffffu, p1, 1); p1 += __shfl_xor_sync(0xffffffffu, p1, 2);
        p2 += __shfl_xor_sync(0xffffffffu, p2, 1); p2 += __shfl_xor_sync(0xffffffffu, p2, 2);
        p3 += __shfl_xor_sync(0xffffffffu, p3, 1); p3 += __shfl_xor_sync(0xffffffffu, p3, 2);
        {
            int j0 = 2 * tq, j1 = j0 + 1, j8 = j0 + 8, j9 = j0 + 9;
            unsigned cF0 = g * 4, cF1 = (g + 8) * 4;
            float a0 = LDSF(fbuf_a + j0 * RSB + cF0) * s[0] + LDSF(fbuf_a + j1 * RSB + cF0) * s[1]
                     + LDSF(fbuf_a + j8 * RSB + cF0) * s[8] + LDSF(fbuf_a + j9 * RSB + cF0) * s[9];
            float a1 = LDSF(fbuf_a + j0 * RSB + cF1) * s[2] + LDSF(fbuf_a + j1 * RSB + cF1) * s[3]
                     + LDSF(fbuf_a + j8 * RSB + cF1) * s[10] + LDSF(fbuf_a + j9 * RSB + cF1) * s[11];
            float a2 = LDSF(conv_a + j0 * RSB + cF0) * s[4] + LDSF(conv_a + j1 * RSB + cF0) * s[5]
                     + LDSF(conv_a + j8 * RSB + cF0) * s[12] + LDSF(conv_a + j9 * RSB + cF0) * s[13];
            float a3 = LDSF(conv_a + j0 * RSB + cF1) * s[6] + LDSF(conv_a + j1 * RSB + cF1) * s[7]
                     + LDSF(conv_a + j8 * RSB + cF1) * s[14] + LDSF(conv_a + j9 * RSB + cF1) * s[15];
            a0 += __shfl_xor_sync(0xffffffffu, a0, 1); a0 += __shfl_xor_sync(0xffffffffu, a0, 2);
            a1 += __shfl_xor_sync(0xffffffffu, a1, 1); a1 += __shfl_xor_sync(0xffffffffu, a1, 2);
            a2 += __shfl_xor_sync(0xffffffffu, a2, 1); a2 += __shfl_xor_sync(0xffffffffu, a2, 2);
            a3 += __shfl_xor_sync(0xffffffffu, a3, 1); a3 += __shfl_xor_sync(0xffffffffu, a3, 2);
            if (tq == 0) {
                sh_agg[warp][t][g]      = __fdividef(a0, p0);
                sh_agg[warp][t][g + 8]  = __fdividef(a1, p1);
                sh_agg[warp][t][g + 16] = __fdividef(a2, p2);
                sh_agg[warp][t][g + 24] = __fdividef(a3, p3);
            }
        }

        // prefetch for t+4
        if (t + 4 < 8) {
            int sN = t + 4;
            int idx = sh_idx[warp][sN][j2];
            const float* src = g_feat_t + (size_t)(b * NN + idx) * HH + h2 * 8;
            unsigned d = feat_a + (sN & 3) * (KK * RSB) + j2 * RSB + h2 * 32;
            cp16(d, src); cp16(d + 16, src + 4);
            if (lane < KK) {
                int ix = sh_idx[warp][sN][lane];
                const float* xs = xyz + (size_t)(b * NN + ix) * 3;
                unsigned dn = nxyz_a + (sN & 3) * 256 + lane * 16;
                cp4(dn, xs); cp4(dn + 4, xs + 1); cp4(dn + 8, xs + 2);
            }
            cp_commit();
        }
        __syncwarp();
    }

    // batched mlp (32->16) for 8 points via tf32 mma
    {
        float s0 = ap1g[g] * inv_bn, s1 = ap1g[g + 8] * inv_bn;
        float c[4];
        c[0] = c[1] = ap1b[g] * s0 + ap1be[g];
        c[2] = c[3] = ap1b[g + 8] * s1 + ap1be[g + 8];
        #pragma unroll
        for (int kT = 0; kT < 4; kT++) {
            int d0 = 8 * kT + tq, d1 = d0 + 4;
            uint32_t af[4];
            af[0] = CVT_TF32(ap1w[g * DD + d0] * s0);
            af[1] = CVT_TF32(ap1w[(g + 8) * DD + d0] * s1);
            af[2] = CVT_TF32(ap1w[g * DD + d1] * s0);
            af[3] = CVT_TF32(ap1w[(g + 8) * DD + d1] * s1);
            uint32_t b0v = CVT_TF32(LDSF(agg_a + g * 144 + d0 * 4));
            uint32_t b1v = CVT_TF32(LDSF(agg_a + g * 144 + d1 * 4));
            MMA_TF32(c, af, b0v, b1v);
        }
        int p0i = pbase + 2 * tq, p1i = p0i + 1;
        g_agg1[(size_t)p0i * HH + g]     = lrelu(c[0]);
        g_agg1[(size_t)p1i * HH + g]     = lrelu(c[1]);
        g_agg1[(size_t)p0i * HH + g + 8] = lrelu(c[2]);
        g_agg1[(size_t)p1i * HH + g + 8] = lrelu(c[3]);
    }
}

// ---------------------------------------------------------------------------
// Stage 2: load f_xyz1 + gather(f_agg1) + mma-conv2 + mma-fc2 + pool,
// then batched mma-mlp2 + coalesced output.
// ---------------------------------------------------------------------------
__global__ void __launch_bounds__(128, 4) stage2_kernel(
    const int* __restrict__ nidx,
    const float* __restrict__ w2, const float* __restrict__ b2,
    const float* __restrict__ g2, const float* __restrict__ be2,
    const float* __restrict__ fc2w, const float* __restrict__ fc2b,
    const float* __restrict__ ap2w, const float* __restrict__ ap2b,
    const float* __restrict__ ap2g, const float* __restrict__ ap2be,
    float* __restrict__ out)
{
    __shared__ __align__(16) float sh_feat[4][3][KK][RS];
    __shared__ __align__(16) float sh_fx1[4][3][KK][RS];   // padded rows
    __shared__ __align__(16) float sh_conv[4][KK][RS];
    __shared__ __align__(16) float sh_agg[4][8][36];
    __shared__ __align__(16) int   sh_idx[4][8][KK];
    __shared__ float sh_out[DD][33];

    const int warp = threadIdx.x >> 5;
    const int lane = threadIdx.x & 31;
    const int g = lane >> 2, tq = lane & 3;
    const float inv_bn = rsqrtf(1.0f + BN_EPS);

    // conv2 weight fragments (BN folded)
    uint32_t aw2[8]; float bb2c0, bb2c1;
    {
        float s0 = g2[g] * inv_bn, s1 = g2[g + 8] * inv_bn;
        #pragma unroll
        for (int kT = 0; kT < 2; kT++) {
            int d0 = 8 * kT + tq, d1 = d0 + 4;
            aw2[kT * 4 + 0] = CVT_TF32(w2[g * HH + d0] * s0);
            aw2[kT * 4 + 1] = CVT_TF32(w2[(g + 8) * HH + d0] * s1);
            aw2[kT * 4 + 2] = CVT_TF32(w2[g * HH + d1] * s0);
            aw2[kT * 4 + 3] = CVT_TF32(w2[(g + 8) * HH + d1] * s1);
        }
        bb2c0 = b2[g] * s0 + be2[g];
        bb2c1 = b2[g + 8] * s1 + be2[g + 8];
    }
    uint32_t aw[32];
    #pragma unroll
    for (int mT = 0; mT < 2; mT++)
        #pragma unroll
        for (int kT = 0; kT < 4; kT++) {
            int r0 = 16 * mT + g, r1 = r0 + 8, d0 = 8 * kT + tq, d1 = d0 + 4;
            int o = (mT * 4 + kT) * 4;
            aw[o + 0] = CVT_TF32(fc2w[r0 * DD + d0]);
            aw[o + 1] = CVT_TF32(fc2w[r1 * DD + d0]);
            aw[o + 2] = CVT_TF32(fc2w[r0 * DD + d1]);
            aw[o + 3] = CVT_TF32(fc2w[r1 * DD + d1]);
        }

    const int b  = blockIdx.x / (NN / 32);
    const int n0 = (blockIdx.x % (NN / 32)) * 32;
    const int pbase = b * NN + n0 + warp * 8;

    const unsigned feat_a = (unsigned)__cvta_generic_to_shared(&sh_feat[warp][0][0][0]);
    const unsigned fx1_a  = (unsigned)__cvta_generic_to_shared(&sh_fx1[warp][0][0][0]);
    const unsigned conv_a = (unsigned)__cvta_generic_to_shared(&sh_conv[warp][0][0]);
    const unsigned agg_a  = (unsigned)__cvta_generic_to_shared(&sh_agg[warp][0][0]);

    {
        int4 iv = *(const int4*)(nidx + (size_t)pbase * KK + lane * 4);
        *(int4*)&sh_idx[warp][lane >> 2][(lane & 3) * 4] = iv;
    }
    __syncthreads();

    const int j2 = lane >> 1, h2 = lane & 1;

    #pragma unroll
    for (int s = 0; s < 3; s++) {
        int idx = sh_idx[warp][s][j2];
        const float* src = g_agg1 + (size_t)(b * NN + idx) * HH + h2 * 8;
        unsigned d = feat_a + s * (KK * RSB) + j2 * RSB + h2 * 32;
        cp16(d, src); cp16(d + 16, src + 4);
        {
            const float* fs = g_fx1 + (size_t)(pbase + s) * (KK * HH) + j2 * HH + h2 * 8;
            unsigned fd = fx1_a + s * (KK * RSB) + j2 * RSB + h2 * 32;
            cp16(fd, fs); cp16(fd + 16, fs + 4);
        }
        cp_commit();
    }

    #pragma unroll
    for (int t = 0; t < 8; t++) {
        const int buf = t % 3;
        if (t < 6) cp_wait<2>(); else if (t == 6) cp_wait<1>(); else cp_wait<0>();
        __syncwarp();

        // conv2 via tf32 mma -> sh_conv
        {
            const unsigned fb = fx1_a + buf * (KK * RSB);
            #pragma unroll
            for (int nT = 0; nT < 2; nT++) {
                float c[4] = {bb2c0, bb2c0, bb2c1, bb2c1};
                unsigned xb = fb + (8 * nT + g) * RSB;
                #pragma unroll
                for (int kT = 0; kT < 2; kT++) {
                    unsigned base = xb + (8 * kT + tq) * 4;
                    uint32_t b0v = CVT_TF32(LDSF(base));
                    uint32_t b1v = CVT_TF32(LDSF(base + 16));
                    MMA_TF32(c, &aw2[kT * 4], b0v, b1v);
                }
                int j0 = 8 * nT + 2 * tq, j1 = j0 + 1;
                sh_conv[warp][j0][g] = lrelu(c[0]);     sh_conv[warp][j1][g] = lrelu(c[1]);
                sh_conv[warp][j0][g + 8] = lrelu(c[2]); sh_conv[warp][j1][g + 8] = lrelu(c[3]);
            }
        }
        __syncwarp();

        // fc2 via tf32 mma
        const unsigned fbuf_a = feat_a + buf * (KK * RSB);
        float s[16];
        #pragma unroll
        for (int nT = 0; nT < 2; nT++) {
            float c0[4] = {0.f, 0.f, 0.f, 0.f}, c1[4] = {0.f, 0.f, 0.f, 0.f};
            int j = g + 8 * nT;
            unsigned xf = fbuf_a + j * RSB;
            unsigned xc = conv_a + j * RSB;
            #pragma unroll
            for (int kT = 0; kT < 4; kT++) {
                unsigned base = (kT < 2) ? (xf + (8 * kT + tq) * 4)
                                         : (xc + (8 * (kT - 2) + tq) * 4);
                uint32_t b0v = LDSU(base), b1v = LDSU(base + 16);
                MMA_TF32(c0, &aw[(0 * 4 + kT) * 4], b0v, b1v);
                MMA_TF32(c1, &aw[(1 * 4 + kT) * 4], b0v, b1v);
            }
            #pragma unroll
            for (int q = 0; q < 4; q++) {
                s[(nT * 2 + 0) * 4 + q] = c0[q];
                s[(nT * 2 + 1) * 4 + q] = c1[q];
            }
        }
        #pragma unroll
        for (int i = 0; i < 16; i++) s[i] = __expf(s[i]);
        float p0 = s[0] + s[1] + s[8]  + s[9];
        float p1 = s[2] + s[3] + s[10] + s[11];
        float p2 = s[4] + s[5] + s[12] + s[13];
        float p3 = s[6] + s[7] + s[14] + s[15];
        p0 += __shfl_xor_sync(0xffffffffu, p0, 1); p0 += __shfl_xor_sync(0xffffffffu, p0, 2);
        p1 += __shfl_xor_sync(0xffffffffu, p1, 1); p1 += __shfl_xor_sync(0xffffffffu, p1, 2);
        p2 += __shfl_xor_sync(0xffffffffu, p2, 1); p2 += __shfl_xor_sync(0xffffffffu, p2, 2);
        p3 += __shfl_xor_sync(0xffffffffu, p3, 1); p3 += __shfl_xor_sync(0xffffffffu, p3, 2);
        {
            int j0 = 2 * tq, j1 = j0 + 1, j8 = j0 + 8, j9 = j0 + 9;
            unsigned cF0 = g * 4, cF1 = (g + 8) * 4;
            float a0 = LDSF(fbuf_a + j0 * RSB + cF0) * s[0] + LDSF(fbuf_a + j1 * RSB + cF0) * s[1]
                     + LDSF(fbuf_a + j8 * RSB + cF0) * s[8] + LDSF(fbuf_a + j9 * RSB + cF0) * s[9];
            float a1 = LDSF(fbuf_a + j0 * RSB + cF1) * s[2] + LDSF(fbuf_a + j1 * RSB + cF1) * s[3]
                     + LDSF(fbuf_a + j8 * RSB + cF1) * s[10] + LDSF(fbuf_a + j9 * RSB + cF1) * s[11];
            float a2 = LDSF(conv_a + j0 * RSB + cF0) * s[4] + LDSF(conv_a + j1 * RSB + cF0) * s[5]
                     + LDSF(conv_a + j8 * RSB + cF0) * s[12] + LDSF(conv_a + j9 * RSB + cF0) * s[13];
            float a3 = LDSF(conv_a + j0 * RSB + cF1) * s[6] + LDSF(conv_a + j1 * RSB + cF1) * s[7]
                     + LDSF(conv_a + j8 * RSB + cF1) * s[14] + LDSF(conv_a + j9 * RSB + cF1) * s[15];
            a0 += __shfl_xor_sync(0xffffffffu, a0, 1); a0 += __shfl_xor_sync(0xffffffffu, a0, 2);
            a1 += __shfl_xor_sync(0xffffffffu, a1, 1); a1 += __shfl_xor_sync(0xffffffffu, a1, 2);
            a2 += __shfl_xor_sync(0xffffffffu, a2, 1); a2 += __shfl_xor_sync(0xffffffffu, a2, 2);
            a3 += __shfl_xor_sync(0xffffffffu, a3, 1); a3 += __shfl_xor_sync(0xffffffffu, a3, 2);
            if (tq == 0) {
                sh_agg[warp][t][g]      = __fdividef(a0, p0);
                sh_agg[warp][t][g + 8]  = __fdividef(a1, p1);
                sh_agg[warp][t][g + 16] = __fdividef(a2, p2);
                sh_agg[warp][t][g + 24] = __fdividef(a3, p3);
            }
        }

        // prefetch for t+3
        if (t + 3 < 8) {
            int sN = t + 3;
            int idx = sh_idx[warp][sN][j2];
            const float* src = g_agg1 + (size_t)(b * NN + idx) * HH + h2 * 8;
            unsigned d = feat_a + (sN % 3) * (KK * RSB) + j2 * RSB + h2 * 32;
            cp16(d, src); cp16(d + 16, src + 4);
            {
                const float* fs = g_fx1 + (size_t)(pbase + sN) * (KK * HH) + j2 * HH + h2 * 8;
                unsigned fd = fx1_a + (sN % 3) * (KK * RSB) + j2 * RSB + h2 * 32;
                cp16(fd, fs); cp16(fd + 16, fs + 4);
            }
            cp_commit();
        }
        __syncwarp();
    }

    // batched mlp2 (32->32) for 8 points via tf32 mma
    #pragma unroll
    for (int mT = 0; mT < 2; mT++) {
        int r0 = 16 * mT + g, r1 = r0 + 8;
        float s0 = ap2g[r0] * inv_bn, s1 = ap2g[r1] * inv_bn;
        float c[4];
        c[0] = c[1] = ap2b[r0] * s0 + ap2be[r0];
        c[2] = c[3] = ap2b[r1] * s1 + ap2be[r1];
        #pragma unroll
        for (int kT = 0; kT < 4; kT++) {
            int d0 = 8 * kT + tq, d1 = d0 + 4;
            uint32_t af[4];
            af[0] = CVT_TF32(ap2w[r0 * DD + d0] * s0);
            af[1] = CVT_TF32(ap2w[r1 * DD + d0] * s1);
            af[2] = CVT_TF32(ap2w[r0 * DD + d1] * s0);
            af[3] = CVT_TF32(ap2w[r1 * DD + d1] * s1);
            uint32_t b0v = CVT_TF32(LDSF(agg_a + g * 144 + d0 * 4));
            uint32_t b1v = CVT_TF32(LDSF(agg_a + g * 144 + d1 * 4));
            MMA_TF32(c, af, b0v, b1v);
        }
        int l0 = warp * 8 + 2 * tq, l1 = l0 + 1;
        sh_out[r0][l0] = lrelu(c[0]); sh_out[r0][l1] = lrelu(c[1]);
        sh_out[r1][l0] = lrelu(c[2]); sh_out[r1][l1] = lrelu(c[3]);
    }

    __syncthreads();
    for (int e = threadIdx.x; e < DD * 32; e += 128) {
        int c = e >> 5, ln = e & 31;
        out[((size_t)b * DD + c) * NN + n0 + ln] = sh_out[c][ln];
    }
}

// ---------------------------------------------------------------------------
extern "C" void kernel_launch(void* const* d_in, const int* in_sizes, int n_in,
                              void* d_out, int out_size) {
    const float* xyz     = (const float*)d_in[0];
    const float* feature = (const float*)d_in[1];
    const int*   nidx    = (const int*)  d_in[2];
    const float* w1   = (const float*)d_in[3];
    const float* b1   = (const float*)d_in[4];
    const float* g1   = (const float*)d_in[5];
    const float* be1  = (const float*)d_in[6];
    const float* fc1w = (const float*)d_in[7];
    const float* fc1b = (const float*)d_in[8];
    const float* ap1w = (const float*)d_in[9];
    const float* ap1b = (const float*)d_in[10];
    const float* ap1g = (const float*)d_in[11];
    const float* ap1be= (const float*)d_in[12];
    const float* w2   = (const float*)d_in[13];
    const float* b2   = (const float*)d_in[14];
    const float* g2   = (const float*)d_in[15];
    const float* be2  = (const float*)d_in[16];
    const float* fc2w = (const float*)d_in[17];
    const float* fc2b = (const float*)d_in[18];
    const float* ap2w = (const float*)d_in[19];
    const float* ap2b = (const float*)d_in[20];
    const float* ap2g = (const float*)d_in[21];
    const float* ap2be= (const float*)d_in[22];
    float* out = (float*)d_out;

    transpose_feat_kernel<<<dim3(NN / 64, BB), 256>>>(feature);
    stage1_kernel<<<BB * NN / 32, 128>>>(xyz, nidx, w1, b1, g1, be1,
                                         fc1w, fc1b, ap1w, ap1b, ap1g, ap1be);
    stage2_kernel<<<BB * NN / 32, 128>>>(nidx, w2, b2, g2, be2, fc2w, fc2b,
                                         ap2w, ap2b, ap2g, ap2be, out);
}

// round 13
// speedup vs baseline: 4.5827x; 1.0325x over previous
#include <cuda_runtime.h>
#include <math.h>
#include <stdint.h>

#define BB 4
#define NN 40960
#define KK 16
#define HH 16
#define DD 32
#define BN_EPS 1e-5f
#define RS 20            // padded row stride (floats) for mma-fed tiles
#define RSB 80           // row stride bytes
#define LOG2E 1.4426950408889634f

__device__ float g_feat_t[BB * NN * HH];
__device__ float g_agg1[BB * NN * HH];
__device__ float g_fx1[(size_t)BB * NN * KK * HH];  // f_xyz1 [b,n,k,16]

__device__ __forceinline__ float lrelu(float y) { return fmaxf(y, 0.2f * y); }

__device__ __forceinline__ uint32_t LDSU(unsigned addr) {
    uint32_t v; asm volatile("ld.shared.b32 %0, [%1];" : "=r"(v) : "r"(addr)); return v;
}
__device__ __forceinline__ float LDSF(unsigned addr) {
    float v; asm volatile("ld.shared.f32 %0, [%1];" : "=f"(v) : "r"(addr)); return v;
}
__device__ __forceinline__ uint32_t CVT_TF32(float x) {
    uint32_t r; asm("cvt.rna.tf32.f32 %0, %1;" : "=r"(r) : "f"(x)); return r;
}
__device__ __forceinline__ float EX2(float x) {
    float r; asm("ex2.approx.f32 %0, %1;" : "=f"(r) : "f"(x)); return r;
}

// tf32 mma m16n8k8: D += A*B
#define MMA_TF32(d, a, b0, b1) \
    asm volatile("mma.sync.aligned.m16n8k8.row.col.f32.tf32.tf32.f32 " \
        "{%0,%1,%2,%3}, {%4,%5,%6,%7}, {%8,%9}, {%0,%1,%2,%3};" \
        : "+f"((d)[0]), "+f"((d)[1]), "+f"((d)[2]), "+f"((d)[3]) \
        : "r"((a)[0]), "r"((a)[1]), "r"((a)[2]), "r"((a)[3]), "r"(b0), "r"(b1))

// ---- cp.async helpers ----
__device__ __forceinline__ void cp16(unsigned dst, const float* src) {
    asm volatile("cp.async.cg.shared.global [%0], [%1], 16;" :: "r"(dst), "l"(src));
}
__device__ __forceinline__ void cp4(unsigned dst, const float* src) {
    asm volatile("cp.async.ca.shared.global [%0], [%1], 4;" :: "r"(dst), "l"(src));
}
__device__ __forceinline__ void cp_commit() {
    asm volatile("cp.async.commit_group;");
}
template <int N> __device__ __forceinline__ void cp_wait() {
    asm volatile("cp.async.wait_group %0;" :: "n"(N));
}

// ---------------------------------------------------------------------------
__global__ void transpose_feat_kernel(const float* __restrict__ feature) {
    __shared__ float tile[HH][64 + 1];
    int b = blockIdx.y;
    int n0 = blockIdx.x * 64;
    int t = threadIdx.x;
    int i = t & 63, cq = t >> 6;
    #pragma unroll
    for (int cc = cq; cc < HH; cc += 4)
        tile[cc][i] = feature[(b * HH + cc) * NN + n0 + i];
    __syncthreads();
    int c = t & 15, iq = t >> 4;
    #pragma unroll
    for (int ii = iq; ii < 64; ii += 16)
        g_feat_t[(b * NN + n0 + ii) * HH + c] = tile[c][ii];
}

// ---------------------------------------------------------------------------
// Stage 1: geometry + mma-conv1 + gather(feat) + mma-fc + softmax-pool,
// then batched mma-mlp for all 8 points.
// ---------------------------------------------------------------------------
__global__ void __launch_bounds__(128, 5) stage1_kernel(
    const float* __restrict__ xyz, const int* __restrict__ nidx,
    const float* __restrict__ w1, const float* __restrict__ b1,
    const float* __restrict__ g1, const float* __restrict__ be1,
    const float* __restrict__ fc1w, const float* __restrict__ fc1b,
    const float* __restrict__ ap1w, const float* __restrict__ ap1b,
    const float* __restrict__ ap1g, const float* __restrict__ ap1be)
{
    __shared__ __align__(16) float sh_feat[4][4][KK][RS];
    __shared__ __align__(16) float sh_nxyz[4][4][KK][4];
    __shared__ __align__(16) float sh_fxyz[4][KK][RS];   // padded geometry rows
    __shared__ __align__(16) float sh_conv[4][KK][RS];
    __shared__ __align__(16) float sh_agg[4][8][36];     // [pt][c], padded
    __shared__ __align__(16) int   sh_idx[4][8][KK];
    __shared__ float sh_cxyz[4][8][3];

    const int warp = threadIdx.x >> 5;
    const int lane = threadIdx.x & 31;
    const int g = lane >> 2, tq = lane & 3;
    const float inv_bn = rsqrtf(1.0f + BN_EPS);

    // conv1 weight fragments (BN folded, K padded 10->16, rna-converted)
    uint32_t aw1[8]; float bb1c0, bb1c1;
    {
        float s0 = g1[g] * inv_bn, s1 = g1[g + 8] * inv_bn;
        #pragma unroll
        for (int kT = 0; kT < 2; kT++) {
            int d0 = 8 * kT + tq, d1 = d0 + 4;
            float w00 = (d0 < 10) ? w1[g * 10 + d0] * s0 : 0.f;
            float w10 = (d0 < 10) ? w1[(g + 8) * 10 + d0] * s1 : 0.f;
            float w01 = (d1 < 10) ? w1[g * 10 + d1] * s0 : 0.f;
            float w11 = (d1 < 10) ? w1[(g + 8) * 10 + d1] * s1 : 0.f;
            aw1[kT * 4 + 0] = CVT_TF32(w00); aw1[kT * 4 + 1] = CVT_TF32(w10);
            aw1[kT * 4 + 2] = CVT_TF32(w01); aw1[kT * 4 + 3] = CVT_TF32(w11);
        }
        bb1c0 = b1[g] * s0 + be1[g];
        bb1c1 = b1[g + 8] * s1 + be1[g + 8];
    }
    // fc weight fragments (pre-scaled by log2e: softmax via ex2)
    uint32_t aw[32];
    #pragma unroll
    for (int mT = 0; mT < 2; mT++)
        #pragma unroll
        for (int kT = 0; kT < 4; kT++) {
            int r0 = 16 * mT + g, r1 = r0 + 8, d0 = 8 * kT + tq, d1 = d0 + 4;
            int o = (mT * 4 + kT) * 4;
            aw[o + 0] = CVT_TF32(fc1w[r0 * DD + d0] * LOG2E);
            aw[o + 1] = CVT_TF32(fc1w[r1 * DD + d0] * LOG2E);
            aw[o + 2] = CVT_TF32(fc1w[r0 * DD + d1] * LOG2E);
            aw[o + 3] = CVT_TF32(fc1w[r1 * DD + d1] * LOG2E);
        }

    const int b  = blockIdx.x / (NN / 32);
    const int n0 = (blockIdx.x % (NN / 32)) * 32;
    const int pbase = b * NN + n0 + warp * 8;

    const unsigned feat_a = (unsigned)__cvta_generic_to_shared(&sh_feat[warp][0][0][0]);
    const unsigned nxyz_a = (unsigned)__cvta_generic_to_shared(&sh_nxyz[warp][0][0][0]);
    const unsigned fxyz_a = (unsigned)__cvta_generic_to_shared(&sh_fxyz[warp][0][0]);
    const unsigned conv_a = (unsigned)__cvta_generic_to_shared(&sh_conv[warp][0][0]);
    const unsigned agg_a  = (unsigned)__cvta_generic_to_shared(&sh_agg[warp][0][0]);

    {
        int4 iv = *(const int4*)(nidx + (size_t)pbase * KK + lane * 4);
        *(int4*)&sh_idx[warp][lane >> 2][(lane & 3) * 4] = iv;
    }
    if (lane < 24) sh_cxyz[warp][lane / 3][lane % 3] = xyz[pbase * 3 + lane];
    // zero-pad geometry rows d=10..15 (once)
    if (lane < KK) {
        ((float2*)&sh_fxyz[warp][lane][10])[0] = make_float2(0.f, 0.f);
        ((float4*)&sh_fxyz[warp][lane][12])[0] = make_float4(0.f, 0.f, 0.f, 0.f);
    }
    __syncthreads();

    const int j2 = lane >> 1, h2 = lane & 1;

    #pragma unroll
    for (int s = 0; s < 4; s++) {
        int idx = sh_idx[warp][s][j2];
        const float* src = g_feat_t + (size_t)(b * NN + idx) * HH + h2 * 8;
        unsigned d = feat_a + s * (KK * RSB) + j2 * RSB + h2 * 32;
        cp16(d, src); cp16(d + 16, src + 4);
        if (lane < KK) {
            int ix = sh_idx[warp][s][lane];
            const float* xs = xyz + (size_t)(b * NN + ix) * 3;
            unsigned dn = nxyz_a + s * 256 + lane * 16;
            cp4(dn, xs); cp4(dn + 4, xs + 1); cp4(dn + 8, xs + 2);
        }
        cp_commit();
    }

    #pragma unroll
    for (int t = 0; t < 8; t++) {
        const int pn = pbase + t;
        const int buf = t & 3;
        if (t < 5) cp_wait<3>(); else if (t == 5) cp_wait<2>();
        else if (t == 6) cp_wait<1>(); else cp_wait<0>();
        __syncwarp();

        // geometry (lane<16)
        if (lane < KK) {
            const float* np_ = &sh_nxyz[warp][buf][lane][0];
            float nx = np_[0], ny = np_[1], nz = np_[2];
            float cx = sh_cxyz[warp][t][0], cy = sh_cxyz[warp][t][1], cz = sh_cxyz[warp][t][2];
            float rx = cx - nx, ry = cy - ny, rz = cz - nz;
            float dis = sqrtf(rx * rx + ry * ry + rz * rz);
            float4* row = (float4*)&sh_fxyz[warp][lane][0];
            row[0] = make_float4(dis, rx, ry, rz);
            row[1] = make_float4(cx, cy, cz, nx);
            ((float2*)&sh_fxyz[warp][lane][8])[0] = make_float2(ny, nz);
        }
        __syncwarp();

        // conv1 via tf32 mma -> sh_conv + g_fx1 (raw-bit B operands)
        {
            size_t gb = (size_t)pn * (KK * HH);
            #pragma unroll
            for (int nT = 0; nT < 2; nT++) {
                float c[4] = {bb1c0, bb1c0, bb1c1, bb1c1};
                unsigned xb = fxyz_a + (8 * nT + g) * RSB;
                #pragma unroll
                for (int kT = 0; kT < 2; kT++) {
                    unsigned base = xb + (8 * kT + tq) * 4;
                    uint32_t b0v = LDSU(base);
                    uint32_t b1v = LDSU(base + 16);
                    MMA_TF32(c, &aw1[kT * 4], b0v, b1v);
                }
                int j0 = 8 * nT + 2 * tq, j1 = j0 + 1;
                float v0 = lrelu(c[0]), v1 = lrelu(c[1]);
                float v2 = lrelu(c[2]), v3 = lrelu(c[3]);
                sh_conv[warp][j0][g] = v0;     sh_conv[warp][j1][g] = v1;
                sh_conv[warp][j0][g + 8] = v2; sh_conv[warp][j1][g + 8] = v3;
                g_fx1[gb + j0 * HH + g] = v0;     g_fx1[gb + j1 * HH + g] = v1;
                g_fx1[gb + j0 * HH + g + 8] = v2; g_fx1[gb + j1 * HH + g + 8] = v3;
            }
        }
        __syncwarp();

        // fc via tf32 mma: scores^T(32c x 16j), pre-scaled by log2e
        const unsigned fbuf_a = feat_a + buf * (KK * RSB);
        float s[16];
        #pragma unroll
        for (int nT = 0; nT < 2; nT++) {
            float c0[4] = {0.f, 0.f, 0.f, 0.f}, c1[4] = {0.f, 0.f, 0.f, 0.f};
            int j = g + 8 * nT;
            unsigned xf = fbuf_a + j * RSB;
            unsigned xc = conv_a + j * RSB;
            #pragma unroll
            for (int kT = 0; kT < 4; kT++) {
                unsigned base = (kT < 2) ? (xf + (8 * kT + tq) * 4)
                                         : (xc + (8 * (kT - 2) + tq) * 4);
                uint32_t b0v = LDSU(base), b1v = LDSU(base + 16);
                MMA_TF32(c0, &aw[(0 * 4 + kT) * 4], b0v, b1v);
                MMA_TF32(c1, &aw[(1 * 4 + kT) * 4], b0v, b1v);
            }
            #pragma unroll
            for (int q = 0; q < 4; q++) {
                s[(nT * 2 + 0) * 4 + q] = c0[q];
                s[(nT * 2 + 1) * 4 + q] = c1[q];
            }
        }
        #pragma unroll
        for (int i = 0; i < 16; i++) s[i] = EX2(s[i]);
        float p0 = s[0] + s[1] + s[8]  + s[9];
        float p1 = s[2] + s[3] + s[10] + s[11];
        float p2 = s[4] + s[5] + s[12] + s[13];
        float p3 = s[6] + s[7] + s[14] + s[15];
        p0 += __shfl_xor_sync(0xffffffffu, p0, 1); p0 += __shfl_xor_sync(0xffffffffu, p0, 2);
        p1 += __shfl_xor_sync(0xffffffffu, p1, 1); p1 += __shfl_xor_sync(0xffffffffu, p1, 2);
        p2 += __shfl_xor_sync(0xffffffffu, p2, 1); p2 += __shfl_xor_sync(0xffffffffu, p2, 2);
        p3 += __shfl_xor_sync(0xffffffffu, p3, 1); p3 += __shfl_xor_sync(0xffffffffu, p3, 2);
        {
            int j0 = 2 * tq, j1 = j0 + 1, j8 = j0 + 8, j9 = j0 + 9;
            unsigned cF0 = g * 4, cF1 = (g + 8) * 4;
            float a0 = LDSF(fbuf_a + j0 * RSB + cF0) * s[0] + LDSF(fbuf_a + j1 * RSB + cF0) * s[1]
                     + LDSF(fbuf_a + j8 * RSB + cF0) * s[8] + LDSF(fbuf_a + j9 * RSB + cF0) * s[9];
            float a1 = LDSF(fbuf_a + j0 * RSB + cF1) * s[2] + LDSF(fbuf_a + j1 * RSB + cF1) * s[3]
                     + LDSF(fbuf_a + j8 * RSB + cF1) * s[10] + LDSF(fbuf_a + j9 * RSB + cF1) * s[11];
            float a2 = LDSF(conv_a + j0 * RSB + cF0) * s[4] + LDSF(conv_a + j1 * RSB + cF0) * s[5]
                     + LDSF(conv_a + j8 * RSB + cF0) * s[12] + LDSF(conv_a + j9 * RSB + cF0) * s[13];
            float a3 = LDSF(conv_a + j0 * RSB + cF1) * s[6] + LDSF(conv_a + j1 * RSB + cF1) * s[7]
                     + LDSF(conv_a + j8 * RSB + cF1) * s[14] + LDSF(conv_a + j9 * RSB + cF1) * s[15];
            a0 += __shfl_xor_sync(0xffffffffu, a0, 1); a0 += __shfl_xor_sync(0xffffffffu, a0, 2);
            a1 += __shfl_xor_sync(0xffffffffu, a1, 1); a1 += __shfl_xor_sync(0xffffffffu, a1, 2);
            a2 += __shfl_xor_sync(0xffffffffu, a2, 1); a2 += __shfl_xor_sync(0xffffffffu, a2, 2);
            a3 += __shfl_xor_sync(0xffffffffu, a3, 1); a3 += __shfl_xor_sync(0xffffffffu, a3, 2);
            if (tq == 0) {
                sh_agg[warp][t][g]      = __fdividef(a0, p0);
                sh_agg[warp][t][g + 8]  = __fdividef(a1, p1);
                sh_agg[warp][t][g + 16] = __fdividef(a2, p2);
                sh_agg[warp][t][g + 24] = __fdividef(a3, p3);
            }
        }

        // prefetch for t+4
        if (t + 4 < 8) {
            int sN = t + 4;
            int idx = sh_idx[warp][sN][j2];
            const float* src = g_feat_t + (size_t)(b * NN + idx) * HH + h2 * 8;
            unsigned d = feat_a + (sN & 3) * (KK * RSB) + j2 * RSB + h2 * 32;
            cp16(d, src); cp16(d + 16, src + 4);
            if (lane < KK) {
                int ix = sh_idx[warp][sN][lane];
                const float* xs = xyz + (size_t)(b * NN + ix) * 3;
                unsigned dn = nxyz_a + (sN & 3) * 256 + lane * 16;
                cp4(dn, xs); cp4(dn + 4, xs + 1); cp4(dn + 8, xs + 2);
            }
            cp_commit();
        }
    }
    __syncwarp();   // sh_agg visible for batched mlp

    // batched mlp (32->16) for 8 points via tf32 mma
    {
        float s0 = ap1g[g] * inv_bn, s1 = ap1g[g + 8] * inv_bn;
        float c[4];
        c[0] = c[1] = ap1b[g] * s0 + ap1be[g];
        c[2] = c[3] = ap1b[g + 8] * s1 + ap1be[g + 8];
        #pragma unroll
        for (int kT = 0; kT < 4; kT++) {
            int d0 = 8 * kT + tq, d1 = d0 + 4;
            uint32_t af[4];
            af[0] = CVT_TF32(ap1w[g * DD + d0] * s0);
            af[1] = CVT_TF32(ap1w[(g + 8) * DD + d0] * s1);
            af[2] = CVT_TF32(ap1w[g * DD + d1] * s0);
            af[3] = CVT_TF32(ap1w[(g + 8) * DD + d1] * s1);
            uint32_t b0v = CVT_TF32(LDSF(agg_a + g * 144 + d0 * 4));
            uint32_t b1v = CVT_TF32(LDSF(agg_a + g * 144 + d1 * 4));
            MMA_TF32(c, af, b0v, b1v);
        }
        int p0i = pbase + 2 * tq, p1i = p0i + 1;
        g_agg1[(size_t)p0i * HH + g]     = lrelu(c[0]);
        g_agg1[(size_t)p1i * HH + g]     = lrelu(c[1]);
        g_agg1[(size_t)p0i * HH + g + 8] = lrelu(c[2]);
        g_agg1[(size_t)p1i * HH + g + 8] = lrelu(c[3]);
    }
}

// ---------------------------------------------------------------------------
// Stage 2: load f_xyz1 + gather(f_agg1) + mma-conv2 + mma-fc2 + pool,
// then batched mma-mlp2 + coalesced output.
// ---------------------------------------------------------------------------
__global__ void __launch_bounds__(128, 4) stage2_kernel(
    const int* __restrict__ nidx,
    const float* __restrict__ w2, const float* __restrict__ b2,
    const float* __restrict__ g2, const float* __restrict__ be2,
    const float* __restrict__ fc2w, const float* __restrict__ fc2b,
    const float* __restrict__ ap2w, const float* __restrict__ ap2b,
    const float* __restrict__ ap2g, const float* __restrict__ ap2be,
    float* __restrict__ out)
{
    __shared__ __align__(16) float sh_feat[4][3][KK][RS];
    __shared__ __align__(16) float sh_fx1[4][3][KK][RS];   // padded rows
    __shared__ __align__(16) float sh_conv[4][KK][RS];
    __shared__ __align__(16) float sh_agg[4][8][36];
    __shared__ __align__(16) int   sh_idx[4][8][KK];
    __shared__ float sh_out[DD][33];

    const int warp = threadIdx.x >> 5;
    const int lane = threadIdx.x & 31;
    const int g = lane >> 2, tq = lane & 3;
    const float inv_bn = rsqrtf(1.0f + BN_EPS);

    // conv2 weight fragments (BN folded)
    uint32_t aw2[8]; float bb2c0, bb2c1;
    {
        float s0 = g2[g] * inv_bn, s1 = g2[g + 8] * inv_bn;
        #pragma unroll
        for (int kT = 0; kT < 2; kT++) {
            int d0 = 8 * kT + tq, d1 = d0 + 4;
            aw2[kT * 4 + 0] = CVT_TF32(w2[g * HH + d0] * s0);
            aw2[kT * 4 + 1] = CVT_TF32(w2[(g + 8) * HH + d0] * s1);
            aw2[kT * 4 + 2] = CVT_TF32(w2[g * HH + d1] * s0);
            aw2[kT * 4 + 3] = CVT_TF32(w2[(g + 8) * HH + d1] * s1);
        }
        bb2c0 = b2[g] * s0 + be2[g];
        bb2c1 = b2[g + 8] * s1 + be2[g + 8];
    }
    uint32_t aw[32];
    #pragma unroll
    for (int mT = 0; mT < 2; mT++)
        #pragma unroll
        for (int kT = 0; kT < 4; kT++) {
            int r0 = 16 * mT + g, r1 = r0 + 8, d0 = 8 * kT + tq, d1 = d0 + 4;
            int o = (mT * 4 + kT) * 4;
            aw[o + 0] = CVT_TF32(fc2w[r0 * DD + d0] * LOG2E);
            aw[o + 1] = CVT_TF32(fc2w[r1 * DD + d0] * LOG2E);
            aw[o + 2] = CVT_TF32(fc2w[r0 * DD + d1] * LOG2E);
            aw[o + 3] = CVT_TF32(fc2w[r1 * DD + d1] * LOG2E);
        }

    const int b  = blockIdx.x / (NN / 32);
    const int n0 = (blockIdx.x % (NN / 32)) * 32;
    const int pbase = b * NN + n0 + warp * 8;

    const unsigned feat_a = (unsigned)__cvta_generic_to_shared(&sh_feat[warp][0][0][0]);
    const unsigned fx1_a  = (unsigned)__cvta_generic_to_shared(&sh_fx1[warp][0][0][0]);
    const unsigned conv_a = (unsigned)__cvta_generic_to_shared(&sh_conv[warp][0][0]);
    const unsigned agg_a  = (unsigned)__cvta_generic_to_shared(&sh_agg[warp][0][0]);

    {
        int4 iv = *(const int4*)(nidx + (size_t)pbase * KK + lane * 4);
        *(int4*)&sh_idx[warp][lane >> 2][(lane & 3) * 4] = iv;
    }
    __syncthreads();

    const int j2 = lane >> 1, h2 = lane & 1;

    #pragma unroll
    for (int s = 0; s < 3; s++) {
        int idx = sh_idx[warp][s][j2];
        const float* src = g_agg1 + (size_t)(b * NN + idx) * HH + h2 * 8;
        unsigned d = feat_a + s * (KK * RSB) + j2 * RSB + h2 * 32;
        cp16(d, src); cp16(d + 16, src + 4);
        {
            const float* fs = g_fx1 + (size_t)(pbase + s) * (KK * HH) + j2 * HH + h2 * 8;
            unsigned fd = fx1_a + s * (KK * RSB) + j2 * RSB + h2 * 32;
            cp16(fd, fs); cp16(fd + 16, fs + 4);
        }
        cp_commit();
    }

    #pragma unroll
    for (int t = 0; t < 8; t++) {
        const int buf = t % 3;
        if (t < 6) cp_wait<2>(); else if (t == 6) cp_wait<1>(); else cp_wait<0>();
        __syncwarp();

        // conv2 via tf32 mma -> sh_conv (raw-bit B operands)
        {
            const unsigned fb = fx1_a + buf * (KK * RSB);
            #pragma unroll
            for (int nT = 0; nT < 2; nT++) {
                float c[4] = {bb2c0, bb2c0, bb2c1, bb2c1};
                unsigned xb = fb + (8 * nT + g) * RSB;
                #pragma unroll
                for (int kT = 0; kT < 2; kT++) {
                    unsigned base = xb + (8 * kT + tq) * 4;
                    uint32_t b0v = LDSU(base);
                    uint32_t b1v = LDSU(base + 16);
                    MMA_TF32(c, &aw2[kT * 4], b0v, b1v);
                }
                int j0 = 8 * nT + 2 * tq, j1 = j0 + 1;
                sh_conv[warp][j0][g] = lrelu(c[0]);     sh_conv[warp][j1][g] = lrelu(c[1]);
                sh_conv[warp][j0][g + 8] = lrelu(c[2]); sh_conv[warp][j1][g + 8] = lrelu(c[3]);
            }
        }
        __syncwarp();

        // fc2 via tf32 mma (log2e pre-scaled)
        const unsigned fbuf_a = feat_a + buf * (KK * RSB);
        float s[16];
        #pragma unroll
        for (int nT = 0; nT < 2; nT++) {
            float c0[4] = {0.f, 0.f, 0.f, 0.f}, c1[4] = {0.f, 0.f, 0.f, 0.f};
            int j = g + 8 * nT;
            unsigned xf = fbuf_a + j * RSB;
            unsigned xc = conv_a + j * RSB;
            #pragma unroll
            for (int kT = 0; kT < 4; kT++) {
                unsigned base = (kT < 2) ? (xf + (8 * kT + tq) * 4)
                                         : (xc + (8 * (kT - 2) + tq) * 4);
                uint32_t b0v = LDSU(base), b1v = LDSU(base + 16);
                MMA_TF32(c0, &aw[(0 * 4 + kT) * 4], b0v, b1v);
                MMA_TF32(c1, &aw[(1 * 4 + kT) * 4], b0v, b1v);
            }
            #pragma unroll
            for (int q = 0; q < 4; q++) {
                s[(nT * 2 + 0) * 4 + q] = c0[q];
                s[(nT * 2 + 1) * 4 + q] = c1[q];
            }
        }
        #pragma unroll
        for (int i = 0; i < 16; i++) s[i] = EX2(s[i]);
        float p0 = s[0] + s[1] + s[8]  + s[9];
        float p1 = s[2] + s[3] + s[10] + s[11];
        float p2 = s[4] + s[5] + s[12] + s[13];
        float p3 = s[6] + s[7] + s[14] + s[15];
        p0 += __shfl_xor_sync(0xffffffffu, p0, 1); p0 += __shfl_xor_sync(0xffffffffu, p0, 2);
        p1 += __shfl_xor_sync(0xffffffffu, p1, 1); p1 += __shfl_xor_sync(0xffffffffu, p1, 2);
        p2 += __shfl_xor_sync(0xffffffffu, p2, 1); p2 += __shfl_xor_sync(0xffffffffu, p2, 2);
        p3 += __shfl_xor_sync(0xffffffffu, p3, 1); p3 += __shfl_xor_sync(0xffffffffu, p3, 2);
        {
            int j0 = 2 * tq, j1 = j0 + 1, j8 = j0 + 8, j9 = j0 + 9;
            unsigned cF0 = g * 4, cF1 = (g + 8) * 4;
            float a0 = LDSF(fbuf_a + j0 * RSB + cF0) * s[0] + LDSF(fbuf_a + j1 * RSB + cF0) * s[1]
                     + LDSF(fbuf_a + j8 * RSB + cF0) * s[8] + LDSF(fbuf_a + j9 * RSB + cF0) * s[9];
            float a1 = LDSF(fbuf_a + j0 * RSB + cF1) * s[2] + LDSF(fbuf_a + j1 * RSB + cF1) * s[3]
                     + LDSF(fbuf_a + j8 * RSB + cF1) * s[10] + LDSF(fbuf_a + j9 * RSB + cF1) * s[11];
            float a2 = LDSF(conv_a + j0 * RSB + cF0) * s[4] + LDSF(conv_a + j1 * RSB + cF0) * s[5]
                     + LDSF(conv_a + j8 * RSB + cF0) * s[12] + LDSF(conv_a + j9 * RSB + cF0) * s[13];
            float a3 = LDSF(conv_a + j0 * RSB + cF1) * s[6] + LDSF(conv_a + j1 * RSB + cF1) * s[7]
                     + LDSF(conv_a + j8 * RSB + cF1) * s[14] + LDSF(conv_a + j9 * RSB + cF1) * s[15];
            a0 += __shfl_xor_sync(0xffffffffu, a0, 1); a0 += __shfl_xor_sync(0xffffffffu, a0, 2);
            a1 += __shfl_xor_sync(0xffffffffu, a1, 1); a1 += __shfl_xor_sync(0xffffffffu, a1, 2);
            a2 += __shfl_xor_sync(0xffffffffu, a2, 1); a2 += __shfl_xor_sync(0xffffffffu, a2, 2);
            a3 += __shfl_xor_sync(0xffffffffu, a3, 1); a3 += __shfl_xor_sync(0xffffffffu, a3, 2);
            if (tq == 0) {
                sh_agg[warp][t][g]      = __fdividef(a0, p0);
                sh_agg[warp][t][g + 8]  = __fdividef(a1, p1);
                sh_agg[warp][t][g + 16] = __fdividef(a2, p2);
                sh_agg[warp][t][g + 24] = __fdividef(a3, p3);
            }
        }

        // prefetch for t+3
        if (t + 3 < 8) {
            int sN = t + 3;
            int idx = sh_idx[warp][sN][j2];
            const float* src = g_agg1 + (size_t)(b * NN + idx) * HH + h2 * 8;
            unsigned d = feat_a + (sN % 3) * (KK * RSB) + j2 * RSB + h2 * 32;
            cp16(d, src); cp16(d + 16, src + 4);
            {
                const float* fs = g_fx1 + (size_t)(pbase + sN) * (KK * HH) + j2 * HH + h2 * 8;
                unsigned fd = fx1_a + (sN % 3) * (KK * RSB) + j2 * RSB + h2 * 32;
                cp16(fd, fs); cp16(fd + 16, fs + 4);
            }
            cp_commit();
        }
    }
    __syncwarp();   // sh_agg visible for batched mlp2

    // batched mlp2 (32->32) for 8 points via tf32 mma
    #pragma unroll
    for (int mT = 0; mT < 2; mT++) {
        int r0 = 16 * mT + g, r1 = r0 + 8;
        float s0 = ap2g[r0] * inv_bn, s1 = ap2g[r1] * inv_bn;
        float c[4];
        c[0] = c[1] = ap2b[r0] * s0 + ap2be[r0];
        c[2] = c[3] = ap2b[r1] * s1 + ap2be[r1];
        #pragma unroll
        for (int kT = 0; kT < 4; kT++) {
            int d0 = 8 * kT + tq, d1 = d0 + 4;
            uint32_t af[4];
            af[0] = CVT_TF32(ap2w[r0 * DD + d0] * s0);
            af[1] = CVT_TF32(ap2w[r1 * DD + d0] * s1);
            af[2] = CVT_TF32(ap2w[r0 * DD + d1] * s0);
            af[3] = CVT_TF32(ap2w[r1 * DD + d1] * s1);
            uint32_t b0v = CVT_TF32(LDSF(agg_a + g * 144 + d0 * 4));
            uint32_t b1v = CVT_TF32(LDSF(agg_a + g * 144 + d1 * 4));
            MMA_TF32(c, af, b0v, b1v);
        }
        int l0 = warp * 8 + 2 * tq, l1 = l0 + 1;
        sh_out[r0][l0] = lrelu(c[0]); sh_out[r0][l1] = lrelu(c[1]);
        sh_out[r1][l0] = lrelu(c[2]); sh_out[r1][l1] = lrelu(c[3]);
    }

    __syncthreads();
    for (int e = threadIdx.x; e < DD * 32; e += 128) {
        int c = e >> 5, ln = e & 31;
        out[((size_t)b * DD + c) * NN + n0 + ln] = sh_out[c][ln];
    }
}

// ---------------------------------------------------------------------------
extern "C" void kernel_launch(void* const* d_in, const int* in_sizes, int n_in,
                              void* d_out, int out_size) {
    const float* xyz     = (const float*)d_in[0];
    const float* feature = (const float*)d_in[1];
    const int*   nidx    = (const int*)  d_in[2];
    const float* w1   = (const float*)d_in[3];
    const float* b1   = (const float*)d_in[4];
    const float* g1   = (const float*)d_in[5];
    const float* be1  = (const float*)d_in[6];
    const float* fc1w = (const float*)d_in[7];
    const float* fc1b = (const float*)d_in[8];
    const float* ap1w = (const float*)d_in[9];
    const float* ap1b = (const float*)d_in[10];
    const float* ap1g = (const float*)d_in[11];
    const float* ap1be= (const float*)d_in[12];
    const float* w2   = (const float*)d_in[13];
    const float* b2   = (const float*)d_in[14];
    const float* g2   = (const float*)d_in[15];
    const float* be2  = (const float*)d_in[16];
    const float* fc2w = (const float*)d_in[17];
    const float* fc2b = (const float*)d_in[18];
    const float* ap2w = (const float*)d_in[19];
    const float* ap2b = (const float*)d_in[20];
    const float* ap2g = (const float*)d_in[21];
    const float* ap2be= (const float*)d_in[22];
    float* out = (float*)d_out;

    transpose_feat_kernel<<<dim3(NN / 64, BB), 256>>>(feature);
    stage1_kernel<<<BB * NN / 32, 128>>>(xyz, nidx, w1, b1, g1, be1,
                                         fc1w, fc1b, ap1w, ap1b, ap1g, ap1be);
    stage2_kernel<<<BB * NN / 32, 128>>>(nidx, w2, b2, g2, be2, fc2w, fc2b,
                                         ap2w, ap2b, ap2g, ap2be, out);
}

// round 15
// speedup vs baseline: 4.7192x; 1.0298x over previous
#include <cuda_runtime.h>
#include <math.h>
#include <stdint.h>

#define BB 4
#define NN 40960
#define KK 16
#define HH 16
#define DD 32
#define BN_EPS 1e-5f
#define RS 20            // padded row stride (floats) for mma-fed tiles
#define RSB 80           // row stride bytes
#define PTB (KK * RSB)   // bytes per point tile (1280)
#define LOG2E 1.4426950408889634f

__device__ float g_feat_t[BB * NN * HH];
__device__ float g_agg1[BB * NN * HH];
__device__ float g_fx1[(size_t)BB * NN * KK * HH];  // f_xyz1 [b,n,k,16]

__device__ __forceinline__ float lrelu(float y) { return fmaxf(y, 0.2f * y); }

__device__ __forceinline__ uint32_t LDSU(unsigned addr) {
    uint32_t v; asm volatile("ld.shared.b32 %0, [%1];" : "=r"(v) : "r"(addr)); return v;
}
__device__ __forceinline__ float LDSF(unsigned addr) {
    float v; asm volatile("ld.shared.f32 %0, [%1];" : "=f"(v) : "r"(addr)); return v;
}
__device__ __forceinline__ uint32_t CVT_TF32(float x) {
    uint32_t r; asm("cvt.rna.tf32.f32 %0, %1;" : "=r"(r) : "f"(x)); return r;
}
__device__ __forceinline__ float EX2(float x) {
    float r; asm("ex2.approx.f32 %0, %1;" : "=f"(r) : "f"(x)); return r;
}

// tf32 mma m16n8k8: D += A*B
#define MMA_TF32(d, a, b0, b1) \
    asm volatile("mma.sync.aligned.m16n8k8.row.col.f32.tf32.tf32.f32 " \
        "{%0,%1,%2,%3}, {%4,%5,%6,%7}, {%8,%9}, {%0,%1,%2,%3};" \
        : "+f"((d)[0]), "+f"((d)[1]), "+f"((d)[2]), "+f"((d)[3]) \
        : "r"((a)[0]), "r"((a)[1]), "r"((a)[2]), "r"((a)[3]), "r"(b0), "r"(b1))

// ---- cp.async helpers ----
__device__ __forceinline__ void cp16(unsigned dst, const float* src) {
    asm volatile("cp.async.cg.shared.global [%0], [%1], 16;" :: "r"(dst), "l"(src));
}
__device__ __forceinline__ void cp4(unsigned dst, const float* src) {
    asm volatile("cp.async.ca.shared.global [%0], [%1], 4;" :: "r"(dst), "l"(src));
}
__device__ __forceinline__ void cp_commit() {
    asm volatile("cp.async.commit_group;");
}
template <int N> __device__ __forceinline__ void cp_wait() {
    asm volatile("cp.async.wait_group %0;" :: "n"(N));
}

// fc scores: 32 channels x 16 j for one point -> s[16] (lane-distributed)
__device__ __forceinline__ void fc_scores(const uint32_t* aw, unsigned fbuf,
                                          unsigned cbuf, int g, int tq, float* s) {
    #pragma unroll
    for (int nT = 0; nT < 2; nT++) {
        float c0[4] = {0.f, 0.f, 0.f, 0.f}, c1[4] = {0.f, 0.f, 0.f, 0.f};
        int j = g + 8 * nT;
        unsigned xf = fbuf + j * RSB;
        unsigned xc = cbuf + j * RSB;
        #pragma unroll
        for (int kT = 0; kT < 4; kT++) {
            unsigned base = (kT < 2) ? (xf + (8 * kT + tq) * 4)
                                     : (xc + (8 * (kT - 2) + tq) * 4);
            uint32_t b0v = LDSU(base), b1v = LDSU(base + 16);
            MMA_TF32(c0, &aw[(0 * 4 + kT) * 4], b0v, b1v);
            MMA_TF32(c1, &aw[(1 * 4 + kT) * 4], b0v, b1v);
        }
        #pragma unroll
        for (int q = 0; q < 4; q++) {
            s[(nT * 2 + 0) * 4 + q] = c0[q];
            s[(nT * 2 + 1) * 4 + q] = c1[q];
        }
    }
}

// softmax-pool: s holds exp'd scores; result valid on tq==0 lanes
__device__ __forceinline__ void softpool(const float* s, unsigned fbuf, unsigned cbuf,
                                         int g, int tq, float4& r) {
    float p0 = s[0] + s[1] + s[8]  + s[9];
    float p1 = s[2] + s[3] + s[10] + s[11];
    float p2 = s[4] + s[5] + s[12] + s[13];
    float p3 = s[6] + s[7] + s[14] + s[15];
    p0 += __shfl_xor_sync(0xffffffffu, p0, 1); p0 += __shfl_xor_sync(0xffffffffu, p0, 2);
    p1 += __shfl_xor_sync(0xffffffffu, p1, 1); p1 += __shfl_xor_sync(0xffffffffu, p1, 2);
    p2 += __shfl_xor_sync(0xffffffffu, p2, 1); p2 += __shfl_xor_sync(0xffffffffu, p2, 2);
    p3 += __shfl_xor_sync(0xffffffffu, p3, 1); p3 += __shfl_xor_sync(0xffffffffu, p3, 2);
    int j0 = 2 * tq, j1 = j0 + 1, j8 = j0 + 8, j9 = j0 + 9;
    unsigned cF0 = g * 4, cF1 = (g + 8) * 4;
    float a0 = LDSF(fbuf + j0 * RSB + cF0) * s[0] + LDSF(fbuf + j1 * RSB + cF0) * s[1]
             + LDSF(fbuf + j8 * RSB + cF0) * s[8] + LDSF(fbuf + j9 * RSB + cF0) * s[9];
    float a1 = LDSF(fbuf + j0 * RSB + cF1) * s[2] + LDSF(fbuf + j1 * RSB + cF1) * s[3]
             + LDSF(fbuf + j8 * RSB + cF1) * s[10] + LDSF(fbuf + j9 * RSB + cF1) * s[11];
    float a2 = LDSF(cbuf + j0 * RSB + cF0) * s[4] + LDSF(cbuf + j1 * RSB + cF0) * s[5]
             + LDSF(cbuf + j8 * RSB + cF0) * s[12] + LDSF(cbuf + j9 * RSB + cF0) * s[13];
    float a3 = LDSF(cbuf + j0 * RSB + cF1) * s[6] + LDSF(cbuf + j1 * RSB + cF1) * s[7]
             + LDSF(cbuf + j8 * RSB + cF1) * s[14] + LDSF(cbuf + j9 * RSB + cF1) * s[15];
    a0 += __shfl_xor_sync(0xffffffffu, a0, 1); a0 += __shfl_xor_sync(0xffffffffu, a0, 2);
    a1 += __shfl_xor_sync(0xffffffffu, a1, 1); a1 += __shfl_xor_sync(0xffffffffu, a1, 2);
    a2 += __shfl_xor_sync(0xffffffffu, a2, 1); a2 += __shfl_xor_sync(0xffffffffu, a2, 2);
    a3 += __shfl_xor_sync(0xffffffffu, a3, 1); a3 += __shfl_xor_sync(0xffffffffu, a3, 2);
    r.x = __fdividef(a0, p0); r.y = __fdividef(a1, p1);
    r.z = __fdividef(a2, p2); r.w = __fdividef(a3, p3);
}

// ---------------------------------------------------------------------------
__global__ void transpose_feat_kernel(const float* __restrict__ feature) {
    __shared__ float tile[HH][64 + 1];
    int b = blockIdx.y;
    int n0 = blockIdx.x * 64;
    int t = threadIdx.x;
    int i = t & 63, cq = t >> 6;
    #pragma unroll
    for (int cc = cq; cc < HH; cc += 4)
        tile[cc][i] = feature[(b * HH + cc) * NN + n0 + i];
    __syncthreads();
    int c = t & 15, iq = t >> 4;
    #pragma unroll
    for (int ii = iq; ii < 64; ii += 16)
        g_feat_t[(b * NN + n0 + ii) * HH + c] = tile[c][ii];
}

// ---------------------------------------------------------------------------
// Stage 1 smem layout (dynamic): 2 points per iteration.
// ---------------------------------------------------------------------------
struct S1Smem {
    float feat[4][4][KK][RS];   // gather ring (4 point-buffers)
    float nxyz[4][4][KK][4];
    float fxyz[4][2][KK][RS];   // pair
    float conv[4][2][KK][RS];   // pair
    float agg[4][8][36];
    int   idx[4][8][KK];
    float cxyz[4][8][3];
};

__global__ void __launch_bounds__(128, 4) stage1_kernel(
    const float* __restrict__ xyz, const int* __restrict__ nidx,
    const float* __restrict__ w1, const float* __restrict__ b1,
    const float* __restrict__ g1, const float* __restrict__ be1,
    const float* __restrict__ fc1w, const float* __restrict__ fc1b,
    const float* __restrict__ ap1w, const float* __restrict__ ap1b,
    const float* __restrict__ ap1g, const float* __restrict__ ap1be)
{
    extern __shared__ __align__(16) char smem_raw[];
    S1Smem* sm = (S1Smem*)smem_raw;

    const int warp = threadIdx.x >> 5;
    const int lane = threadIdx.x & 31;
    const int g = lane >> 2, tq = lane & 3;
    const float inv_bn = rsqrtf(1.0f + BN_EPS);

    // conv1 weight fragments (BN folded, K padded 10->16)
    uint32_t aw1[8]; float bb1c0, bb1c1;
    {
        float s0 = g1[g] * inv_bn, s1 = g1[g + 8] * inv_bn;
        #pragma unroll
        for (int kT = 0; kT < 2; kT++) {
            int d0 = 8 * kT + tq, d1 = d0 + 4;
            float w00 = (d0 < 10) ? w1[g * 10 + d0] * s0 : 0.f;
            float w10 = (d0 < 10) ? w1[(g + 8) * 10 + d0] * s1 : 0.f;
            float w01 = (d1 < 10) ? w1[g * 10 + d1] * s0 : 0.f;
            float w11 = (d1 < 10) ? w1[(g + 8) * 10 + d1] * s1 : 0.f;
            aw1[kT * 4 + 0] = CVT_TF32(w00); aw1[kT * 4 + 1] = CVT_TF32(w10);
            aw1[kT * 4 + 2] = CVT_TF32(w01); aw1[kT * 4 + 3] = CVT_TF32(w11);
        }
        bb1c0 = b1[g] * s0 + be1[g];
        bb1c1 = b1[g + 8] * s1 + be1[g + 8];
    }
    // fc weight fragments (log2e folded)
    uint32_t aw[32];
    #pragma unroll
    for (int mT = 0; mT < 2; mT++)
        #pragma unroll
        for (int kT = 0; kT < 4; kT++) {
            int r0 = 16 * mT + g, r1 = r0 + 8, d0 = 8 * kT + tq, d1 = d0 + 4;
            int o = (mT * 4 + kT) * 4;
            aw[o + 0] = CVT_TF32(fc1w[r0 * DD + d0] * LOG2E);
            aw[o + 1] = CVT_TF32(fc1w[r1 * DD + d0] * LOG2E);
            aw[o + 2] = CVT_TF32(fc1w[r0 * DD + d1] * LOG2E);
            aw[o + 3] = CVT_TF32(fc1w[r1 * DD + d1] * LOG2E);
        }

    const int b  = blockIdx.x / (NN / 32);
    const int n0 = (blockIdx.x % (NN / 32)) * 32;
    const int pbase = b * NN + n0 + warp * 8;

    const unsigned feat_a = (unsigned)__cvta_generic_to_shared(&sm->feat[warp][0][0][0]);
    const unsigned nxyz_a = (unsigned)__cvta_generic_to_shared(&sm->nxyz[warp][0][0][0]);
    const unsigned fxyz_a = (unsigned)__cvta_generic_to_shared(&sm->fxyz[warp][0][0][0]);
    const unsigned conv_a = (unsigned)__cvta_generic_to_shared(&sm->conv[warp][0][0][0]);
    const unsigned agg_a  = (unsigned)__cvta_generic_to_shared(&sm->agg[warp][0][0]);

    {
        int4 iv = *(const int4*)(nidx + (size_t)pbase * KK + lane * 4);
        *(int4*)&sm->idx[warp][lane >> 2][(lane & 3) * 4] = iv;
    }
    if (lane < 24) sm->cxyz[warp][lane / 3][lane % 3] = xyz[pbase * 3 + lane];
    // zero-pad geometry rows d=10..15 for both pair buffers
    {
        int pt = lane >> 4, j = lane & 15;
        ((float2*)&sm->fxyz[warp][pt][j][10])[0] = make_float2(0.f, 0.f);
        ((float4*)&sm->fxyz[warp][pt][j][12])[0] = make_float4(0.f, 0.f, 0.f, 0.f);
    }
    __syncthreads();

    const int j2 = lane >> 1, h2 = lane & 1;

    #pragma unroll
    for (int s = 0; s < 4; s++) {
        int idx = sm->idx[warp][s][j2];
        const float* src = g_feat_t + (size_t)(b * NN + idx) * HH + h2 * 8;
        unsigned d = feat_a + s * PTB + j2 * RSB + h2 * 32;
        cp16(d, src); cp16(d + 16, src + 4);
        if (lane < KK) {
            int ix = sm->idx[warp][s][lane];
            const float* xs = xyz + (size_t)(b * NN + ix) * 3;
            unsigned dn = nxyz_a + s * 256 + lane * 16;
            cp4(dn, xs); cp4(dn + 4, xs + 1); cp4(dn + 8, xs + 2);
        }
        cp_commit();
    }

    #pragma unroll
    for (int t = 0; t < 4; t++) {
        const int p0 = 2 * t, p1 = p0 + 1;
        const int pn0 = pbase + p0, pn1 = pbase + p1;
        const int buf0 = p0 & 3;
        if (t < 3) cp_wait<2>(); else cp_wait<0>();
        __syncwarp();

        // geometry: all 32 lanes (pt = lane>>4)
        {
            int pt = lane >> 4, j = lane & 15;
            const float* np_ = &sm->nxyz[warp][buf0 + pt][j][0];
            float nx = np_[0], ny = np_[1], nz = np_[2];
            const float* cp_ = &sm->cxyz[warp][p0 + pt][0];
            float cx = cp_[0], cy = cp_[1], cz = cp_[2];
            float rx = cx - nx, ry = cy - ny, rz = cz - nz;
            float dis = sqrtf(rx * rx + ry * ry + rz * rz);
            float4* row = (float4*)&sm->fxyz[warp][pt][j][0];
            row[0] = make_float4(dis, rx, ry, rz);
            row[1] = make_float4(cx, cy, cz, nx);
            ((float2*)&sm->fxyz[warp][pt][j][8])[0] = make_float2(ny, nz);
        }
        __syncwarp();

        // conv1 via tf32 mma for both points
        #pragma unroll
        for (int pt = 0; pt < 2; pt++) {
            size_t gb = (size_t)(pt ? pn1 : pn0) * (KK * HH);
            #pragma unroll
            for (int nT = 0; nT < 2; nT++) {
                float c[4] = {bb1c0, bb1c0, bb1c1, bb1c1};
                unsigned xb = fxyz_a + pt * PTB + (8 * nT + g) * RSB;
                #pragma unroll
                for (int kT = 0; kT < 2; kT++) {
                    unsigned base = xb + (8 * kT + tq) * 4;
                    uint32_t b0v = LDSU(base);
                    uint32_t b1v = LDSU(base + 16);
                    MMA_TF32(c, &aw1[kT * 4], b0v, b1v);
                }
                int j0 = 8 * nT + 2 * tq, j1 = j0 + 1;
                float v0 = lrelu(c[0]), v1 = lrelu(c[1]);
                float v2 = lrelu(c[2]), v3 = lrelu(c[3]);
                sm->conv[warp][pt][j0][g] = v0;     sm->conv[warp][pt][j1][g] = v1;
                sm->conv[warp][pt][j0][g + 8] = v2; sm->conv[warp][pt][j1][g + 8] = v3;
                g_fx1[gb + j0 * HH + g] = v0;     g_fx1[gb + j1 * HH + g] = v1;
                g_fx1[gb + j0 * HH + g + 8] = v2; g_fx1[gb + j1 * HH + g + 8] = v3;
            }
        }
        __syncwarp();

        // fc + softmax + pool, both points interleaved
        const unsigned fb0 = feat_a + (buf0 + 0) * PTB, cb0 = conv_a + 0 * PTB;
        const unsigned fb1 = feat_a + (buf0 + 1) * PTB, cb1 = conv_a + 1 * PTB;
        float s0v[16], s1v[16];
        fc_scores(aw, fb0, cb0, g, tq, s0v);
        fc_scores(aw, fb1, cb1, g, tq, s1v);
        #pragma unroll
        for (int i = 0; i < 16; i++) { s0v[i] = EX2(s0v[i]); s1v[i] = EX2(s1v[i]); }
        float4 r0, r1;
        softpool(s0v, fb0, cb0, g, tq, r0);
        softpool(s1v, fb1, cb1, g, tq, r1);
        if (tq == 0) {
            sm->agg[warp][p0][g]      = r0.x; sm->agg[warp][p0][g + 8]  = r0.y;
            sm->agg[warp][p0][g + 16] = r0.z; sm->agg[warp][p0][g + 24] = r0.w;
            sm->agg[warp][p1][g]      = r1.x; sm->agg[warp][p1][g + 8]  = r1.y;
            sm->agg[warp][p1][g + 16] = r1.z; sm->agg[warp][p1][g + 24] = r1.w;
        }

        // prefetch points p0+4, p0+5
        if (t < 2) {
            #pragma unroll
            for (int pt = 0; pt < 2; pt++) {
                int sN = p0 + 4 + pt;
                int idx = sm->idx[warp][sN][j2];
                const float* src = g_feat_t + (size_t)(b * NN + idx) * HH + h2 * 8;
                unsigned d = feat_a + (sN & 3) * PTB + j2 * RSB + h2 * 32;
                cp16(d, src); cp16(d + 16, src + 4);
                if (lane < KK) {
                    int ix = sm->idx[warp][sN][lane];
                    const float* xs = xyz + (size_t)(b * NN + ix) * 3;
                    unsigned dn = nxyz_a + (sN & 3) * 256 + lane * 16;
                    cp4(dn, xs); cp4(dn + 4, xs + 1); cp4(dn + 8, xs + 2);
                }
                cp_commit();
            }
        }
    }
    __syncwarp();   // agg visible for batched mlp

    // batched mlp (32->16) for 8 points via tf32 mma
    {
        float s0 = ap1g[g] * inv_bn, s1 = ap1g[g + 8] * inv_bn;
        float c[4];
        c[0] = c[1] = ap1b[g] * s0 + ap1be[g];
        c[2] = c[3] = ap1b[g + 8] * s1 + ap1be[g + 8];
        #pragma unroll
        for (int kT = 0; kT < 4; kT++) {
            int d0 = 8 * kT + tq, d1 = d0 + 4;
            uint32_t af[4];
            af[0] = CVT_TF32(ap1w[g * DD + d0] * s0);
            af[1] = CVT_TF32(ap1w[(g + 8) * DD + d0] * s1);
            af[2] = CVT_TF32(ap1w[g * DD + d1] * s0);
            af[3] = CVT_TF32(ap1w[(g + 8) * DD + d1] * s1);
            uint32_t b0v = CVT_TF32(LDSF(agg_a + g * 144 + d0 * 4));
            uint32_t b1v = CVT_TF32(LDSF(agg_a + g * 144 + d1 * 4));
            MMA_TF32(c, af, b0v, b1v);
        }
        int p0i = pbase + 2 * tq, p1i = p0i + 1;
        g_agg1[(size_t)p0i * HH + g]     = lrelu(c[0]);
        g_agg1[(size_t)p1i * HH + g]     = lrelu(c[1]);
        g_agg1[(size_t)p0i * HH + g + 8] = lrelu(c[2]);
        g_agg1[(size_t)p1i * HH + g + 8] = lrelu(c[3]);
    }
}

// ---------------------------------------------------------------------------
// Stage 2 smem layout (dynamic): 2 points per iteration, direct output stores.
// ---------------------------------------------------------------------------
struct S2Smem {
    float feat[4][4][KK][RS];
    float fx1[4][4][KK][RS];
    float conv[4][2][KK][RS];
    float agg[4][8][36];
    int   idx[4][8][KK];
};

__global__ void __launch_bounds__(128, 3) stage2_kernel(
    const int* __restrict__ nidx,
    const float* __restrict__ w2, const float* __restrict__ b2,
    const float* __restrict__ g2, const float* __restrict__ be2,
    const float* __restrict__ fc2w, const float* __restrict__ fc2b,
    const float* __restrict__ ap2w, const float* __restrict__ ap2b,
    const float* __restrict__ ap2g, const float* __restrict__ ap2be,
    float* __restrict__ out)
{
    extern __shared__ __align__(16) char smem_raw[];
    S2Smem* sm = (S2Smem*)smem_raw;

    const int warp = threadIdx.x >> 5;
    const int lane = threadIdx.x & 31;
    const int g = lane >> 2, tq = lane & 3;
    const float inv_bn = rsqrtf(1.0f + BN_EPS);

    uint32_t aw2[8]; float bb2c0, bb2c1;
    {
        float s0 = g2[g] * inv_bn, s1 = g2[g + 8] * inv_bn;
        #pragma unroll
        for (int kT = 0; kT < 2; kT++) {
            int d0 = 8 * kT + tq, d1 = d0 + 4;
            aw2[kT * 4 + 0] = CVT_TF32(w2[g * HH + d0] * s0);
            aw2[kT * 4 + 1] = CVT_TF32(w2[(g + 8) * HH + d0] * s1);
            aw2[kT * 4 + 2] = CVT_TF32(w2[g * HH + d1] * s0);
            aw2[kT * 4 + 3] = CVT_TF32(w2[(g + 8) * HH + d1] * s1);
        }
        bb2c0 = b2[g] * s0 + be2[g];
        bb2c1 = b2[g + 8] * s1 + be2[g + 8];
    }
    uint32_t aw[32];
    #pragma unroll
    for (int mT = 0; mT < 2; mT++)
        #pragma unroll
        for (int kT = 0; kT < 4; kT++) {
            int r0 = 16 * mT + g, r1 = r0 + 8, d0 = 8 * kT + tq, d1 = d0 + 4;
            int o = (mT * 4 + kT) * 4;
            aw[o + 0] = CVT_TF32(fc2w[r0 * DD + d0] * LOG2E);
            aw[o + 1] = CVT_TF32(fc2w[r1 * DD + d0] * LOG2E);
            aw[o + 2] = CVT_TF32(fc2w[r0 * DD + d1] * LOG2E);
            aw[o + 3] = CVT_TF32(fc2w[r1 * DD + d1] * LOG2E);
        }

    const int b  = blockIdx.x / (NN / 32);
    const int n0 = (blockIdx.x % (NN / 32)) * 32;
    const int pbase = b * NN + n0 + warp * 8;

    const unsigned feat_a = (unsigned)__cvta_generic_to_shared(&sm->feat[warp][0][0][0]);
    const unsigned fx1_a  = (unsigned)__cvta_generic_to_shared(&sm->fx1[warp][0][0][0]);
    const unsigned conv_a = (unsigned)__cvta_generic_to_shared(&sm->conv[warp][0][0][0]);
    const unsigned agg_a  = (unsigned)__cvta_generic_to_shared(&sm->agg[warp][0][0]);

    {
        int4 iv = *(const int4*)(nidx + (size_t)pbase * KK + lane * 4);
        *(int4*)&sm->idx[warp][lane >> 2][(lane & 3) * 4] = iv;
    }
    __syncthreads();

    const int j2 = lane >> 1, h2 = lane & 1;

    #pragma unroll
    for (int s = 0; s < 4; s++) {
        int idx = sm->idx[warp][s][j2];
        const float* src = g_agg1 + (size_t)(b * NN + idx) * HH + h2 * 8;
        unsigned d = feat_a + s * PTB + j2 * RSB + h2 * 32;
        cp16(d, src); cp16(d + 16, src + 4);
        {
            const float* fs = g_fx1 + (size_t)(pbase + s) * (KK * HH) + j2 * HH + h2 * 8;
            unsigned fd = fx1_a + s * PTB + j2 * RSB + h2 * 32;
            cp16(fd, fs); cp16(fd + 16, fs + 4);
        }
        cp_commit();
    }

    #pragma unroll
    for (int t = 0; t < 4; t++) {
        const int p0 = 2 * t, p1 = p0 + 1;
        const int buf0 = p0 & 3;
        if (t < 3) cp_wait<2>(); else cp_wait<0>();
        __syncwarp();

        // conv2 via tf32 mma for both points
        #pragma unroll
        for (int pt = 0; pt < 2; pt++) {
            const unsigned fbx = fx1_a + (buf0 + pt) * PTB;
            #pragma unroll
            for (int nT = 0; nT < 2; nT++) {
                float c[4] = {bb2c0, bb2c0, bb2c1, bb2c1};
                unsigned xb = fbx + (8 * nT + g) * RSB;
                #pragma unroll
                for (int kT = 0; kT < 2; kT++) {
                    unsigned base = xb + (8 * kT + tq) * 4;
                    uint32_t b0v = LDSU(base);
                    uint32_t b1v = LDSU(base + 16);
                    MMA_TF32(c, &aw2[kT * 4], b0v, b1v);
                }
                int j0 = 8 * nT + 2 * tq, j1 = j0 + 1;
                sm->conv[warp][pt][j0][g] = lrelu(c[0]);
                sm->conv[warp][pt][j1][g] = lrelu(c[1]);
                sm->conv[warp][pt][j0][g + 8] = lrelu(c[2]);
                sm->conv[warp][pt][j1][g + 8] = lrelu(c[3]);
            }
        }
        __syncwarp();

        // fc2 + softmax + pool, both points interleaved
        const unsigned fb0 = feat_a + (buf0 + 0) * PTB, cb0 = conv_a + 0 * PTB;
        const unsigned fb1 = feat_a + (buf0 + 1) * PTB, cb1 = conv_a + 1 * PTB;
        float s0v[16], s1v[16];
        fc_scores(aw, fb0, cb0, g, tq, s0v);
        fc_scores(aw, fb1, cb1, g, tq, s1v);
        #pragma unroll
        for (int i = 0; i < 16; i++) { s0v[i] = EX2(s0v[i]); s1v[i] = EX2(s1v[i]); }
        float4 r0, r1;
        softpool(s0v, fb0, cb0, g, tq, r0);
        softpool(s1v, fb1, cb1, g, tq, r1);
        if (tq == 0) {
            sm->agg[warp][p0][g]      = r0.x; sm->agg[warp][p0][g + 8]  = r0.y;
            sm->agg[warp][p0][g + 16] = r0.z; sm->agg[warp][p0][g + 24] = r0.w;
            sm->agg[warp][p1][g]      = r1.x; sm->agg[warp][p1][g + 8]  = r1.y;
            sm->agg[warp][p1][g + 16] = r1.z; sm->agg[warp][p1][g + 24] = r1.w;
        }

        // prefetch points p0+4, p0+5
        if (t < 2) {
            #pragma unroll
            for (int pt = 0; pt < 2; pt++) {
                int sN = p0 + 4 + pt;
                int idx = sm->idx[warp][sN][j2];
                const float* src = g_agg1 + (size_t)(b * NN + idx) * HH + h2 * 8;
                unsigned d = feat_a + (sN & 3) * PTB + j2 * RSB + h2 * 32;
                cp16(d, src); cp16(d + 16, src + 4);
                {
                    const float* fs = g_fx1 + (size_t)(pbase + sN) * (KK * HH) + j2 * HH + h2 * 8;
                    unsigned fd = fx1_a + (sN & 3) * PTB + j2 * RSB + h2 * 32;
                    cp16(fd, fs); cp16(fd + 16, fs + 4);
                }
                cp_commit();
            }
        }
    }
    __syncwarp();   // agg visible for batched mlp2

    // batched mlp2 (32->32), direct float2 stores to output
    #pragma unroll
    for (int mT = 0; mT < 2; mT++) {
        int r0 = 16 * mT + g, r1 = r0 + 8;
        float s0 = ap2g[r0] * inv_bn, s1 = ap2g[r1] * inv_bn;
        float c[4];
        c[0] = c[1] = ap2b[r0] * s0 + ap2be[r0];
        c[2] = c[3] = ap2b[r1] * s1 + ap2be[r1];
        #pragma unroll
        for (int kT = 0; kT < 4; kT++) {
            int d0 = 8 * kT + tq, d1 = d0 + 4;
            uint32_t af[4];
            af[0] = CVT_TF32(ap2w[r0 * DD + d0] * s0);
            af[1] = CVT_TF32(ap2w[r1 * DD + d0] * s1);
            af[2] = CVT_TF32(ap2w[r0 * DD + d1] * s0);
            af[3] = CVT_TF32(ap2w[r1 * DD + d1] * s1);
            uint32_t b0v = CVT_TF32(LDSF(agg_a + g * 144 + d0 * 4));
            uint32_t b1v = CVT_TF32(LDSF(agg_a + g * 144 + d1 * 4));
            MMA_TF32(c, af, b0v, b1v);
        }
        int nb = n0 + warp * 8 + 2 * tq;
        float2 v0 = make_float2(lrelu(c[0]), lrelu(c[1]));
        float2 v1 = make_float2(lrelu(c[2]), lrelu(c[3]));
        *(float2*)&out[((size_t)b * DD + r0) * NN + nb] = v0;
        *(float2*)&out[((size_t)b * DD + r1) * NN + nb] = v1;
    }
}

// ---------------------------------------------------------------------------
extern "C" void kernel_launch(void* const* d_in, const int* in_sizes, int n_in,
                              void* d_out, int out_size) {
    const float* xyz     = (const float*)d_in[0];
    const float* feature = (const float*)d_in[1];
    const int*   nidx    = (const int*)  d_in[2];
    const float* w1   = (const float*)d_in[3];
    const float* b1   = (const float*)d_in[4];
    const float* g1   = (const float*)d_in[5];
    const float* be1  = (const float*)d_in[6];
    const float* fc1w = (const float*)d_in[7];
    const float* fc1b = (const float*)d_in[8];
    const float* ap1w = (const float*)d_in[9];
    const float* ap1b = (const float*)d_in[10];
    const float* ap1g = (const float*)d_in[11];
    const float* ap1be= (const float*)d_in[12];
    const float* w2   = (const float*)d_in[13];
    const float* b2   = (const float*)d_in[14];
    const float* g2   = (const float*)d_in[15];
    const float* be2  = (const float*)d_in[16];
    const float* fc2w = (const float*)d_in[17];
    const float* fc2b = (const float*)d_in[18];
    const float* ap2w = (const float*)d_in[19];
    const float* ap2b = (const float*)d_in[20];
    const float* ap2g = (const float*)d_in[21];
    const float* ap2be= (const float*)d_in[22];
    float* out = (float*)d_out;

    // idempotent, not a stream op — safe during graph capture, no static guard
    cudaFuncSetAttribute(stage1_kernel,
        cudaFuncAttributeMaxDynamicSharedMemorySize, (int)sizeof(S1Smem));
    cudaFuncSetAttribute(stage2_kernel,
        cudaFuncAttributeMaxDynamicSharedMemorySize, (int)sizeof(S2Smem));

    transpose_feat_kernel<<<dim3(NN / 64, BB), 256>>>(feature);
    stage1_kernel<<<BB * NN / 32, 128, sizeof(S1Smem)>>>(
        xyz, nidx, w1, b1, g1, be1, fc1w, fc1b, ap1w, ap1b, ap1g, ap1be);
    stage2_kernel<<<BB * NN / 32, 128, sizeof(S2Smem)>>>(
        nidx, w2, b2, g2, be2, fc2w, fc2b, ap2w, ap2b, ap2g, ap2be, out);
}